// round 2
// baseline (speedup 1.0000x reference)
#include <cuda_runtime.h>
#include <math.h>
#include <stddef.h>

#define BATCH 4
#define CIN 64
#define COUT 64
#define LSEQ 131072
#define KW 9
#define PADW 4
#define TILE 128
#define XW (TILE + 2 * PADW) /* 136 */
#define NTHREADS 256
#define NTILES (BATCH * (LSEQ / TILE)) /* 4096 */

#define SMEM_FLOATS (KW * CIN * COUT + CIN * XW + 3 * XW + KW * TILE)

__device__ double g_sum[COUT];
__device__ double g_sumsq[COUT];
__device__ float g_scale[COUT];
__device__ float g_shift[COUT];

__device__ __forceinline__ float2 ffma2(float2 a, float2 b, float2 c) {
    float2 d;
    asm("fma.rn.f32x2 %0, %1, %2, %3;"
        : "=l"(reinterpret_cast<unsigned long long &>(d))
        : "l"(reinterpret_cast<unsigned long long &>(a)),
          "l"(reinterpret_cast<unsigned long long &>(b)),
          "l"(reinterpret_cast<unsigned long long &>(c)));
    return d;
}

__device__ __forceinline__ float2 fmul2(float2 a, float2 b) {
    float2 d;
    asm("mul.rn.f32x2 %0, %1, %2;"
        : "=l"(reinterpret_cast<unsigned long long &>(d))
        : "l"(reinterpret_cast<unsigned long long &>(a)),
          "l"(reinterpret_cast<unsigned long long &>(b)));
    return d;
}

__global__ void zero_stats_kernel() {
    int i = threadIdx.x;
    if (i < COUT) {
        g_sum[i] = 0.0;
        g_sumsq[i] = 0.0;
    }
}

__global__ __launch_bounds__(NTHREADS, 1) void conv_kernel(
    const float* __restrict__ x, const float* __restrict__ coords,
    const float* __restrict__ W, const float* __restrict__ bias,
    float* __restrict__ out) {
    extern __shared__ float smem[];
    float* Wsh = smem;                    // [KW][CIN][COUT]  (Wsh[k][c][o] = W[o][c][k])
    float* xsh = Wsh + KW * CIN * COUT;   // [CIN][XW]
    float* csh = xsh + CIN * XW;          // [3][XW]
    float* wsh = csh + 3 * XW;            // [KW][TILE]

    const int tid = threadIdx.x;
    const int tx = tid & 31;  // L lane: cols tx, tx+32, tx+64, tx+96
    const int ty = tid >> 5;  // Cout group: rows ty*8 .. ty*8+7

    // One-time: stage W transposed into smem (coalesced global reads).
    for (int i = tid; i < KW * CIN * COUT; i += NTHREADS) {
        int o = i / (CIN * KW);
        int rem = i - o * (CIN * KW);
        int c = rem / KW;
        int k = rem - c * KW;
        Wsh[(k * CIN + c) * COUT + o] = W[i];
    }

    for (int t = blockIdx.x; t < NTILES; t += gridDim.x) {
        const int b = t / (LSEQ / TILE);
        const int l0 = (t - b * (LSEQ / TILE)) * TILE;
        __syncthreads();  // previous tile's consumers done before overwriting stage buffers

        const float* xb = x + (size_t)b * CIN * LSEQ;
        for (int i = tid; i < CIN * XW; i += NTHREADS) {
            int c = i / XW;
            int j = i - c * XW;
            int l = l0 - PADW + j;
            xsh[i] = (l >= 0 && l < LSEQ) ? xb[(size_t)c * LSEQ + l] : 0.0f;
        }
        const float* cb = coords + (size_t)b * 3 * LSEQ;
        for (int i = tid; i < 3 * XW; i += NTHREADS) {
            int d = i / XW;
            int j = i - d * XW;
            int l = l0 - PADW + j;
            csh[i] = (l >= 0 && l < LSEQ) ? cb[(size_t)d * LSEQ + l] : 0.0f;
        }
        __syncthreads();

        // Gaussian spatial weights: w[k][lc] = exp(-0.5 * |c[lc+k-4] - c[lc]|^2)
        for (int i = tid; i < KW * TILE; i += NTHREADS) {
            int k = i / TILE;
            int lc = i - k * TILE;
            float d0 = csh[lc + k] - csh[lc + PADW];
            float d1 = csh[XW + lc + k] - csh[XW + lc + PADW];
            float d2 = csh[2 * XW + lc + k] - csh[2 * XW + lc + PADW];
            float dist2 = d0 * d0 + d1 * d1 + d2 * d2;
            wsh[i] = __expf(-0.5f * dist2);
        }
        __syncthreads();

        float2 acc[8][2];
#pragma unroll
        for (int r = 0; r < 8; r++) {
            acc[r][0] = make_float2(0.f, 0.f);
            acc[r][1] = make_float2(0.f, 0.f);
        }

#pragma unroll
        for (int k = 0; k < KW; k++) {
            const float2 wv0 = make_float2(wsh[k * TILE + tx], wsh[k * TILE + 32 + tx]);
            const float2 wv1 = make_float2(wsh[k * TILE + 64 + tx], wsh[k * TILE + 96 + tx]);
            const float* xrow = xsh + tx + k;
            const float* wrow = Wsh + k * CIN * COUT + ty * 8;
#pragma unroll 4
            for (int c = 0; c < CIN; c++) {
                float b0 = xrow[c * XW];
                float b1 = xrow[c * XW + 32];
                float b2 = xrow[c * XW + 64];
                float b3 = xrow[c * XW + 96];
                float2 bw0 = fmul2(make_float2(b0, b1), wv0);
                float2 bw1 = fmul2(make_float2(b2, b3), wv1);
                float4 a0 = *reinterpret_cast<const float4*>(wrow + c * COUT);
                float4 a1 = *reinterpret_cast<const float4*>(wrow + c * COUT + 4);
                acc[0][0] = ffma2(make_float2(a0.x, a0.x), bw0, acc[0][0]);
                acc[0][1] = ffma2(make_float2(a0.x, a0.x), bw1, acc[0][1]);
                acc[1][0] = ffma2(make_float2(a0.y, a0.y), bw0, acc[1][0]);
                acc[1][1] = ffma2(make_float2(a0.y, a0.y), bw1, acc[1][1]);
                acc[2][0] = ffma2(make_float2(a0.z, a0.z), bw0, acc[2][0]);
                acc[2][1] = ffma2(make_float2(a0.z, a0.z), bw1, acc[2][1]);
                acc[3][0] = ffma2(make_float2(a0.w, a0.w), bw0, acc[3][0]);
                acc[3][1] = ffma2(make_float2(a0.w, a0.w), bw1, acc[3][1]);
                acc[4][0] = ffma2(make_float2(a1.x, a1.x), bw0, acc[4][0]);
                acc[4][1] = ffma2(make_float2(a1.x, a1.x), bw1, acc[4][1]);
                acc[5][0] = ffma2(make_float2(a1.y, a1.y), bw0, acc[5][0]);
                acc[5][1] = ffma2(make_float2(a1.y, a1.y), bw1, acc[5][1]);
                acc[6][0] = ffma2(make_float2(a1.z, a1.z), bw0, acc[6][0]);
                acc[6][1] = ffma2(make_float2(a1.z, a1.z), bw1, acc[6][1]);
                acc[7][0] = ffma2(make_float2(a1.w, a1.w), bw0, acc[7][0]);
                acc[7][1] = ffma2(make_float2(a1.w, a1.w), bw1, acc[7][1]);
            }
        }

        // Epilogue: +bias, store raw, accumulate per-channel batch stats.
        float* outb = out + (size_t)b * COUT * LSEQ;
#pragma unroll
        for (int r = 0; r < 8; r++) {
            int o = ty * 8 + r;
            float bz = __ldg(&bias[o]);
            float v0 = acc[r][0].x + bz;
            float v1 = acc[r][0].y + bz;
            float v2 = acc[r][1].x + bz;
            float v3 = acc[r][1].y + bz;
            size_t base = (size_t)o * LSEQ + l0 + tx;
            outb[base] = v0;
            outb[base + 32] = v1;
            outb[base + 64] = v2;
            outb[base + 96] = v3;
            float s1 = (v0 + v1) + (v2 + v3);
            float s2 = (v0 * v0 + v1 * v1) + (v2 * v2 + v3 * v3);
#pragma unroll
            for (int off = 16; off > 0; off >>= 1) {
                s1 += __shfl_xor_sync(0xffffffffu, s1, off);
                s2 += __shfl_xor_sync(0xffffffffu, s2, off);
            }
            if (tx == 0) {
                atomicAdd(&g_sum[o], (double)s1);
                atomicAdd(&g_sumsq[o], (double)s2);
            }
        }
    }
}

__global__ void stats_kernel(const float* __restrict__ gamma,
                             const float* __restrict__ beta) {
    int o = threadIdx.x;
    if (o < COUT) {
        double N = (double)BATCH * (double)LSEQ;
        double mean = g_sum[o] / N;
        double var = g_sumsq[o] / N - mean * mean;
        double rstd = 1.0 / sqrt(var + 1e-5);
        float sc = gamma[o] * (float)rstd;
        g_scale[o] = sc;
        g_shift[o] = beta[o] - (float)mean * sc;
    }
}

__global__ void norm_kernel(float* __restrict__ out) {
    const size_t total4 = (size_t)BATCH * COUT * LSEQ / 4;
    size_t stride = (size_t)gridDim.x * blockDim.x;
    for (size_t i = (size_t)blockIdx.x * blockDim.x + threadIdx.x; i < total4;
         i += stride) {
        float4 v = reinterpret_cast<float4*>(out)[i];
        int ch = (int)((i * 4 / LSEQ)) & (COUT - 1);
        float sc = g_scale[ch];
        float sh = g_shift[ch];
        v.x = fmaxf(fmaf(v.x, sc, sh), 0.0f);
        v.y = fmaxf(fmaf(v.y, sc, sh), 0.0f);
        v.z = fmaxf(fmaf(v.z, sc, sh), 0.0f);
        v.w = fmaxf(fmaf(v.w, sc, sh), 0.0f);
        reinterpret_cast<float4*>(out)[i] = v;
    }
}

extern "C" void kernel_launch(void* const* d_in, const int* in_sizes, int n_in,
                              void* d_out, int out_size) {
    const float* x = (const float*)d_in[0];       // [4,64,131072]
    const float* coords = (const float*)d_in[1];  // [4,3,131072]
    const float* W = (const float*)d_in[2];       // [64,64,9]
    const float* bias = (const float*)d_in[3];    // [64]
    const float* gamma = (const float*)d_in[4];   // [64]
    const float* beta = (const float*)d_in[5];    // [64]
    float* out = (float*)d_out;

    const size_t smem = SMEM_FLOATS * sizeof(float);
    cudaFuncSetAttribute(conv_kernel, cudaFuncAttributeMaxDynamicSharedMemorySize,
                         (int)smem);
    int sms = 148;
    cudaDeviceGetAttribute(&sms, cudaDevAttrMultiProcessorCount, 0);

    zero_stats_kernel<<<1, 128>>>();
    conv_kernel<<<sms, NTHREADS, smem>>>(x, coords, W, bias, out);
    stats_kernel<<<1, 64>>>(gamma, beta);
    norm_kernel<<<8192, 256>>>(out);
}

// round 4
// speedup vs baseline: 2.2244x; 2.2244x over previous
#include <cuda_runtime.h>
#include <math.h>
#include <stddef.h>
#include <stdint.h>

#define BATCH 4
#define CIN 64
#define COUT 64
#define LSEQ 131072
#define KW 9
#define PADW 4
#define TILE 128
#define XW (TILE + 2 * PADW) /* 136 */
#define NTHREADS 256
#define TPB_L (LSEQ / TILE)    /* 1024 */
#define NTILES (BATCH * TPB_L) /* 4096 */

/* SMEM layout (bytes):
   FRAG: tf32 B fragments, uint2 per lane: [kk][ks][nt][lane] = 9*8*8*32*8 = 147456
   XSH : x tile [64][136] f32 = 34816
   CSH : coords [3][136] f32  = 1632
   WSH : gaussian w [9][128]  = 4608          total = 188512 */
#define SM_FRAG 0
#define SM_X (SM_FRAG + KW * 8 * 8 * 32 * 8)
#define SM_C (SM_X + CIN * XW * 4)
#define SM_W (SM_C + 3 * XW * 4)
#define SM_TOTAL (SM_W + KW * TILE * 4)

static __device__ double g_sum[COUT];
static __device__ double g_sumsq[COUT];
static __device__ float g_scale[COUT];
static __device__ float g_shift[COUT];

__device__ __forceinline__ uint32_t cvt_tf32(float v) {
    uint32_t r;
    asm("cvt.rna.tf32.f32 %0, %1;" : "=r"(r) : "f"(v));
    return r;
}

__device__ __forceinline__ void mma_tf32(float* d, uint32_t a0, uint32_t a1, uint32_t a2,
                                         uint32_t a3, uint32_t b0, uint32_t b1) {
    asm volatile(
        "mma.sync.aligned.m16n8k8.row.col.f32.tf32.tf32.f32 "
        "{%0,%1,%2,%3}, {%4,%5,%6,%7}, {%8,%9}, {%0,%1,%2,%3};"
        : "+f"(d[0]), "+f"(d[1]), "+f"(d[2]), "+f"(d[3])
        : "r"(a0), "r"(a1), "r"(a2), "r"(a3), "r"(b0), "r"(b1));
}

__global__ void zero_stats_kernel() {
    int i = threadIdx.x;
    if (i < COUT) {
        g_sum[i] = 0.0;
        g_sumsq[i] = 0.0;
    }
}

__global__ __launch_bounds__(NTHREADS, 1) void conv_mma_kernel(
    const float* __restrict__ x, const float* __restrict__ coords, const float* __restrict__ W,
    const float* __restrict__ bias, float* __restrict__ out) {
    extern __shared__ char smem[];
    uint2* frag = (uint2*)(smem + SM_FRAG);
    float* xsh = (float*)(smem + SM_X);
    float* csh = (float*)(smem + SM_C);
    float* wsh = (float*)(smem + SM_W);

    const int tid = threadIdx.x;
    const int wid = tid >> 5;
    const int lane = tid & 31;
    const int t = lane & 3;  /* frag column group (c / o-pair selector) */
    const int g = lane >> 2; /* frag row group */
    const int mrowg = wid & 3;
    const int ncolg = wid >> 2;
    const int le0 = mrowg * 32;

    /* One-time: bake W into per-lane tf32 B fragments.
       B frag for m16n8k8: b0 = W[o = nt*8 + g][c = ks*8 + t][kk], b1 = same with c+4 */
    for (int i = tid; i < KW * 8 * 8 * 32; i += NTHREADS) {
        int kk = i >> 11;
        int r = i & 2047;
        int ks = r >> 8;
        int r2 = r & 255;
        int nt = r2 >> 5;
        int li = r2 & 31;
        int c = ks * 8 + (li & 3);
        int o = nt * 8 + (li >> 2);
        uint2 f;
        f.x = cvt_tf32(W[(o * CIN + c) * KW + kk]);
        f.y = cvt_tf32(W[(o * CIN + c + 4) * KW + kk]);
        frag[i] = f;
    }

    /* per-thread fixed output columns: o = ncolg*32 + nt*8 + t*2 + {0,1} */
    float bz[4][2];
#pragma unroll
    for (int nt = 0; nt < 4; nt++) {
        bz[nt][0] = bias[ncolg * 32 + nt * 8 + t * 2];
        bz[nt][1] = bias[ncolg * 32 + nt * 8 + t * 2 + 1];
    }
    float s1[4][2], s2[4][2];
#pragma unroll
    for (int nt = 0; nt < 4; nt++)
#pragma unroll
        for (int j = 0; j < 2; j++) {
            s1[nt][j] = 0.f;
            s2[nt][j] = 0.f;
        }
    __syncthreads();

    for (int tt = blockIdx.x; tt < NTILES; tt += gridDim.x) {
        const int b = tt >> 10;
        const int l0 = (tt & (TPB_L - 1)) * TILE;
        __syncthreads(); /* previous tile fully consumed before restage */

        const float* xb = x + (size_t)b * CIN * LSEQ;
        for (int i = tid; i < CIN * XW; i += NTHREADS) {
            int c = i / XW;
            int j = i - c * XW;
            int l = l0 - PADW + j;
            xsh[i] = (l >= 0 && l < LSEQ) ? xb[(size_t)c * LSEQ + l] : 0.0f;
        }
        const float* cb = coords + (size_t)b * 3 * LSEQ;
        for (int i = tid; i < 3 * XW; i += NTHREADS) {
            int d = i / XW;
            int j = i - d * XW;
            int l = l0 - PADW + j;
            csh[i] = (l >= 0 && l < LSEQ) ? cb[(size_t)d * LSEQ + l] : 0.0f;
        }
        __syncthreads();

        for (int i = tid; i < KW * TILE; i += NTHREADS) {
            int k = i / TILE;
            int lc = i - k * TILE;
            float d0 = csh[lc + k] - csh[lc + PADW];
            float d1 = csh[XW + lc + k] - csh[XW + lc + PADW];
            float d2 = csh[2 * XW + lc + k] - csh[2 * XW + lc + PADW];
            wsh[i] = __expf(-0.5f * (d0 * d0 + d1 * d1 + d2 * d2));
        }
        __syncthreads();

        float acc[2][4][4];
#pragma unroll
        for (int mt = 0; mt < 2; mt++)
#pragma unroll
            for (int nt = 0; nt < 4; nt++)
#pragma unroll
                for (int j = 0; j < 4; j++) acc[mt][nt][j] = 0.f;

#pragma unroll 1
        for (int kk = 0; kk < KW; kk++) {
            /* Gaussian weights for this thread's A rows (per m-tile: rows g, g+8) */
            float wA[2], wB[2];
            wA[0] = wsh[kk * TILE + le0 + g];
            wB[0] = wsh[kk * TILE + le0 + g + 8];
            wA[1] = wsh[kk * TILE + le0 + 16 + g];
            wB[1] = wsh[kk * TILE + le0 + 24 + g];
            const float* xbase = xsh + kk; /* x[c][le+kk] = xsh[c*XW + le + kk] */
            const uint2* fb0 = frag + ((kk * 8) * 8 + ncolg * 4) * 32 + lane;
#pragma unroll
            for (int ks = 0; ks < 8; ks++) {
                const uint2* fb = fb0 + ks * 256;
                uint2 bf0 = fb[0];
                uint2 bf1 = fb[32];
                uint2 bf2 = fb[64];
                uint2 bf3 = fb[96];
                uint32_t af[2][4];
#pragma unroll
                for (int mt = 0; mt < 2; mt++) {
                    const float* xp = xbase + (ks * 8 + t) * XW + le0 + mt * 16 + g;
                    float x0 = xp[0];
                    float x1 = xp[8];
                    float x2 = xp[4 * XW];
                    float x3 = xp[4 * XW + 8];
                    af[mt][0] = cvt_tf32(x0 * wA[mt]);
                    af[mt][1] = cvt_tf32(x1 * wB[mt]);
                    af[mt][2] = cvt_tf32(x2 * wA[mt]);
                    af[mt][3] = cvt_tf32(x3 * wB[mt]);
                }
#pragma unroll
                for (int mt = 0; mt < 2; mt++) {
                    mma_tf32(acc[mt][0], af[mt][0], af[mt][1], af[mt][2], af[mt][3], bf0.x, bf0.y);
                    mma_tf32(acc[mt][1], af[mt][0], af[mt][1], af[mt][2], af[mt][3], bf1.x, bf1.y);
                    mma_tf32(acc[mt][2], af[mt][0], af[mt][1], af[mt][2], af[mt][3], bf2.x, bf2.y);
                    mma_tf32(acc[mt][3], af[mt][0], af[mt][1], af[mt][2], af[mt][3], bf3.x, bf3.y);
                }
            }
        }

        /* epilogue: +bias, store raw conv result, accumulate stats.
           c-frag: c0 (row g,   col 2t), c1 (row g,   col 2t+1),
                   c2 (row g+8, col 2t), c3 (row g+8, col 2t+1) */
        float* outb = out + (size_t)b * COUT * LSEQ + l0;
#pragma unroll
        for (int mt = 0; mt < 2; mt++) {
            int le = le0 + mt * 16 + g;
#pragma unroll
            for (int nt = 0; nt < 4; nt++) {
                int o = ncolg * 32 + nt * 8 + t * 2;
                float v0 = acc[mt][nt][0] + bz[nt][0];
                float v1 = acc[mt][nt][1] + bz[nt][1];
                float v2 = acc[mt][nt][2] + bz[nt][0];
                float v3 = acc[mt][nt][3] + bz[nt][1];
                outb[(size_t)o * LSEQ + le] = v0;
                outb[(size_t)(o + 1) * LSEQ + le] = v1;
                outb[(size_t)o * LSEQ + le + 8] = v2;
                outb[(size_t)(o + 1) * LSEQ + le + 8] = v3;
                s1[nt][0] += v0 + v2;
                s1[nt][1] += v1 + v3;
                s2[nt][0] += v0 * v0 + v2 * v2;
                s2[nt][1] += v1 * v1 + v3 * v3;
            }
        }
    }

    /* flush stats: reduce over lanes sharing the same t (xor 4,8,16 preserves t) */
#pragma unroll
    for (int nt = 0; nt < 4; nt++)
#pragma unroll
        for (int j = 0; j < 2; j++) {
            float a = s1[nt][j], q = s2[nt][j];
#pragma unroll
            for (int off = 16; off >= 4; off >>= 1) {
                a += __shfl_xor_sync(0xffffffffu, a, off);
                q += __shfl_xor_sync(0xffffffffu, q, off);
            }
            if (g == 0) {
                int o = ncolg * 32 + nt * 8 + t * 2 + j;
                atomicAdd(&g_sum[o], (double)a);
                atomicAdd(&g_sumsq[o], (double)q);
            }
        }
}

__global__ void stats_kernel(const float* __restrict__ gamma, const float* __restrict__ beta) {
    int o = threadIdx.x;
    if (o < COUT) {
        double N = (double)BATCH * (double)LSEQ;
        double mean = g_sum[o] / N;
        double var = g_sumsq[o] / N - mean * mean;
        double rstd = 1.0 / sqrt(var + 1e-5);
        float sc = gamma[o] * (float)rstd;
        g_scale[o] = sc;
        g_shift[o] = beta[o] - (float)mean * sc;
    }
}

__global__ void norm_kernel(float* __restrict__ out) {
    const size_t total4 = (size_t)BATCH * COUT * LSEQ / 4;
    size_t stride = (size_t)gridDim.x * blockDim.x;
    for (size_t i = (size_t)blockIdx.x * blockDim.x + threadIdx.x; i < total4; i += stride) {
        float4 v = reinterpret_cast<float4*>(out)[i];
        int ch = (int)((i * 4 / LSEQ)) & (COUT - 1);
        float sc = g_scale[ch];
        float sh = g_shift[ch];
        v.x = fmaxf(fmaf(v.x, sc, sh), 0.0f);
        v.y = fmaxf(fmaf(v.y, sc, sh), 0.0f);
        v.z = fmaxf(fmaf(v.z, sc, sh), 0.0f);
        v.w = fmaxf(fmaf(v.w, sc, sh), 0.0f);
        reinterpret_cast<float4*>(out)[i] = v;
    }
}

extern "C" void kernel_launch(void* const* d_in, const int* in_sizes, int n_in, void* d_out,
                              int out_size) {
    const float* x = (const float*)d_in[0];       // [4,64,131072]
    const float* coords = (const float*)d_in[1];  // [4,3,131072]
    const float* W = (const float*)d_in[2];       // [64,64,9]
    const float* bias = (const float*)d_in[3];    // [64]
    const float* gamma = (const float*)d_in[4];   // [64]
    const float* beta = (const float*)d_in[5];    // [64]
    float* out = (float*)d_out;

    cudaFuncSetAttribute(conv_mma_kernel, cudaFuncAttributeMaxDynamicSharedMemorySize, SM_TOTAL);
    int sms = 148;
    cudaDeviceGetAttribute(&sms, cudaDevAttrMultiProcessorCount, 0);

    zero_stats_kernel<<<1, 128>>>();
    conv_mma_kernel<<<sms, NTHREADS, SM_TOTAL>>>(x, coords, W, bias, out);
    stats_kernel<<<1, 64>>>(gamma, beta);
    norm_kernel<<<8192, 256>>>(out);
}

// round 5
// speedup vs baseline: 2.5041x; 1.1257x over previous
#include <cuda_runtime.h>
#include <math.h>
#include <stddef.h>
#include <stdint.h>

#define BATCH 4
#define CIN 64
#define COUT 64
#define LSEQ 131072
#define KW 9
#define PADW 4
#define TILE 128
#define XW (TILE + 2 * PADW) /* 136 */
#define NTHREADS 512
#define TPB_L (LSEQ / TILE)    /* 1024 */
#define NTILES (BATCH * TPB_L) /* 4096 */

/* SMEM layout (bytes):
   FRAG: tf32 B fragments, uint2 per lane: [kk][ks][nt][lane] = 9*8*8*32*8 = 147456
   XSH : x tile [64][136] f32 = 34816
   CSH : coords [3][136] f32  = 1632
   WSH : gaussian w [9][128]  = 4608          total = 188512 */
#define SM_FRAG 0
#define SM_X (SM_FRAG + KW * 8 * 8 * 32 * 8)
#define SM_C (SM_X + CIN * XW * 4)
#define SM_W (SM_C + 3 * XW * 4)
#define SM_TOTAL (SM_W + KW * TILE * 4)

static __device__ double g_sum[COUT];
static __device__ double g_sumsq[COUT];
static __device__ float g_scale[COUT];
static __device__ float g_shift[COUT];

__device__ __forceinline__ uint32_t cvt_tf32(float v) {
    uint32_t r;
    asm("cvt.rna.tf32.f32 %0, %1;" : "=r"(r) : "f"(v));
    return r;
}

__device__ __forceinline__ void mma_tf32(float* d, uint32_t a0, uint32_t a1, uint32_t a2,
                                         uint32_t a3, uint32_t b0, uint32_t b1) {
    asm volatile(
        "mma.sync.aligned.m16n8k8.row.col.f32.tf32.tf32.f32 "
        "{%0,%1,%2,%3}, {%4,%5,%6,%7}, {%8,%9}, {%0,%1,%2,%3};"
        : "+f"(d[0]), "+f"(d[1]), "+f"(d[2]), "+f"(d[3])
        : "r"(a0), "r"(a1), "r"(a2), "r"(a3), "r"(b0), "r"(b1));
}

__global__ void zero_stats_kernel() {
    int i = threadIdx.x;
    if (i < COUT) {
        g_sum[i] = 0.0;
        g_sumsq[i] = 0.0;
    }
}

__global__ __launch_bounds__(NTHREADS, 1) void conv_mma_kernel(
    const float* __restrict__ x, const float* __restrict__ coords, const float* __restrict__ W,
    const float* __restrict__ bias, float* __restrict__ out) {
    extern __shared__ char smem[];
    uint2* frag = (uint2*)(smem + SM_FRAG);
    float* xsh = (float*)(smem + SM_X);
    float* csh = (float*)(smem + SM_C);
    float* wsh = (float*)(smem + SM_W);

    const int tid = threadIdx.x;
    const int wid = tid >> 5;
    const int lane = tid & 31;
    const int t = lane & 3;  /* frag column group */
    const int g = lane >> 2; /* frag row group */
    const int mrowg = wid & 7;  /* 16 L rows per warp */
    const int ncolg = wid >> 3; /* 32 Couts per warp */
    const int le0 = mrowg * 16;

    /* One-time: bake W into per-lane tf32 B fragments.
       B frag for m16n8k8: b0 = W[o = nt*8 + g][c = ks*8 + t][kk], b1 = same with c+4 */
    for (int i = tid; i < KW * 8 * 8 * 32; i += NTHREADS) {
        int kk = i >> 11;
        int r = i & 2047;
        int ks = r >> 8;
        int r2 = r & 255;
        int nt = r2 >> 5;
        int li = r2 & 31;
        int c = ks * 8 + (li & 3);
        int o = nt * 8 + (li >> 2);
        uint2 f;
        f.x = cvt_tf32(W[(o * CIN + c) * KW + kk]);
        f.y = cvt_tf32(W[(o * CIN + c + 4) * KW + kk]);
        frag[i] = f;
    }

    /* per-thread fixed output columns: o = ncolg*32 + nt*8 + t*2 + {0,1} */
    float bz[4][2];
#pragma unroll
    for (int nt = 0; nt < 4; nt++) {
        bz[nt][0] = bias[ncolg * 32 + nt * 8 + t * 2];
        bz[nt][1] = bias[ncolg * 32 + nt * 8 + t * 2 + 1];
    }
    float s1[4][2], s2[4][2];
#pragma unroll
    for (int nt = 0; nt < 4; nt++)
#pragma unroll
        for (int j = 0; j < 2; j++) {
            s1[nt][j] = 0.f;
            s2[nt][j] = 0.f;
        }
    __syncthreads();

    for (int tt = blockIdx.x; tt < NTILES; tt += gridDim.x) {
        const int b = tt >> 10;
        const int l0 = (tt & (TPB_L - 1)) * TILE;
        __syncthreads(); /* previous tile fully consumed before restage */

        /* stage x: vectorized core (l0 is 512B-aligned) + scalar halo */
        const float* xb = x + (size_t)b * CIN * LSEQ;
        {
            const float4* xb4 = (const float4*)(xb + l0);
            for (int f = tid; f < CIN * 32; f += NTHREADS) {
                int c = f >> 5;
                int q = f & 31;
                *(float4*)&xsh[c * XW + 4 + 4 * q] = xb4[c * (LSEQ / 4) + q];
            }
            for (int i = tid; i < CIN * 8; i += NTHREADS) {
                int c = i >> 3;
                int j = i & 7;
                int jj = (j < 4) ? j : 128 + j; /* 0..3 or 132..135 */
                int l = l0 - PADW + jj;
                xsh[c * XW + jj] = (l >= 0 && l < LSEQ) ? xb[(size_t)c * LSEQ + l] : 0.0f;
            }
        }
        const float* cb = coords + (size_t)b * 3 * LSEQ;
        for (int i = tid; i < 3 * XW; i += NTHREADS) {
            int d = i / XW;
            int j = i - d * XW;
            int l = l0 - PADW + j;
            csh[i] = (l >= 0 && l < LSEQ) ? cb[(size_t)d * LSEQ + l] : 0.0f;
        }
        __syncthreads();

        for (int i = tid; i < KW * TILE; i += NTHREADS) {
            int k = i / TILE;
            int lc = i - k * TILE;
            float d0 = csh[lc + k] - csh[lc + PADW];
            float d1 = csh[XW + lc + k] - csh[XW + lc + PADW];
            float d2 = csh[2 * XW + lc + k] - csh[2 * XW + lc + PADW];
            wsh[i] = __expf(-0.5f * (d0 * d0 + d1 * d1 + d2 * d2));
        }
        __syncthreads();

        float acc[4][4];
#pragma unroll
        for (int nt = 0; nt < 4; nt++)
#pragma unroll
            for (int j = 0; j < 4; j++) acc[nt][j] = 0.f;

#pragma unroll 1
        for (int kk = 0; kk < KW; kk++) {
            /* Gaussian weights for this thread's A rows (rows g and g+8 of warp tile) */
            const float wA = wsh[kk * TILE + le0 + g];
            const float wB = wsh[kk * TILE + le0 + g + 8];
            const float* xbase = xsh + kk + le0 + g; /* x[c][le+kk] */
            const uint2* fb0 = frag + ((kk * 8) * 8 + ncolg * 4) * 32 + lane;
#pragma unroll
            for (int ks = 0; ks < 8; ks++) {
                const uint2* fb = fb0 + ks * 256;
                uint2 bf0 = fb[0];
                uint2 bf1 = fb[32];
                uint2 bf2 = fb[64];
                uint2 bf3 = fb[96];
                const float* xp = xbase + (ks * 8 + t) * XW;
                float x0 = xp[0];
                float x1 = xp[8];
                float x2 = xp[4 * XW];
                float x3 = xp[4 * XW + 8];
                uint32_t a0 = cvt_tf32(x0 * wA);
                uint32_t a1 = cvt_tf32(x1 * wB);
                uint32_t a2 = cvt_tf32(x2 * wA);
                uint32_t a3 = cvt_tf32(x3 * wB);
                mma_tf32(acc[0], a0, a1, a2, a3, bf0.x, bf0.y);
                mma_tf32(acc[1], a0, a1, a2, a3, bf1.x, bf1.y);
                mma_tf32(acc[2], a0, a1, a2, a3, bf2.x, bf2.y);
                mma_tf32(acc[3], a0, a1, a2, a3, bf3.x, bf3.y);
            }
        }

        /* epilogue: +bias, store raw conv result, accumulate stats.
           c-frag: c0 (row g, col 2t), c1 (row g, col 2t+1),
                   c2 (row g+8, col 2t), c3 (row g+8, col 2t+1) */
        float* outb = out + (size_t)b * COUT * LSEQ + l0;
        const int le = le0 + g;
#pragma unroll
        for (int nt = 0; nt < 4; nt++) {
            int o = ncolg * 32 + nt * 8 + t * 2;
            float v0 = acc[nt][0] + bz[nt][0];
            float v1 = acc[nt][1] + bz[nt][1];
            float v2 = acc[nt][2] + bz[nt][0];
            float v3 = acc[nt][3] + bz[nt][1];
            outb[(size_t)o * LSEQ + le] = v0;
            outb[(size_t)(o + 1) * LSEQ + le] = v1;
            outb[(size_t)o * LSEQ + le + 8] = v2;
            outb[(size_t)(o + 1) * LSEQ + le + 8] = v3;
            s1[nt][0] += v0 + v2;
            s1[nt][1] += v1 + v3;
            s2[nt][0] += v0 * v0 + v2 * v2;
            s2[nt][1] += v1 * v1 + v3 * v3;
        }
    }

    /* flush stats: reduce over lanes sharing the same t (xor 4,8,16 preserves t) */
#pragma unroll
    for (int nt = 0; nt < 4; nt++)
#pragma unroll
        for (int j = 0; j < 2; j++) {
            float a = s1[nt][j], q = s2[nt][j];
#pragma unroll
            for (int off = 16; off >= 4; off >>= 1) {
                a += __shfl_xor_sync(0xffffffffu, a, off);
                q += __shfl_xor_sync(0xffffffffu, q, off);
            }
            if (g == 0) {
                int o = ncolg * 32 + nt * 8 + t * 2 + j;
                atomicAdd(&g_sum[o], (double)a);
                atomicAdd(&g_sumsq[o], (double)q);
            }
        }
}

__global__ void stats_kernel(const float* __restrict__ gamma, const float* __restrict__ beta) {
    int o = threadIdx.x;
    if (o < COUT) {
        double N = (double)BATCH * (double)LSEQ;
        double mean = g_sum[o] / N;
        double var = g_sumsq[o] / N - mean * mean;
        double rstd = 1.0 / sqrt(var + 1e-5);
        float sc = gamma[o] * (float)rstd;
        g_scale[o] = sc;
        g_shift[o] = beta[o] - (float)mean * sc;
    }
}

__global__ void norm_kernel(float* __restrict__ out) {
    const size_t total4 = (size_t)BATCH * COUT * LSEQ / 4;
    size_t stride = (size_t)gridDim.x * blockDim.x;
    for (size_t i = (size_t)blockIdx.x * blockDim.x + threadIdx.x; i < total4; i += stride) {
        float4 v = reinterpret_cast<float4*>(out)[i];
        int ch = (int)((i * 4 / LSEQ)) & (COUT - 1);
        float sc = g_scale[ch];
        float sh = g_shift[ch];
        v.x = fmaxf(fmaf(v.x, sc, sh), 0.0f);
        v.y = fmaxf(fmaf(v.y, sc, sh), 0.0f);
        v.z = fmaxf(fmaf(v.z, sc, sh), 0.0f);
        v.w = fmaxf(fmaf(v.w, sc, sh), 0.0f);
        reinterpret_cast<float4*>(out)[i] = v;
    }
}

extern "C" void kernel_launch(void* const* d_in, const int* in_sizes, int n_in, void* d_out,
                              int out_size) {
    const float* x = (const float*)d_in[0];       // [4,64,131072]
    const float* coords = (const float*)d_in[1];  // [4,3,131072]
    const float* W = (const float*)d_in[2];       // [64,64,9]
    const float* bias = (const float*)d_in[3];    // [64]
    const float* gamma = (const float*)d_in[4];   // [64]
    const float* beta = (const float*)d_in[5];    // [64]
    float* out = (float*)d_out;

    cudaFuncSetAttribute(conv_mma_kernel, cudaFuncAttributeMaxDynamicSharedMemorySize, SM_TOTAL);
    int sms = 148;
    cudaDeviceGetAttribute(&sms, cudaDevAttrMultiProcessorCount, 0);

    zero_stats_kernel<<<1, 128>>>();
    conv_mma_kernel<<<sms, NTHREADS, SM_TOTAL>>>(x, coords, W, bias, out);
    stats_kernel<<<1, 64>>>(gamma, beta);
    norm_kernel<<<8192, 256>>>(out);
}

// round 7
// speedup vs baseline: 3.0699x; 1.2259x over previous
#include <cuda_runtime.h>
#include <math.h>
#include <stddef.h>
#include <stdint.h>

#define BATCH 4
#define CIN 64
#define COUT 64
#define LSEQ 131072
#define KW 9
#define PADW 4
#define TILE 128
#define XW 136 /* valid extent */
#define XS 140 /* padded row stride (floats) — conflict-free A loads */
#define NTHREADS 512
#define TPB_L (LSEQ / TILE)    /* 1024 */
#define NTILES (BATCH * TPB_L) /* 4096 */

/* SMEM layout (bytes):
   FRAG: fp16 B fragments, uint2/lane: [kk][ks][nt=8][lane] = 9*4*8*32*8 = 73728
   XSH : x tile [64][140] f32 = 35840
   CSH : coords [3][136] f32  = 1632
   WSH : gaussian w [9][128]  = 4608      total = 115808 */
#define SM_FRAG 0
#define SM_X (SM_FRAG + KW * 4 * 8 * 32 * 8)
#define SM_C (SM_X + CIN * XS * 4)
#define SM_W (SM_C + 3 * XW * 4)
#define SM_TOTAL (SM_W + KW * TILE * 4)

static __device__ double g_sum[COUT];
static __device__ double g_sumsq[COUT];
static __device__ float g_scale[COUT];
static __device__ float g_shift[COUT];

/* pack two f32 -> f16x2 reg: lo half = 'even', hi half = 'odd' */
__device__ __forceinline__ uint32_t pack_f16x2(float even, float odd) {
    uint32_t r;
    asm("cvt.rn.f16x2.f32 %0, %1, %2;" : "=r"(r) : "f"(odd), "f"(even));
    return r;
}

__device__ __forceinline__ void mma_f16(float* d, uint32_t a0, uint32_t a1, uint32_t a2,
                                        uint32_t a3, uint32_t b0, uint32_t b1) {
    asm volatile(
        "mma.sync.aligned.m16n8k16.row.col.f32.f16.f16.f32 "
        "{%0,%1,%2,%3}, {%4,%5,%6,%7}, {%8,%9}, {%0,%1,%2,%3};"
        : "+f"(d[0]), "+f"(d[1]), "+f"(d[2]), "+f"(d[3])
        : "r"(a0), "r"(a1), "r"(a2), "r"(a3), "r"(b0), "r"(b1));
}

__global__ void zero_stats_kernel() {
    int i = threadIdx.x;
    if (i < COUT) {
        g_sum[i] = 0.0;
        g_sumsq[i] = 0.0;
    }
}

__global__ __launch_bounds__(NTHREADS, 1) void conv_mma_kernel(
    const float* __restrict__ x, const float* __restrict__ coords, const float* __restrict__ W,
    const float* __restrict__ bias, float* __restrict__ out) {
    extern __shared__ char smem[];
    uint2* frag = (uint2*)(smem + SM_FRAG);
    float* xsh = (float*)(smem + SM_X);
    float* csh = (float*)(smem + SM_C);
    float* wsh = (float*)(smem + SM_W);

    const int tid = threadIdx.x;
    const int wid = tid >> 5;
    const int lane = tid & 31;
    const int t = lane & 3;     /* frag k-pair selector */
    const int g = lane >> 2;    /* frag row group */
    const int mrowg = wid & 7;  /* 16 L rows per warp */
    const int ncolg = wid >> 3; /* 32 Couts per warp */
    const int le0 = mrowg * 16;

    /* One-time: bake W into per-lane fp16 B fragments (m16n8k16.col), nt = 0..7:
       o = nt*8 + (lane>>2), c = ks*16 + 2*(lane&3);
       b0 = {k=c, k=c+1} at n=o; b1 = {k=c+8, k=c+9} at n=o */
    for (int i = tid; i < KW * 4 * 8 * 32; i += NTHREADS) {
        int kk = i >> 10;
        int r = i & 1023;
        int ks = r >> 8;
        int r2 = r & 255;
        int nt = r2 >> 5;
        int li = r2 & 31;
        int c = ks * 16 + 2 * (li & 3);
        int o = nt * 8 + (li >> 2);
        const float* wp = W + (size_t)(o * CIN + c) * KW + kk;
        uint2 f;
        f.x = pack_f16x2(wp[0], wp[KW]);
        f.y = pack_f16x2(wp[8 * KW], wp[9 * KW]);
        frag[i] = f;
    }

    /* per-thread fixed output columns: o = ncolg*32 + nt*8 + t*2 + {0,1} */
    float bz[4][2];
#pragma unroll
    for (int nt = 0; nt < 4; nt++) {
        bz[nt][0] = bias[ncolg * 32 + nt * 8 + t * 2];
        bz[nt][1] = bias[ncolg * 32 + nt * 8 + t * 2 + 1];
    }
    float s1[4][2], s2[4][2];
#pragma unroll
    for (int nt = 0; nt < 4; nt++)
#pragma unroll
        for (int j = 0; j < 2; j++) {
            s1[nt][j] = 0.f;
            s2[nt][j] = 0.f;
        }
    __syncthreads();

    for (int tt = blockIdx.x; tt < NTILES; tt += gridDim.x) {
        const int b = tt >> 10;
        const int l0 = (tt & (TPB_L - 1)) * TILE;
        __syncthreads(); /* previous tile fully consumed before restage */

        /* stage x: vectorized core (l0 is 512B-aligned) + scalar halo */
        const float* xb = x + (size_t)b * CIN * LSEQ;
        {
            const float4* xb4 = (const float4*)(xb + l0);
            for (int f = tid; f < CIN * 32; f += NTHREADS) {
                int c = f >> 5;
                int q = f & 31;
                *(float4*)&xsh[c * XS + 4 + 4 * q] = xb4[c * (LSEQ / 4) + q];
            }
            for (int i = tid; i < CIN * 8; i += NTHREADS) {
                int c = i >> 3;
                int j = i & 7;
                int jj = (j < 4) ? j : 128 + j; /* 0..3 or 132..135 */
                int l = l0 - PADW + jj;
                xsh[c * XS + jj] = (l >= 0 && l < LSEQ) ? xb[(size_t)c * LSEQ + l] : 0.0f;
            }
        }
        const float* cb = coords + (size_t)b * 3 * LSEQ;
        for (int i = tid; i < 3 * XW; i += NTHREADS) {
            int d = i / XW;
            int j = i - d * XW;
            int l = l0 - PADW + j;
            csh[i] = (l >= 0 && l < LSEQ) ? cb[(size_t)d * LSEQ + l] : 0.0f;
        }
        __syncthreads();

        for (int i = tid; i < KW * TILE; i += NTHREADS) {
            int k = i / TILE;
            int lc = i - k * TILE;
            float d0 = csh[lc + k] - csh[lc + PADW];
            float d1 = csh[XW + lc + k] - csh[XW + lc + PADW];
            float d2 = csh[2 * XW + lc + k] - csh[2 * XW + lc + PADW];
            wsh[i] = __expf(-0.5f * (d0 * d0 + d1 * d1 + d2 * d2));
        }
        __syncthreads();

        float acc[4][4];
#pragma unroll
        for (int nt = 0; nt < 4; nt++)
#pragma unroll
            for (int j = 0; j < 4; j++) acc[nt][j] = 0.f;

#pragma unroll 1
        for (int kk = 0; kk < KW; kk++) {
            const float wA = wsh[kk * TILE + le0 + g];     /* row g    */
            const float wB = wsh[kk * TILE + le0 + g + 8]; /* row g+8  */
            /* x[c][le+kk], this lane reads channels (2t, 2t+1, 2t+8, 2t+9) + ks*16 */
            const float* xbase = xsh + kk + le0 + g + 2 * t * XS;
#pragma unroll
            for (int ks = 0; ks < 4; ks++) {
                const uint2* fb = frag + (size_t)(((kk * 4 + ks) * 8 + ncolg * 4) * 32 + lane);
                uint2 bf0 = fb[0];
                uint2 bf1 = fb[32];
                uint2 bf2 = fb[64];
                uint2 bf3 = fb[96];
                const float* xp = xbase + ks * 16 * XS;
                float xe0 = xp[0];          /* c=2t,   row g   */
                float xo0 = xp[XS];         /* c=2t+1, row g   */
                float xe1 = xp[8];          /* c=2t,   row g+8 */
                float xo1 = xp[XS + 8];     /* c=2t+1, row g+8 */
                float xe2 = xp[8 * XS];     /* c=2t+8, row g   */
                float xo2 = xp[9 * XS];     /* c=2t+9, row g   */
                float xe3 = xp[8 * XS + 8]; /* c=2t+8, row g+8 */
                float xo3 = xp[9 * XS + 8]; /* c=2t+9, row g+8 */
                uint32_t a0 = pack_f16x2(xe0 * wA, xo0 * wA);
                uint32_t a1 = pack_f16x2(xe1 * wB, xo1 * wB);
                uint32_t a2 = pack_f16x2(xe2 * wA, xo2 * wA);
                uint32_t a3 = pack_f16x2(xe3 * wB, xo3 * wB);
                mma_f16(acc[0], a0, a1, a2, a3, bf0.x, bf0.y);
                mma_f16(acc[1], a0, a1, a2, a3, bf1.x, bf1.y);
                mma_f16(acc[2], a0, a1, a2, a3, bf2.x, bf2.y);
                mma_f16(acc[3], a0, a1, a2, a3, bf3.x, bf3.y);
            }
        }

        /* epilogue: +bias, store raw conv, accumulate stats.
           c-frag: c0 (row g, col 2t), c1 (row g, col 2t+1),
                   c2 (row g+8, col 2t), c3 (row g+8, col 2t+1) */
        float* outb = out + (size_t)b * COUT * LSEQ + l0;
        const int le = le0 + g;
#pragma unroll
        for (int nt = 0; nt < 4; nt++) {
            int o = ncolg * 32 + nt * 8 + t * 2;
            float v0 = acc[nt][0] + bz[nt][0];
            float v1 = acc[nt][1] + bz[nt][1];
            float v2 = acc[nt][2] + bz[nt][0];
            float v3 = acc[nt][3] + bz[nt][1];
            outb[(size_t)o * LSEQ + le] = v0;
            outb[(size_t)(o + 1) * LSEQ + le] = v1;
            outb[(size_t)o * LSEQ + le + 8] = v2;
            outb[(size_t)(o + 1) * LSEQ + le + 8] = v3;
            s1[nt][0] += v0 + v2;
            s1[nt][1] += v1 + v3;
            s2[nt][0] += v0 * v0 + v2 * v2;
            s2[nt][1] += v1 * v1 + v3 * v3;
        }
    }

    /* flush stats: reduce over lanes sharing the same t (xor 4,8,16 preserves t) */
#pragma unroll
    for (int nt = 0; nt < 4; nt++)
#pragma unroll
        for (int j = 0; j < 2; j++) {
            float a = s1[nt][j], q = s2[nt][j];
#pragma unroll
            for (int off = 16; off >= 4; off >>= 1) {
                a += __shfl_xor_sync(0xffffffffu, a, off);
                q += __shfl_xor_sync(0xffffffffu, q, off);
            }
            if (g == 0) {
                int o = ncolg * 32 + nt * 8 + t * 2 + j;
                atomicAdd(&g_sum[o], (double)a);
                atomicAdd(&g_sumsq[o], (double)q);
            }
        }
}

__global__ void stats_kernel(const float* __restrict__ gamma, const float* __restrict__ beta) {
    int o = threadIdx.x;
    if (o < COUT) {
        double N = (double)BATCH * (double)LSEQ;
        double mean = g_sum[o] / N;
        double var = g_sumsq[o] / N - mean * mean;
        double rstd = 1.0 / sqrt(var + 1e-5);
        float sc = gamma[o] * (float)rstd;
        g_scale[o] = sc;
        g_shift[o] = beta[o] - (float)mean * sc;
    }
}

__global__ void norm_kernel(float* __restrict__ out) {
    const size_t total4 = (size_t)BATCH * COUT * LSEQ / 4;
    size_t stride = (size_t)gridDim.x * blockDim.x;
    for (size_t i = (size_t)blockIdx.x * blockDim.x + threadIdx.x; i < total4; i += stride) {
        float4 v = reinterpret_cast<float4*>(out)[i];
        int ch = (int)((i * 4 / LSEQ)) & (COUT - 1);
        float sc = g_scale[ch];
        float sh = g_shift[ch];
        v.x = fmaxf(fmaf(v.x, sc, sh), 0.0f);
        v.y = fmaxf(fmaf(v.y, sc, sh), 0.0f);
        v.z = fmaxf(fmaf(v.z, sc, sh), 0.0f);
        v.w = fmaxf(fmaf(v.w, sc, sh), 0.0f);
        reinterpret_cast<float4*>(out)[i] = v;
    }
}

extern "C" void kernel_launch(void* const* d_in, const int* in_sizes, int n_in, void* d_out,
                              int out_size) {
    const float* x = (const float*)d_in[0];       // [4,64,131072]
    const float* coords = (const float*)d_in[1];  // [4,3,131072]
    const float* W = (const float*)d_in[2];       // [64,64,9]
    const float* bias = (const float*)d_in[3];    // [64]
    const float* gamma = (const float*)d_in[4];   // [64]
    const float* beta = (const float*)d_in[5];    // [64]
    float* out = (float*)d_out;

    cudaFuncSetAttribute(conv_mma_kernel, cudaFuncAttributeMaxDynamicSharedMemorySize, SM_TOTAL);
    int sms = 148;
    cudaDeviceGetAttribute(&sms, cudaDevAttrMultiProcessorCount, 0);

    zero_stats_kernel<<<1, 128>>>();
    conv_mma_kernel<<<sms, NTHREADS, SM_TOTAL>>>(x, coords, W, bias, out);
    stats_kernel<<<1, 64>>>(gamma, beta);
    norm_kernel<<<8192, 256>>>(out);
}

// round 8
// speedup vs baseline: 3.7031x; 1.2063x over previous
#include <cuda_runtime.h>
#include <math.h>
#include <stddef.h>
#include <stdint.h>

#define BATCH 4
#define CIN 64
#define COUT 64
#define LSEQ 131072
#define KW 9
#define PADW 4
#define TILE 256
#define JW 264 /* padded rows of xht */
#define NTHREADS 512
#define TPB_L (LSEQ / TILE)    /* 512 */
#define NTILES (BATCH * TPB_L) /* 2048 */

/* SMEM (bytes):
   FRAG: fp16 B frags uint2/lane [kk][ks][nt8][lane] = 9*4*8*32*8 = 73728
   XHT : fp16 x^T tile, swizzled 128B rows [j=264][c=64]   = 33792
   CSH : coords [3][264] f32 = 3168
   WSH : gaussian [9][256] f32 = 9216
   BIAS: 256                                   total 120160 */
#define SM_FRAG 0
#define SM_XT (SM_FRAG + KW * 4 * 8 * 32 * 8)
#define SM_C (SM_XT + JW * 128)
#define SM_W (SM_C + 3 * JW * 4)
#define SM_BIAS (SM_W + KW * TILE * 4)
#define SM_TOTAL (SM_BIAS + COUT * 4)

static __device__ double g_sum[COUT];
static __device__ double g_sumsq[COUT];
static __device__ float g_scale[COUT];
static __device__ float g_shift[COUT];

__device__ __forceinline__ uint32_t smem_u32(const void* p) {
    uint32_t a;
    asm("{ .reg .u64 t; cvta.to.shared.u64 t, %1; cvt.u32.u64 %0, t; }" : "=r"(a) : "l"(p));
    return a;
}
/* pack two f32 -> f16x2: lo half = 'even', hi half = 'odd' */
__device__ __forceinline__ uint32_t pack_f16x2(float even, float odd) {
    uint32_t r;
    asm("cvt.rn.f16x2.f32 %0, %1, %2;" : "=r"(r) : "f"(odd), "f"(even));
    return r;
}
__device__ __forceinline__ uint32_t hmul2(uint32_t a, uint32_t b) {
    uint32_t r;
    asm("mul.rn.f16x2 %0, %1, %2;" : "=r"(r) : "r"(a), "r"(b));
    return r;
}
__device__ __forceinline__ void ldsm_x4(uint32_t* r, uint32_t addr) {
    asm volatile("ldmatrix.sync.aligned.m8n8.x4.shared.b16 {%0,%1,%2,%3}, [%4];"
                 : "=r"(r[0]), "=r"(r[1]), "=r"(r[2]), "=r"(r[3])
                 : "r"(addr));
}
__device__ __forceinline__ void mma_f16(float* d, uint32_t a0, uint32_t a1, uint32_t a2,
                                        uint32_t a3, uint32_t b0, uint32_t b1) {
    asm volatile(
        "mma.sync.aligned.m16n8k16.row.col.f32.f16.f16.f32 "
        "{%0,%1,%2,%3}, {%4,%5,%6,%7}, {%8,%9}, {%0,%1,%2,%3};"
        : "+f"(d[0]), "+f"(d[1]), "+f"(d[2]), "+f"(d[3])
        : "r"(a0), "r"(a1), "r"(a2), "r"(a3), "r"(b0), "r"(b1));
}

__global__ void zero_stats_kernel() {
    int i = threadIdx.x;
    if (i < COUT) {
        g_sum[i] = 0.0;
        g_sumsq[i] = 0.0;
    }
}

__global__ __launch_bounds__(NTHREADS, 1) void conv_mma_kernel(
    const float* __restrict__ x, const float* __restrict__ coords, const float* __restrict__ W,
    const float* __restrict__ bias, float* __restrict__ out) {
    extern __shared__ char smem[];
    uint2* frag = (uint2*)(smem + SM_FRAG);
    float* csh = (float*)(smem + SM_C);
    float* wsh = (float*)(smem + SM_W);
    float* bsh = (float*)(smem + SM_BIAS);
    const uint32_t sxt = smem_u32(smem + SM_XT);

    const int tid = threadIdx.x;
    const int wid = tid >> 5;
    const int lane = tid & 31;
    const int t = lane & 3;
    const int g = lane >> 2;
    const int mrowg = wid & 7;  /* 32 L rows per warp */
    const int ncolg = wid >> 3; /* 32 Couts per warp */
    const int le0 = mrowg * 32;
    /* ldmatrix lane geometry */
    const int rr = lane & 15;           /* row offset within x4 */
    const int ee = (lane >> 4) << 2;    /* +4 words when lane>=16 (k+8 half) */

    /* One-time: bake W into fp16 B fragments (m16n8k16.col), nt = 0..7 */
    for (int i = tid; i < KW * 4 * 8 * 32; i += NTHREADS) {
        int kk = i >> 10;
        int r = i & 1023;
        int ks = r >> 8;
        int r2 = r & 255;
        int nt = r2 >> 5;
        int li = r2 & 31;
        int c = ks * 16 + 2 * (li & 3);
        int o = nt * 8 + (li >> 2);
        const float* wp = W + (size_t)(o * CIN + c) * KW + kk;
        uint2 f;
        f.x = pack_f16x2(wp[0], wp[KW]);
        f.y = pack_f16x2(wp[8 * KW], wp[9 * KW]);
        frag[i] = f;
    }
    for (int i = tid; i < COUT; i += NTHREADS) bsh[i] = bias[i];

    float bz[4][2];
#pragma unroll
    for (int nt = 0; nt < 4; nt++) {
        bz[nt][0] = bias[ncolg * 32 + nt * 8 + t * 2];
        bz[nt][1] = bias[ncolg * 32 + nt * 8 + t * 2 + 1];
    }
    float s1[4][2], s2[4][2];
#pragma unroll
    for (int nt = 0; nt < 4; nt++)
#pragma unroll
        for (int j = 0; j < 2; j++) {
            s1[nt][j] = 0.f;
            s2[nt][j] = 0.f;
        }
    __syncthreads();

    for (int tt = blockIdx.x; tt < NTILES; tt += gridDim.x) {
        const int b = tt / TPB_L;
        const int l0 = (tt - b * TPB_L) * TILE;
        __syncthreads(); /* previous tile fully consumed before restage */

        /* ---- stage xht: fp16 transposed [j][c], swizzled 128B rows ----
           core: warp w owns c = 4w..4w+3; iter it owns j-block 32it. */
        {
            const float* xb = x + (size_t)b * CIN * LSEQ + l0;
            const int i4 = lane >> 3; /* c sub-row 0..3 */
            const int q = lane & 7;   /* j quad selector */
#pragma unroll 1
            for (int it = 0; it < 8; it++) {
                float4 v = *(const float4*)(xb + (size_t)(4 * wid + i4) * LSEQ + 32 * it + 4 * q);
                /* 4x4 transpose among lanes {q, q+8, q+16, q+24} */
                if (i4 & 1) { float tmp = v.x; v.x = v.y; v.y = tmp; tmp = v.z; v.z = v.w; v.w = tmp; }
                v.y = __shfl_xor_sync(0xffffffffu, v.y, 8);
                v.w = __shfl_xor_sync(0xffffffffu, v.w, 8);
                if (i4 & 1) { float tmp = v.x; v.x = v.y; v.y = tmp; tmp = v.z; v.z = v.w; v.w = tmp; }
                if (i4 & 2) { float tmp = v.x; v.x = v.z; v.z = tmp; tmp = v.y; v.y = v.w; v.w = tmp; }
                v.z = __shfl_xor_sync(0xffffffffu, v.z, 16);
                v.w = __shfl_xor_sync(0xffffffffu, v.w, 16);
                if (i4 & 2) { float tmp = v.x; v.x = v.z; v.z = tmp; tmp = v.y; v.y = v.w; v.w = tmp; }
                /* thread now holds c = 4w..4w+3 at j = PADW + 32it + 4q + i4 */
                int j = PADW + 32 * it + 4 * q + i4;
                uint32_t h0 = pack_f16x2(v.x, v.y);
                uint32_t h1 = pack_f16x2(v.z, v.w);
                uint32_t word = (uint32_t)j * 32 + (((uint32_t)(2 * wid)) ^ (((uint32_t)(j & 7)) << 2));
                asm volatile("st.shared.v2.b32 [%0], {%1, %2};" ::"r"(sxt + word * 4), "r"(h0),
                             "r"(h1)
                             : "memory");
            }
            /* halo: j in {0..3} U {260..263}, fp16 pairs */
            if (tid < 256) {
                int c2 = tid & 31;
                int hs = tid >> 5;
                int j = (hs < 4) ? hs : 256 + hs;
                int l = l0 - PADW + j;
                const float* xr = x + (size_t)b * CIN * LSEQ + (size_t)(2 * c2) * LSEQ;
                float e = (l >= 0 && l < LSEQ) ? xr[l] : 0.0f;
                float o = (l >= 0 && l < LSEQ) ? xr[LSEQ + l] : 0.0f;
                uint32_t h = pack_f16x2(e, o);
                uint32_t word = (uint32_t)j * 32 + (((uint32_t)c2) ^ (((uint32_t)(j & 7)) << 2));
                asm volatile("st.shared.b32 [%0], %1;" ::"r"(sxt + word * 4), "r"(h) : "memory");
            }
        }
        /* stage coords */
        const float* cb = coords + (size_t)b * 3 * LSEQ;
        for (int i = tid; i < 3 * JW; i += NTHREADS) {
            int d = i / JW;
            int j = i - d * JW;
            int l = l0 - PADW + j;
            csh[i] = (l >= 0 && l < LSEQ) ? cb[(size_t)d * LSEQ + l] : 0.0f;
        }
        __syncthreads();

        for (int i = tid; i < KW * TILE; i += NTHREADS) {
            int k = i / TILE;
            int lc = i - k * TILE;
            float d0 = csh[lc + k] - csh[lc + PADW];
            float d1 = csh[JW + lc + k] - csh[JW + lc + PADW];
            float d2 = csh[2 * JW + lc + k] - csh[2 * JW + lc + PADW];
            wsh[i] = __expf(-0.5f * (d0 * d0 + d1 * d1 + d2 * d2));
        }
        __syncthreads();

        float acc[2][4][4];
#pragma unroll
        for (int mt = 0; mt < 2; mt++)
#pragma unroll
            for (int nt = 0; nt < 4; nt++)
#pragma unroll
                for (int j = 0; j < 4; j++) acc[mt][nt][j] = 0.f;

#pragma unroll 1
        for (int kk = 0; kk < KW; kk++) {
            /* replicated f16x2 weights for this thread's 4 A rows */
            uint32_t wh[2][2];
            uint32_t rowa[2], mxor[2];
#pragma unroll
            for (int mt = 0; mt < 2; mt++) {
                float wg = wsh[kk * TILE + le0 + mt * 16 + g];
                float wg8 = wsh[kk * TILE + le0 + mt * 16 + g + 8];
                wh[mt][0] = pack_f16x2(wg, wg);
                wh[mt][1] = pack_f16x2(wg8, wg8);
                int jj = le0 + mt * 16 + kk + rr;
                rowa[mt] = sxt + (uint32_t)jj * 128;
                mxor[mt] = ((uint32_t)(jj & 7)) << 2;
            }
#pragma unroll
            for (int ks = 0; ks < 4; ks++) {
                const uint2* fb = frag + (size_t)(((kk * 4 + ks) * 8 + ncolg * 4) * 32 + lane);
                uint2 bf0 = fb[0];
                uint2 bf1 = fb[32];
                uint2 bf2 = fb[64];
                uint2 bf3 = fb[96];
                uint32_t a[2][4];
#pragma unroll
                for (int mt = 0; mt < 2; mt++) {
                    uint32_t addr =
                        rowa[mt] + ((((uint32_t)(8 * ks) + (uint32_t)ee) ^ mxor[mt]) << 2);
                    ldsm_x4(a[mt], addr);
                    a[mt][0] = hmul2(a[mt][0], wh[mt][0]);
                    a[mt][1] = hmul2(a[mt][1], wh[mt][1]);
                    a[mt][2] = hmul2(a[mt][2], wh[mt][0]);
                    a[mt][3] = hmul2(a[mt][3], wh[mt][1]);
                }
#pragma unroll
                for (int mt = 0; mt < 2; mt++) {
                    mma_f16(acc[mt][0], a[mt][0], a[mt][1], a[mt][2], a[mt][3], bf0.x, bf0.y);
                    mma_f16(acc[mt][1], a[mt][0], a[mt][1], a[mt][2], a[mt][3], bf1.x, bf1.y);
                    mma_f16(acc[mt][2], a[mt][0], a[mt][1], a[mt][2], a[mt][3], bf2.x, bf2.y);
                    mma_f16(acc[mt][3], a[mt][0], a[mt][1], a[mt][2], a[mt][3], bf3.x, bf3.y);
                }
            }
        }

        /* epilogue: +bias, store raw conv, stats */
        float* outb = out + (size_t)b * COUT * LSEQ + l0;
#pragma unroll
        for (int mt = 0; mt < 2; mt++) {
            const int le = le0 + mt * 16 + g;
#pragma unroll
            for (int nt = 0; nt < 4; nt++) {
                int o = ncolg * 32 + nt * 8 + t * 2;
                float v0 = acc[mt][nt][0] + bz[nt][0];
                float v1 = acc[mt][nt][1] + bz[nt][1];
                float v2 = acc[mt][nt][2] + bz[nt][0];
                float v3 = acc[mt][nt][3] + bz[nt][1];
                outb[(size_t)o * LSEQ + le] = v0;
                outb[(size_t)(o + 1) * LSEQ + le] = v1;
                outb[(size_t)o * LSEQ + le + 8] = v2;
                outb[(size_t)(o + 1) * LSEQ + le + 8] = v3;
                s1[nt][0] += v0 + v2;
                s1[nt][1] += v1 + v3;
                s2[nt][0] += v0 * v0 + v2 * v2;
                s2[nt][1] += v1 * v1 + v3 * v3;
            }
        }
    }

    /* flush stats: reduce over lanes sharing t (xor 16,8,4 preserves t) */
#pragma unroll
    for (int nt = 0; nt < 4; nt++)
#pragma unroll
        for (int j = 0; j < 2; j++) {
            float a = s1[nt][j], q = s2[nt][j];
#pragma unroll
            for (int off = 16; off >= 4; off >>= 1) {
                a += __shfl_xor_sync(0xffffffffu, a, off);
                q += __shfl_xor_sync(0xffffffffu, q, off);
            }
            if (g == 0) {
                int o = ncolg * 32 + nt * 8 + t * 2 + j;
                atomicAdd(&g_sum[o], (double)a);
                atomicAdd(&g_sumsq[o], (double)q);
            }
        }
}

__global__ void stats_kernel(const float* __restrict__ gamma, const float* __restrict__ beta) {
    int o = threadIdx.x;
    if (o < COUT) {
        double N = (double)BATCH * (double)LSEQ;
        double mean = g_sum[o] / N;
        double var = g_sumsq[o] / N - mean * mean;
        double rstd = 1.0 / sqrt(var + 1e-5);
        float sc = gamma[o] * (float)rstd;
        g_scale[o] = sc;
        g_shift[o] = beta[o] - (float)mean * sc;
    }
}

__global__ void norm_kernel(float* __restrict__ out) {
    const size_t total4 = (size_t)BATCH * COUT * LSEQ / 4;
    size_t stride = (size_t)gridDim.x * blockDim.x;
    for (size_t i = (size_t)blockIdx.x * blockDim.x + threadIdx.x; i < total4; i += stride) {
        float4 v = reinterpret_cast<float4*>(out)[i];
        int ch = (int)((i * 4 / LSEQ)) & (COUT - 1);
        float sc = g_scale[ch];
        float sh = g_shift[ch];
        v.x = fmaxf(fmaf(v.x, sc, sh), 0.0f);
        v.y = fmaxf(fmaf(v.y, sc, sh), 0.0f);
        v.z = fmaxf(fmaf(v.z, sc, sh), 0.0f);
        v.w = fmaxf(fmaf(v.w, sc, sh), 0.0f);
        reinterpret_cast<float4*>(out)[i] = v;
    }
}

extern "C" void kernel_launch(void* const* d_in, const int* in_sizes, int n_in, void* d_out,
                              int out_size) {
    const float* x = (const float*)d_in[0];       // [4,64,131072]
    const float* coords = (const float*)d_in[1];  // [4,3,131072]
    const float* W = (const float*)d_in[2];       // [64,64,9]
    const float* bias = (const float*)d_in[3];    // [64]
    const float* gamma = (const float*)d_in[4];   // [64]
    const float* beta = (const float*)d_in[5];    // [64]
    float* out = (float*)d_out;

    cudaFuncSetAttribute(conv_mma_kernel, cudaFuncAttributeMaxDynamicSharedMemorySize, SM_TOTAL);
    int sms = 148;
    cudaDeviceGetAttribute(&sms, cudaDevAttrMultiProcessorCount, 0);

    zero_stats_kernel<<<1, 128>>>();
    conv_mma_kernel<<<sms, NTHREADS, SM_TOTAL>>>(x, coords, W, bias, out);
    stats_kernel<<<1, 64>>>(gamma, beta);
    norm_kernel<<<8192, 256>>>(out);
}

// round 9
// speedup vs baseline: 3.7044x; 1.0003x over previous
#include <cuda_runtime.h>
#include <math.h>
#include <stddef.h>
#include <stdint.h>

#define BATCH 4
#define CIN 64
#define COUT 64
#define LSEQ 131072
#define KW 9
#define PADW 4
#define TILE 512
#define JW 520 /* padded rows of xht */
#define NTHREADS 512
#define TPB_L (LSEQ / TILE)    /* 256 */
#define NTILES (BATCH * TPB_L) /* 1024 */

/* SMEM (bytes):
   FRAG: fp16 B frags uint4/lane [kk][ks][np=4][lane] = 9*4*4*32*16 = 73728
   XHT : fp16 x^T tile, swizzled 128B rows [j=520][c=64] = 66560
   CSH : coords [3][520] f32 = 6240
   WSH : gaussian [9][512] f32 = 18432        total = 164960 */
#define SM_FRAG 0
#define SM_XT (SM_FRAG + KW * 4 * 4 * 32 * 16)
#define SM_C (SM_XT + JW * 128)
#define SM_W (SM_C + 3 * JW * 4)
#define SM_TOTAL (SM_W + KW * TILE * 4)

static __device__ double g_sum[COUT];
static __device__ double g_sumsq[COUT];
static __device__ float g_scale[COUT];
static __device__ float g_shift[COUT];

__device__ __forceinline__ uint32_t smem_u32(const void* p) {
    uint32_t a;
    asm("{ .reg .u64 t; cvta.to.shared.u64 t, %1; cvt.u32.u64 %0, t; }" : "=r"(a) : "l"(p));
    return a;
}
/* pack two f32 -> f16x2: lo half = 'even', hi half = 'odd' */
__device__ __forceinline__ uint32_t pack_f16x2(float even, float odd) {
    uint32_t r;
    asm("cvt.rn.f16x2.f32 %0, %1, %2;" : "=r"(r) : "f"(odd), "f"(even));
    return r;
}
__device__ __forceinline__ uint32_t hmul2(uint32_t a, uint32_t b) {
    uint32_t r;
    asm("mul.rn.f16x2 %0, %1, %2;" : "=r"(r) : "r"(a), "r"(b));
    return r;
}
__device__ __forceinline__ void ldsm_x4(uint32_t* r, uint32_t addr) {
    asm volatile("ldmatrix.sync.aligned.m8n8.x4.shared.b16 {%0,%1,%2,%3}, [%4];"
                 : "=r"(r[0]), "=r"(r[1]), "=r"(r[2]), "=r"(r[3])
                 : "r"(addr));
}
__device__ __forceinline__ void mma_f16(float* d, uint32_t a0, uint32_t a1, uint32_t a2,
                                        uint32_t a3, uint32_t b0, uint32_t b1) {
    asm volatile(
        "mma.sync.aligned.m16n8k16.row.col.f32.f16.f16.f32 "
        "{%0,%1,%2,%3}, {%4,%5,%6,%7}, {%8,%9}, {%0,%1,%2,%3};"
        : "+f"(d[0]), "+f"(d[1]), "+f"(d[2]), "+f"(d[3])
        : "r"(a0), "r"(a1), "r"(a2), "r"(a3), "r"(b0), "r"(b1));
}

__global__ void zero_stats_kernel() {
    int i = threadIdx.x;
    if (i < COUT) {
        g_sum[i] = 0.0;
        g_sumsq[i] = 0.0;
    }
}

__global__ __launch_bounds__(NTHREADS, 1) void conv_mma_kernel(
    const float* __restrict__ x, const float* __restrict__ coords, const float* __restrict__ W,
    const float* __restrict__ bias, float* __restrict__ out) {
    extern __shared__ char smem[];
    uint4* frag = (uint4*)(smem + SM_FRAG);
    float* csh = (float*)(smem + SM_C);
    float* wsh = (float*)(smem + SM_W);
    const uint32_t sxt = smem_u32(smem + SM_XT);

    const int tid = threadIdx.x;
    const int wid = tid >> 5;
    const int lane = tid & 31;
    const int t = lane & 3;
    const int g = lane >> 2;
    const int mrowg = wid & 7;  /* 64 L rows per warp */
    const int ncolg = wid >> 3; /* 32 Couts per warp */
    const int le0 = mrowg * 64;
    const int rr = lane & 15;        /* ldmatrix row offset */
    const int ee = (lane >> 4) << 2; /* +4 words when lane>=16 */

    /* One-time: bake W into fp16 B fragments, nt-paired (uint4/lane):
       np=0..3 covers nt={2np, 2np+1}; o = nt*8 + (lane>>2), c = ks*16 + 2*(lane&3) */
    for (int i = tid; i < KW * 4 * 4 * 32; i += NTHREADS) {
        int kk = i >> 9;
        int r = i & 511;
        int ks = r >> 7;
        int r2 = r & 127;
        int np = r2 >> 5;
        int li = r2 & 31;
        int c = ks * 16 + 2 * (li & 3);
        int o0 = 2 * np * 8 + (li >> 2);
        const float* wp0 = W + (size_t)(o0 * CIN + c) * KW + kk;
        const float* wp1 = wp0 + (size_t)8 * CIN * KW;
        uint4 f;
        f.x = pack_f16x2(wp0[0], wp0[KW]);
        f.y = pack_f16x2(wp0[8 * KW], wp0[9 * KW]);
        f.z = pack_f16x2(wp1[0], wp1[KW]);
        f.w = pack_f16x2(wp1[8 * KW], wp1[9 * KW]);
        frag[i] = f;
    }

    float bz[4][2];
#pragma unroll
    for (int nt = 0; nt < 4; nt++) {
        bz[nt][0] = bias[ncolg * 32 + nt * 8 + t * 2];
        bz[nt][1] = bias[ncolg * 32 + nt * 8 + t * 2 + 1];
    }
    float s1[4][2], s2[4][2];
#pragma unroll
    for (int nt = 0; nt < 4; nt++)
#pragma unroll
        for (int j = 0; j < 2; j++) {
            s1[nt][j] = 0.f;
            s2[nt][j] = 0.f;
        }
    __syncthreads();

    for (int tt = blockIdx.x; tt < NTILES; tt += gridDim.x) {
        const int b = tt >> 8;
        const int l0 = (tt & (TPB_L - 1)) * TILE;
        __syncthreads(); /* previous tile fully consumed before restage */

        /* ---- stage xht: fp16 transposed [j][c], swizzled 128B rows ---- */
        {
            const float* xb = x + (size_t)b * CIN * LSEQ + l0;
            const int i4 = lane >> 3; /* c sub-row 0..3 */
            const int q = lane & 7;   /* j quad selector */
#pragma unroll 1
            for (int it = 0; it < 16; it++) {
                float4 v = *(const float4*)(xb + (size_t)(4 * wid + i4) * LSEQ + 32 * it + 4 * q);
                if (i4 & 1) { float tmp = v.x; v.x = v.y; v.y = tmp; tmp = v.z; v.z = v.w; v.w = tmp; }
                v.y = __shfl_xor_sync(0xffffffffu, v.y, 8);
                v.w = __shfl_xor_sync(0xffffffffu, v.w, 8);
                if (i4 & 1) { float tmp = v.x; v.x = v.y; v.y = tmp; tmp = v.z; v.z = v.w; v.w = tmp; }
                if (i4 & 2) { float tmp = v.x; v.x = v.z; v.z = tmp; tmp = v.y; v.y = v.w; v.w = tmp; }
                v.z = __shfl_xor_sync(0xffffffffu, v.z, 16);
                v.w = __shfl_xor_sync(0xffffffffu, v.w, 16);
                if (i4 & 2) { float tmp = v.x; v.x = v.z; v.z = tmp; tmp = v.y; v.y = v.w; v.w = tmp; }
                int j = PADW + 32 * it + 4 * q + i4;
                uint32_t h0 = pack_f16x2(v.x, v.y);
                uint32_t h1 = pack_f16x2(v.z, v.w);
                uint32_t word =
                    (uint32_t)j * 32 + (((uint32_t)(2 * wid)) ^ (((uint32_t)(j & 7)) << 2));
                asm volatile("st.shared.v2.b32 [%0], {%1, %2};" ::"r"(sxt + word * 4), "r"(h0),
                             "r"(h1)
                             : "memory");
            }
            /* halo: j in {0..3} U {516..519} */
            if (tid < 256) {
                int c2 = tid & 31;
                int hs = tid >> 5;
                int j = (hs < 4) ? hs : 512 + hs;
                int l = l0 - PADW + j;
                const float* xr = x + (size_t)b * CIN * LSEQ + (size_t)(2 * c2) * LSEQ;
                float e = (l >= 0 && l < LSEQ) ? xr[l] : 0.0f;
                float o = (l >= 0 && l < LSEQ) ? xr[LSEQ + l] : 0.0f;
                uint32_t h = pack_f16x2(e, o);
                uint32_t word = (uint32_t)j * 32 + (((uint32_t)c2) ^ (((uint32_t)(j & 7)) << 2));
                asm volatile("st.shared.b32 [%0], %1;" ::"r"(sxt + word * 4), "r"(h) : "memory");
            }
        }
        /* stage coords */
        const float* cb = coords + (size_t)b * 3 * LSEQ;
        for (int i = tid; i < 3 * JW; i += NTHREADS) {
            int d = i / JW;
            int j = i - d * JW;
            int l = l0 - PADW + j;
            csh[i] = (l >= 0 && l < LSEQ) ? cb[(size_t)d * LSEQ + l] : 0.0f;
        }
        __syncthreads();

        for (int i = tid; i < KW * TILE; i += NTHREADS) {
            int k = i >> 9;
            int lc = i & (TILE - 1);
            float d0 = csh[lc + k] - csh[lc + PADW];
            float d1 = csh[JW + lc + k] - csh[JW + lc + PADW];
            float d2 = csh[2 * JW + lc + k] - csh[2 * JW + lc + PADW];
            wsh[i] = __expf(-0.5f * (d0 * d0 + d1 * d1 + d2 * d2));
        }
        __syncthreads();

        float acc[4][4][4];
#pragma unroll
        for (int mt = 0; mt < 4; mt++)
#pragma unroll
            for (int nt = 0; nt < 4; nt++)
#pragma unroll
                for (int j = 0; j < 4; j++) acc[mt][nt][j] = 0.f;

#pragma unroll 1
        for (int kk = 0; kk < KW; kk++) {
            uint32_t wh[4][2];
            uint32_t rowa[4], mxor[4];
#pragma unroll
            for (int mt = 0; mt < 4; mt++) {
                float wg = wsh[kk * TILE + le0 + mt * 16 + g];
                float wg8 = wsh[kk * TILE + le0 + mt * 16 + g + 8];
                wh[mt][0] = pack_f16x2(wg, wg);
                wh[mt][1] = pack_f16x2(wg8, wg8);
                int jj = le0 + mt * 16 + kk + rr;
                rowa[mt] = sxt + (uint32_t)jj * 128;
                mxor[mt] = ((uint32_t)(jj & 7)) << 2;
            }
#pragma unroll
            for (int ks = 0; ks < 4; ks++) {
                const uint4* fbq = frag + (size_t)(((kk * 4 + ks) * 4 + ncolg * 2) * 32 + lane);
                uint4 q0 = fbq[0];  /* nt0, nt1 */
                uint4 q1 = fbq[32]; /* nt2, nt3 */
                const uint32_t koff = ((uint32_t)(8 * ks) + (uint32_t)ee);
#pragma unroll
                for (int mt = 0; mt < 4; mt++) {
                    uint32_t a[4];
                    ldsm_x4(a, rowa[mt] + ((koff ^ mxor[mt]) << 2));
                    a[0] = hmul2(a[0], wh[mt][0]);
                    a[1] = hmul2(a[1], wh[mt][1]);
                    a[2] = hmul2(a[2], wh[mt][0]);
                    a[3] = hmul2(a[3], wh[mt][1]);
                    mma_f16(acc[mt][0], a[0], a[1], a[2], a[3], q0.x, q0.y);
                    mma_f16(acc[mt][1], a[0], a[1], a[2], a[3], q0.z, q0.w);
                    mma_f16(acc[mt][2], a[0], a[1], a[2], a[3], q1.x, q1.y);
                    mma_f16(acc[mt][3], a[0], a[1], a[2], a[3], q1.z, q1.w);
                }
            }
        }

        /* epilogue: +bias, store raw conv, stats */
        float* outb = out + (size_t)b * COUT * LSEQ + l0;
#pragma unroll
        for (int mt = 0; mt < 4; mt++) {
            const int le = le0 + mt * 16 + g;
#pragma unroll
            for (int nt = 0; nt < 4; nt++) {
                int o = ncolg * 32 + nt * 8 + t * 2;
                float v0 = acc[mt][nt][0] + bz[nt][0];
                float v1 = acc[mt][nt][1] + bz[nt][1];
                float v2 = acc[mt][nt][2] + bz[nt][0];
                float v3 = acc[mt][nt][3] + bz[nt][1];
                outb[(size_t)o * LSEQ + le] = v0;
                outb[(size_t)(o + 1) * LSEQ + le] = v1;
                outb[(size_t)o * LSEQ + le + 8] = v2;
                outb[(size_t)(o + 1) * LSEQ + le + 8] = v3;
                s1[nt][0] += v0 + v2;
                s1[nt][1] += v1 + v3;
                s2[nt][0] += v0 * v0 + v2 * v2;
                s2[nt][1] += v1 * v1 + v3 * v3;
            }
        }
    }

    /* flush stats: reduce over lanes sharing t (xor 16,8,4 preserves t) */
#pragma unroll
    for (int nt = 0; nt < 4; nt++)
#pragma unroll
        for (int j = 0; j < 2; j++) {
            float a = s1[nt][j], q = s2[nt][j];
#pragma unroll
            for (int off = 16; off >= 4; off >>= 1) {
                a += __shfl_xor_sync(0xffffffffu, a, off);
                q += __shfl_xor_sync(0xffffffffu, q, off);
            }
            if (g == 0) {
                int o = ncolg * 32 + nt * 8 + t * 2 + j;
                atomicAdd(&g_sum[o], (double)a);
                atomicAdd(&g_sumsq[o], (double)q);
            }
        }
}

__global__ void stats_kernel(const float* __restrict__ gamma, const float* __restrict__ beta) {
    int o = threadIdx.x;
    if (o < COUT) {
        double N = (double)BATCH * (double)LSEQ;
        double mean = g_sum[o] / N;
        double var = g_sumsq[o] / N - mean * mean;
        double rstd = 1.0 / sqrt(var + 1e-5);
        float sc = gamma[o] * (float)rstd;
        g_scale[o] = sc;
        g_shift[o] = beta[o] - (float)mean * sc;
    }
}

__global__ void norm_kernel(float* __restrict__ out) {
    const size_t total4 = (size_t)BATCH * COUT * LSEQ / 4;
    size_t stride = (size_t)gridDim.x * blockDim.x;
    for (size_t i = (size_t)blockIdx.x * blockDim.x + threadIdx.x; i < total4; i += stride) {
        float4 v = reinterpret_cast<float4*>(out)[i];
        int ch = (int)((i * 4 / LSEQ)) & (COUT - 1);
        float sc = g_scale[ch];
        float sh = g_shift[ch];
        v.x = fmaxf(fmaf(v.x, sc, sh), 0.0f);
        v.y = fmaxf(fmaf(v.y, sc, sh), 0.0f);
        v.z = fmaxf(fmaf(v.z, sc, sh), 0.0f);
        v.w = fmaxf(fmaf(v.w, sc, sh), 0.0f);
        reinterpret_cast<float4*>(out)[i] = v;
    }
}

extern "C" void kernel_launch(void* const* d_in, const int* in_sizes, int n_in, void* d_out,
                              int out_size) {
    const float* x = (const float*)d_in[0];       // [4,64,131072]
    const float* coords = (const float*)d_in[1];  // [4,3,131072]
    const float* W = (const float*)d_in[2];       // [64,64,9]
    const float* bias = (const float*)d_in[3];    // [64]
    const float* gamma = (const float*)d_in[4];   // [64]
    const float* beta = (const float*)d_in[5];    // [64]
    float* out = (float*)d_out;

    cudaFuncSetAttribute(conv_mma_kernel, cudaFuncAttributeMaxDynamicSharedMemorySize, SM_TOTAL);
    int sms = 148;
    cudaDeviceGetAttribute(&sms, cudaDevAttrMultiProcessorCount, 0);

    zero_stats_kernel<<<1, 128>>>();
    conv_mma_kernel<<<sms, NTHREADS, SM_TOTAL>>>(x, coords, W, bias, out);
    stats_kernel<<<1, 64>>>(gamma, beta);
    norm_kernel<<<8192, 256>>>(out);
}

// round 11
// speedup vs baseline: 4.5919x; 1.2396x over previous
#include <cuda_runtime.h>
#include <cuda_fp16.h>
#include <math.h>
#include <stddef.h>
#include <stdint.h>

#define BATCH 4
#define CIN 64
#define COUT 64
#define LSEQ 131072
#define KW 9
#define PADW 4
#define TILE 512
#define JW 520 /* padded rows of xht */
#define NTHREADS 512
#define TPB_L (LSEQ / TILE)    /* 256 */
#define NTILES (BATCH * TPB_L) /* 1024 */

/* SMEM (bytes) */
#define SM_FRAG 0
#define SM_XT (SM_FRAG + KW * 4 * 4 * 32 * 16) /* 73728 */
#define SM_C (SM_XT + JW * 128)                /* +66560 */
#define SM_W (SM_C + 3 * JW * 4)               /* +6240 */
#define SM_TOTAL (SM_W + KW * TILE * 4)        /* +18432 = 164960 */

static __device__ double g_sum[COUT];
static __device__ double g_sumsq[COUT];
static __device__ float g_scale[COUT];
static __device__ float g_shift[COUT];
static __device__ __align__(16) __half g_scr[(size_t)BATCH * COUT * LSEQ]; /* 67 MB */

__device__ __forceinline__ uint32_t smem_u32(const void* p) {
    uint32_t a;
    asm("{ .reg .u64 t; cvta.to.shared.u64 t, %1; cvt.u32.u64 %0, t; }" : "=r"(a) : "l"(p));
    return a;
}
/* pack two f32 -> f16x2: lo half = 'even', hi half = 'odd' */
__device__ __forceinline__ uint32_t pack_f16x2(float even, float odd) {
    uint32_t r;
    asm("cvt.rn.f16x2.f32 %0, %1, %2;" : "=r"(r) : "f"(odd), "f"(even));
    return r;
}
__device__ __forceinline__ uint32_t hmul2(uint32_t a, uint32_t b) {
    uint32_t r;
    asm("mul.rn.f16x2 %0, %1, %2;" : "=r"(r) : "r"(a), "r"(b));
    return r;
}
__device__ __forceinline__ void ldsm_x4(uint32_t* r, uint32_t addr) {
    asm volatile("ldmatrix.sync.aligned.m8n8.x4.shared.b16 {%0,%1,%2,%3}, [%4];"
                 : "=r"(r[0]), "=r"(r[1]), "=r"(r[2]), "=r"(r[3])
                 : "r"(addr));
}
__device__ __forceinline__ void mma_f16(float* d, uint32_t a0, uint32_t a1, uint32_t a2,
                                        uint32_t a3, uint32_t b0, uint32_t b1) {
    asm volatile(
        "mma.sync.aligned.m16n8k16.row.col.f32.f16.f16.f32 "
        "{%0,%1,%2,%3}, {%4,%5,%6,%7}, {%8,%9}, {%0,%1,%2,%3};"
        : "+f"(d[0]), "+f"(d[1]), "+f"(d[2]), "+f"(d[3])
        : "r"(a0), "r"(a1), "r"(a2), "r"(a3), "r"(b0), "r"(b1));
}

__global__ __launch_bounds__(NTHREADS, 1) void conv_mma_kernel(
    const float* __restrict__ x, const float* __restrict__ coords, const float* __restrict__ W,
    const float* __restrict__ bias) {
    extern __shared__ char smem[];
    uint4* frag = (uint4*)(smem + SM_FRAG);
    float* csh = (float*)(smem + SM_C);
    float* wsh = (float*)(smem + SM_W);
    const uint32_t sxt = smem_u32(smem + SM_XT);

    const int tid = threadIdx.x;
    const int wid = tid >> 5;
    const int lane = tid & 31;
    const int t = lane & 3;
    const int g = lane >> 2;
    const int mrowg = wid & 7;  /* 64 L rows per warp */
    const int ncolg = wid >> 3; /* 32 Couts per warp */
    const int le0 = mrowg * 64;
    const int rr = lane & 15;        /* ldmatrix row offset */
    const int ee = (lane >> 4) << 2; /* +4 words when lane>=16 */

    /* One-time: bake W into fp16 B fragments, nt-paired (uint4/lane) */
    for (int i = tid; i < KW * 4 * 4 * 32; i += NTHREADS) {
        int kk = i >> 9;
        int r = i & 511;
        int ks = r >> 7;
        int r2 = r & 127;
        int np = r2 >> 5;
        int li = r2 & 31;
        int c = ks * 16 + 2 * (li & 3);
        int o0 = 2 * np * 8 + (li >> 2);
        const float* wp0 = W + (size_t)(o0 * CIN + c) * KW + kk;
        const float* wp1 = wp0 + (size_t)8 * CIN * KW;
        uint4 f;
        f.x = pack_f16x2(wp0[0], wp0[KW]);
        f.y = pack_f16x2(wp0[8 * KW], wp0[9 * KW]);
        f.z = pack_f16x2(wp1[0], wp1[KW]);
        f.w = pack_f16x2(wp1[8 * KW], wp1[9 * KW]);
        frag[i] = f;
    }

    float bz[4][2];
#pragma unroll
    for (int nt = 0; nt < 4; nt++) {
        bz[nt][0] = bias[ncolg * 32 + nt * 8 + t * 2];
        bz[nt][1] = bias[ncolg * 32 + nt * 8 + t * 2 + 1];
    }
    float s1[4][2], s2[4][2];
#pragma unroll
    for (int nt = 0; nt < 4; nt++)
#pragma unroll
        for (int j = 0; j < 2; j++) {
            s1[nt][j] = 0.f;
            s2[nt][j] = 0.f;
        }
    __syncthreads();

    for (int tt = blockIdx.x; tt < NTILES; tt += gridDim.x) {
        const int b = tt >> 8;
        const int l0 = (tt & (TPB_L - 1)) * TILE;
        __syncthreads(); /* previous tile fully consumed before restage */

        /* ---- issue coord + halo LDGs early (latency hidden under x pipeline) ----
           coord stage is 3*JW = 1560 floats -> FOUR strided elements per thread */
        const float* cb = coords + (size_t)b * 3 * LSEQ;
        float cr0, cr1, cr2, cr3;
        {
            int i0 = tid, i1 = tid + 512, i2 = tid + 1024, i3 = tid + 1536;
            int d0 = i0 / JW, j0 = i0 - d0 * JW, l0c = l0 - PADW + j0;
            int d1 = i1 / JW, j1 = i1 - d1 * JW, l1c = l0 - PADW + j1;
            int d2 = i2 / JW, j2 = i2 - d2 * JW, l2c = l0 - PADW + j2;
            cr0 = (l0c >= 0 && l0c < LSEQ) ? cb[(size_t)d0 * LSEQ + l0c] : 0.0f;
            cr1 = (l1c >= 0 && l1c < LSEQ) ? cb[(size_t)d1 * LSEQ + l1c] : 0.0f;
            cr2 = (l2c >= 0 && l2c < LSEQ) ? cb[(size_t)d2 * LSEQ + l2c] : 0.0f;
            cr3 = 0.0f;
            if (i3 < 3 * JW) {
                int j3 = i3 - 2 * JW; /* d=2 for all tail entries */
                int l3c = l0 - PADW + j3;
                cr3 = (l3c >= 0 && l3c < LSEQ) ? cb[(size_t)2 * LSEQ + l3c] : 0.0f;
            }
        }
        float he = 0.0f, ho = 0.0f;
        int hj = 0;
        if (tid < 256) {
            int c2 = tid & 31;
            int hs = tid >> 5;
            hj = (hs < 4) ? hs : 512 + hs;
            int l = l0 - PADW + hj;
            const float* xr = x + (size_t)b * CIN * LSEQ + (size_t)(2 * c2) * LSEQ;
            he = (l >= 0 && l < LSEQ) ? xr[l] : 0.0f;
            ho = (l >= 0 && l < LSEQ) ? xr[LSEQ + l] : 0.0f;
        }

        /* ---- stage xht: fp16 transposed [j][c], swizzled; 4-deep LDG pipeline ---- */
        {
            const int i4 = lane >> 3; /* c sub-row 0..3 */
            const int q = lane & 7;   /* j quad selector */
            const float* xrow =
                x + (size_t)b * CIN * LSEQ + l0 + (size_t)(4 * wid + i4) * LSEQ + 4 * q;
            float4 vb[4], vn[4];
#pragma unroll
            for (int i = 0; i < 4; i++) vb[i] = *(const float4*)(xrow + 32 * i);
#pragma unroll 1
            for (int itb = 0; itb < 4; itb++) {
                if (itb < 3) {
#pragma unroll
                    for (int i = 0; i < 4; i++)
                        vn[i] = *(const float4*)(xrow + 32 * (4 * (itb + 1) + i));
                }
#pragma unroll
                for (int i = 0; i < 4; i++) {
                    float4 v = vb[i];
                    if (i4 & 1) { float tmp = v.x; v.x = v.y; v.y = tmp; tmp = v.z; v.z = v.w; v.w = tmp; }
                    v.y = __shfl_xor_sync(0xffffffffu, v.y, 8);
                    v.w = __shfl_xor_sync(0xffffffffu, v.w, 8);
                    if (i4 & 1) { float tmp = v.x; v.x = v.y; v.y = tmp; tmp = v.z; v.z = v.w; v.w = tmp; }
                    if (i4 & 2) { float tmp = v.x; v.x = v.z; v.z = tmp; tmp = v.y; v.y = v.w; v.w = tmp; }
                    v.z = __shfl_xor_sync(0xffffffffu, v.z, 16);
                    v.w = __shfl_xor_sync(0xffffffffu, v.w, 16);
                    if (i4 & 2) { float tmp = v.x; v.x = v.z; v.z = tmp; tmp = v.y; v.y = v.w; v.w = tmp; }
                    int j = PADW + 32 * (4 * itb + i) + 4 * q + i4;
                    uint32_t h0 = pack_f16x2(v.x, v.y);
                    uint32_t h1 = pack_f16x2(v.z, v.w);
                    uint32_t word =
                        (uint32_t)j * 32 + (((uint32_t)(2 * wid)) ^ (((uint32_t)(j & 7)) << 2));
                    asm volatile("st.shared.v2.b32 [%0], {%1, %2};" ::"r"(sxt + word * 4),
                                 "r"(h0), "r"(h1)
                                 : "memory");
                }
#pragma unroll
                for (int i = 0; i < 4; i++) vb[i] = vn[i];
            }
            /* halo store */
            if (tid < 256) {
                int c2 = tid & 31;
                uint32_t h = pack_f16x2(he, ho);
                uint32_t word =
                    (uint32_t)hj * 32 + (((uint32_t)c2) ^ (((uint32_t)(hj & 7)) << 2));
                asm volatile("st.shared.b32 [%0], %1;" ::"r"(sxt + word * 4), "r"(h) : "memory");
            }
        }
        /* coords stores (all four strided slots) */
        csh[tid] = cr0;
        csh[tid + 512] = cr1;
        csh[tid + 1024] = cr2;
        if (tid + 1536 < 3 * JW) csh[tid + 1536] = cr3;
        __syncthreads();

        for (int i = tid; i < KW * TILE; i += NTHREADS) {
            int k = i >> 9;
            int lc = i & (TILE - 1);
            float d0 = csh[lc + k] - csh[lc + PADW];
            float d1 = csh[JW + lc + k] - csh[JW + lc + PADW];
            float d2 = csh[2 * JW + lc + k] - csh[2 * JW + lc + PADW];
            wsh[i] = __expf(-0.5f * (d0 * d0 + d1 * d1 + d2 * d2));
        }
        __syncthreads();

        float acc[4][4][4];
#pragma unroll
        for (int mt = 0; mt < 4; mt++)
#pragma unroll
            for (int nt = 0; nt < 4; nt++)
#pragma unroll
                for (int j = 0; j < 4; j++) acc[mt][nt][j] = 0.f;

#pragma unroll 1
        for (int kk = 0; kk < KW; kk++) {
            uint32_t wh[4][2];
            uint32_t rowa[4], mxor[4];
#pragma unroll
            for (int mt = 0; mt < 4; mt++) {
                float wg = wsh[kk * TILE + le0 + mt * 16 + g];
                float wg8 = wsh[kk * TILE + le0 + mt * 16 + g + 8];
                wh[mt][0] = pack_f16x2(wg, wg);
                wh[mt][1] = pack_f16x2(wg8, wg8);
                int jj = le0 + mt * 16 + kk + rr;
                rowa[mt] = sxt + (uint32_t)jj * 128;
                mxor[mt] = ((uint32_t)(jj & 7)) << 2;
            }
#pragma unroll
            for (int ks = 0; ks < 4; ks++) {
                const uint4* fbq = frag + (size_t)(((kk * 4 + ks) * 4 + ncolg * 2) * 32 + lane);
                uint4 q0 = fbq[0];  /* nt0, nt1 */
                uint4 q1 = fbq[32]; /* nt2, nt3 */
                const uint32_t koff = ((uint32_t)(8 * ks) + (uint32_t)ee);
#pragma unroll
                for (int mt = 0; mt < 4; mt++) {
                    uint32_t a[4];
                    ldsm_x4(a, rowa[mt] + ((koff ^ mxor[mt]) << 2));
                    a[0] = hmul2(a[0], wh[mt][0]);
                    a[1] = hmul2(a[1], wh[mt][1]);
                    a[2] = hmul2(a[2], wh[mt][0]);
                    a[3] = hmul2(a[3], wh[mt][1]);
                    mma_f16(acc[mt][0], a[0], a[1], a[2], a[3], q0.x, q0.y);
                    mma_f16(acc[mt][1], a[0], a[1], a[2], a[3], q0.z, q0.w);
                    mma_f16(acc[mt][2], a[0], a[1], a[2], a[3], q1.x, q1.y);
                    mma_f16(acc[mt][3], a[0], a[1], a[2], a[3], q1.z, q1.w);
                }
            }
        }

        /* epilogue: +bias, store raw conv (fp16 scratch), stats (f32) */
        __half* scrb = g_scr + (size_t)b * COUT * LSEQ + l0;
#pragma unroll
        for (int mt = 0; mt < 4; mt++) {
            const int le = le0 + mt * 16 + g;
#pragma unroll
            for (int nt = 0; nt < 4; nt++) {
                int o = ncolg * 32 + nt * 8 + t * 2;
                float v0 = acc[mt][nt][0] + bz[nt][0];
                float v1 = acc[mt][nt][1] + bz[nt][1];
                float v2 = acc[mt][nt][2] + bz[nt][0];
                float v3 = acc[mt][nt][3] + bz[nt][1];
                scrb[(size_t)o * LSEQ + le] = __float2half_rn(v0);
                scrb[(size_t)(o + 1) * LSEQ + le] = __float2half_rn(v1);
                scrb[(size_t)o * LSEQ + le + 8] = __float2half_rn(v2);
                scrb[(size_t)(o + 1) * LSEQ + le + 8] = __float2half_rn(v3);
                s1[nt][0] += v0 + v2;
                s1[nt][1] += v1 + v3;
                s2[nt][0] += v0 * v0 + v2 * v2;
                s2[nt][1] += v1 * v1 + v3 * v3;
            }
        }
    }

    /* flush stats: reduce over lanes sharing t (xor 16,8,4 preserves t) */
#pragma unroll
    for (int nt = 0; nt < 4; nt++)
#pragma unroll
        for (int j = 0; j < 2; j++) {
            float a = s1[nt][j], q = s2[nt][j];
#pragma unroll
            for (int off = 16; off >= 4; off >>= 1) {
                a += __shfl_xor_sync(0xffffffffu, a, off);
                q += __shfl_xor_sync(0xffffffffu, q, off);
            }
            if (g == 0) {
                int o = ncolg * 32 + nt * 8 + t * 2 + j;
                atomicAdd(&g_sum[o], (double)a);
                atomicAdd(&g_sumsq[o], (double)q);
            }
        }
}

/* Computes per-channel scale/shift, then resets accumulators for the next
   (graph-replayed) run. Statics are zero-initialized at module load, so run 1
   also sees zeros. */
__global__ void stats_kernel(const float* __restrict__ gamma, const float* __restrict__ beta) {
    int o = threadIdx.x;
    if (o < COUT) {
        double N = (double)BATCH * (double)LSEQ;
        double mean = g_sum[o] / N;
        double var = g_sumsq[o] / N - mean * mean;
        double rstd = 1.0 / sqrt(var + 1e-5);
        float sc = gamma[o] * (float)rstd;
        g_scale[o] = sc;
        g_shift[o] = beta[o] - (float)mean * sc;
        g_sum[o] = 0.0;
        g_sumsq[o] = 0.0;
    }
}

__global__ void norm_kernel(float* __restrict__ out) {
    const size_t total4 = (size_t)BATCH * COUT * LSEQ / 4;
    size_t stride = (size_t)gridDim.x * blockDim.x;
    const uint2* scr4 = (const uint2*)g_scr;
    for (size_t i = (size_t)blockIdx.x * blockDim.x + threadIdx.x; i < total4; i += stride) {
        uint2 hv = scr4[i];
        float2 f01 = __half22float2(*(const __half2*)&hv.x);
        float2 f23 = __half22float2(*(const __half2*)&hv.y);
        int ch = (int)((i * 4 / LSEQ)) & (COUT - 1);
        float sc = g_scale[ch];
        float sh = g_shift[ch];
        float4 v;
        v.x = fmaxf(fmaf(f01.x, sc, sh), 0.0f);
        v.y = fmaxf(fmaf(f01.y, sc, sh), 0.0f);
        v.z = fmaxf(fmaf(f23.x, sc, sh), 0.0f);
        v.w = fmaxf(fmaf(f23.y, sc, sh), 0.0f);
        reinterpret_cast<float4*>(out)[i] = v;
    }
}

extern "C" void kernel_launch(void* const* d_in, const int* in_sizes, int n_in, void* d_out,
                              int out_size) {
    const float* x = (const float*)d_in[0];       // [4,64,131072]
    const float* coords = (const float*)d_in[1];  // [4,3,131072]
    const float* W = (const float*)d_in[2];       // [64,64,9]
    const float* bias = (const float*)d_in[3];    // [64]
    const float* gamma = (const float*)d_in[4];   // [64]
    const float* beta = (const float*)d_in[5];    // [64]
    float* out = (float*)d_out;

    cudaFuncSetAttribute(conv_mma_kernel, cudaFuncAttributeMaxDynamicSharedMemorySize, SM_TOTAL);
    int sms = 148;
    cudaDeviceGetAttribute(&sms, cudaDevAttrMultiProcessorCount, 0);

    conv_mma_kernel<<<sms, NTHREADS, SM_TOTAL>>>(x, coords, W, bias);
    stats_kernel<<<1, 64>>>(gamma, beta);
    norm_kernel<<<8192, 256>>>(out);
}

// round 12
// speedup vs baseline: 4.7154x; 1.0269x over previous
#include <cuda_runtime.h>
#include <cuda_fp16.h>
#include <math.h>
#include <stddef.h>
#include <stdint.h>

#define BATCH 4
#define CIN 64
#define COUT 64
#define LSEQ 131072
#define KW 9
#define PADW 4
#define TILE 512
#define JW 520 /* padded rows of xht */
#define NTHREADS 512
#define TPB_L (LSEQ / TILE)    /* 256 */
#define NTILES (BATCH * TPB_L) /* 1024 */

/* SMEM (bytes) */
#define SM_FRAG 0
#define SM_XT (SM_FRAG + KW * 4 * 4 * 32 * 16) /* 73728 */
#define SM_C (SM_XT + JW * 128)                /* +66560 */
#define SM_W (SM_C + 3 * JW * 4)               /* +6240: f16x2-packed gaussian [9][512] */
#define SM_BIAS (SM_W + KW * TILE * 4)         /* +18432 */
#define SM_ST (SM_BIAS + 256)                  /* stats [16][512] f32 = 32768 */
#define SM_TOTAL (SM_ST + 16 * NTHREADS * 4)   /* = 198176 */

static __device__ double g_sum[COUT];
static __device__ double g_sumsq[COUT];
static __device__ float g_scale[COUT];
static __device__ float g_shift[COUT];
static __device__ __align__(16) __half g_scr[(size_t)BATCH * COUT * LSEQ]; /* 67 MB */

__device__ __forceinline__ uint32_t smem_u32(const void* p) {
    uint32_t a;
    asm("{ .reg .u64 t; cvta.to.shared.u64 t, %1; cvt.u32.u64 %0, t; }" : "=r"(a) : "l"(p));
    return a;
}
/* pack two f32 -> f16x2: lo half = 'even', hi half = 'odd' */
__device__ __forceinline__ uint32_t pack_f16x2(float even, float odd) {
    uint32_t r;
    asm("cvt.rn.f16x2.f32 %0, %1, %2;" : "=r"(r) : "f"(odd), "f"(even));
    return r;
}
__device__ __forceinline__ uint32_t hmul2(uint32_t a, uint32_t b) {
    uint32_t r;
    asm("mul.rn.f16x2 %0, %1, %2;" : "=r"(r) : "r"(a), "r"(b));
    return r;
}
__device__ __forceinline__ void ldsm_x4(uint32_t* r, uint32_t addr) {
    asm volatile("ldmatrix.sync.aligned.m8n8.x4.shared.b16 {%0,%1,%2,%3}, [%4];"
                 : "=r"(r[0]), "=r"(r[1]), "=r"(r[2]), "=r"(r[3])
                 : "r"(addr));
}
__device__ __forceinline__ void mma_f16(float* d, uint32_t a0, uint32_t a1, uint32_t a2,
                                        uint32_t a3, uint32_t b0, uint32_t b1) {
    asm volatile(
        "mma.sync.aligned.m16n8k16.row.col.f32.f16.f16.f32 "
        "{%0,%1,%2,%3}, {%4,%5,%6,%7}, {%8,%9}, {%0,%1,%2,%3};"
        : "+f"(d[0]), "+f"(d[1]), "+f"(d[2]), "+f"(d[3])
        : "r"(a0), "r"(a1), "r"(a2), "r"(a3), "r"(b0), "r"(b1));
}

__global__ __launch_bounds__(NTHREADS, 1) void conv_mma_kernel(
    const float* __restrict__ x, const float* __restrict__ coords, const float* __restrict__ W,
    const float* __restrict__ bias) {
    extern __shared__ char smem[];
    uint4* frag = (uint4*)(smem + SM_FRAG);
    float* csh = (float*)(smem + SM_C);
    uint32_t* wsh2 = (uint32_t*)(smem + SM_W);
    float* bsh = (float*)(smem + SM_BIAS);
    float* stsh = (float*)(smem + SM_ST);
    const uint32_t sxt = smem_u32(smem + SM_XT);

    const int tid = threadIdx.x;
    const int wid = tid >> 5;
    const int lane = tid & 31;
    const int t = lane & 3;
    const int g = lane >> 2;
    const int mrowg = wid & 7;  /* 64 L rows per warp */
    const int ncolg = wid >> 3; /* 32 Couts per warp */
    const int le0 = mrowg * 64;
    const int rr = lane & 15;        /* ldmatrix row offset */
    const int ee = (lane >> 4) << 2; /* +4 words when lane>=16 */

    /* One-time: bake W into fp16 B fragments, nt-paired (uint4/lane) */
    for (int i = tid; i < KW * 4 * 4 * 32; i += NTHREADS) {
        int kk = i >> 9;
        int r = i & 511;
        int ks = r >> 7;
        int r2 = r & 127;
        int np = r2 >> 5;
        int li = r2 & 31;
        int c = ks * 16 + 2 * (li & 3);
        int o0 = 2 * np * 8 + (li >> 2);
        const float* wp0 = W + (size_t)(o0 * CIN + c) * KW + kk;
        const float* wp1 = wp0 + (size_t)8 * CIN * KW;
        uint4 f;
        f.x = pack_f16x2(wp0[0], wp0[KW]);
        f.y = pack_f16x2(wp0[8 * KW], wp0[9 * KW]);
        f.z = pack_f16x2(wp1[0], wp1[KW]);
        f.w = pack_f16x2(wp1[8 * KW], wp1[9 * KW]);
        frag[i] = f;
    }
    for (int i = tid; i < COUT; i += NTHREADS) bsh[i] = bias[i];
    /* zero per-thread stats slots: stsh[j*NTHREADS + tid], j = 0..15 */
#pragma unroll
    for (int j = 0; j < 16; j++) stsh[j * NTHREADS + tid] = 0.f;
    __syncthreads();

    for (int tt = blockIdx.x; tt < NTILES; tt += gridDim.x) {
        const int b = tt >> 8;
        const int l0 = (tt & (TPB_L - 1)) * TILE;
        __syncthreads(); /* previous tile fully consumed before restage */

        /* ---- issue coord + halo LDGs early (latency hidden under x pipeline) ----
           coord stage is 3*JW = 1560 floats -> FOUR strided elements per thread */
        const float* cb = coords + (size_t)b * 3 * LSEQ;
        float cr0, cr1, cr2, cr3;
        {
            int i0 = tid, i1 = tid + 512, i2 = tid + 1024, i3 = tid + 1536;
            int d0 = i0 / JW, j0 = i0 - d0 * JW, l0c = l0 - PADW + j0;
            int d1 = i1 / JW, j1 = i1 - d1 * JW, l1c = l0 - PADW + j1;
            int d2 = i2 / JW, j2 = i2 - d2 * JW, l2c = l0 - PADW + j2;
            cr0 = (l0c >= 0 && l0c < LSEQ) ? cb[(size_t)d0 * LSEQ + l0c] : 0.0f;
            cr1 = (l1c >= 0 && l1c < LSEQ) ? cb[(size_t)d1 * LSEQ + l1c] : 0.0f;
            cr2 = (l2c >= 0 && l2c < LSEQ) ? cb[(size_t)d2 * LSEQ + l2c] : 0.0f;
            cr3 = 0.0f;
            if (i3 < 3 * JW) {
                int j3 = i3 - 2 * JW; /* d=2 for all tail entries */
                int l3c = l0 - PADW + j3;
                cr3 = (l3c >= 0 && l3c < LSEQ) ? cb[(size_t)2 * LSEQ + l3c] : 0.0f;
            }
        }
        float he = 0.0f, ho = 0.0f;
        int hj = 0;
        if (tid < 256) {
            int c2 = tid & 31;
            int hs = tid >> 5;
            hj = (hs < 4) ? hs : 512 + hs;
            int l = l0 - PADW + hj;
            const float* xr = x + (size_t)b * CIN * LSEQ + (size_t)(2 * c2) * LSEQ;
            he = (l >= 0 && l < LSEQ) ? xr[l] : 0.0f;
            ho = (l >= 0 && l < LSEQ) ? xr[LSEQ + l] : 0.0f;
        }

        /* ---- stage xht: fp16 transposed [j][c], swizzled; 4-deep LDG pipeline ---- */
        {
            const int i4 = lane >> 3; /* c sub-row 0..3 */
            const int q = lane & 7;   /* j quad selector */
            const float* xrow =
                x + (size_t)b * CIN * LSEQ + l0 + (size_t)(4 * wid + i4) * LSEQ + 4 * q;
            float4 vb[4], vn[4];
#pragma unroll
            for (int i = 0; i < 4; i++) vb[i] = *(const float4*)(xrow + 32 * i);
#pragma unroll 1
            for (int itb = 0; itb < 4; itb++) {
                if (itb < 3) {
#pragma unroll
                    for (int i = 0; i < 4; i++)
                        vn[i] = *(const float4*)(xrow + 32 * (4 * (itb + 1) + i));
                }
#pragma unroll
                for (int i = 0; i < 4; i++) {
                    float4 v = vb[i];
                    if (i4 & 1) { float tmp = v.x; v.x = v.y; v.y = tmp; tmp = v.z; v.z = v.w; v.w = tmp; }
                    v.y = __shfl_xor_sync(0xffffffffu, v.y, 8);
                    v.w = __shfl_xor_sync(0xffffffffu, v.w, 8);
                    if (i4 & 1) { float tmp = v.x; v.x = v.y; v.y = tmp; tmp = v.z; v.z = v.w; v.w = tmp; }
                    if (i4 & 2) { float tmp = v.x; v.x = v.z; v.z = tmp; tmp = v.y; v.y = v.w; v.w = tmp; }
                    v.z = __shfl_xor_sync(0xffffffffu, v.z, 16);
                    v.w = __shfl_xor_sync(0xffffffffu, v.w, 16);
                    if (i4 & 2) { float tmp = v.x; v.x = v.z; v.z = tmp; tmp = v.y; v.y = v.w; v.w = tmp; }
                    int j = PADW + 32 * (4 * itb + i) + 4 * q + i4;
                    uint32_t h0 = pack_f16x2(v.x, v.y);
                    uint32_t h1 = pack_f16x2(v.z, v.w);
                    uint32_t word =
                        (uint32_t)j * 32 + (((uint32_t)(2 * wid)) ^ (((uint32_t)(j & 7)) << 2));
                    asm volatile("st.shared.v2.b32 [%0], {%1, %2};" ::"r"(sxt + word * 4),
                                 "r"(h0), "r"(h1)
                                 : "memory");
                }
#pragma unroll
                for (int i = 0; i < 4; i++) vb[i] = vn[i];
            }
            /* halo store */
            if (tid < 256) {
                int c2 = tid & 31;
                uint32_t h = pack_f16x2(he, ho);
                uint32_t word =
                    (uint32_t)hj * 32 + (((uint32_t)c2) ^ (((uint32_t)(hj & 7)) << 2));
                asm volatile("st.shared.b32 [%0], %1;" ::"r"(sxt + word * 4), "r"(h) : "memory");
            }
        }
        /* coords stores (all four strided slots) */
        csh[tid] = cr0;
        csh[tid + 512] = cr1;
        csh[tid + 1024] = cr2;
        if (tid + 1536 < 3 * JW) csh[tid + 1536] = cr3;
        __syncthreads();

        /* gaussian weights, pre-packed f16x2(w, w) */
        for (int i = tid; i < KW * TILE; i += NTHREADS) {
            int k = i >> 9;
            int lc = i & (TILE - 1);
            float d0 = csh[lc + k] - csh[lc + PADW];
            float d1 = csh[JW + lc + k] - csh[JW + lc + PADW];
            float d2 = csh[2 * JW + lc + k] - csh[2 * JW + lc + PADW];
            float w = __expf(-0.5f * (d0 * d0 + d1 * d1 + d2 * d2));
            wsh2[i] = pack_f16x2(w, w);
        }
        __syncthreads();

        float acc[4][4][4];
#pragma unroll
        for (int mt = 0; mt < 4; mt++)
#pragma unroll
            for (int nt = 0; nt < 4; nt++)
#pragma unroll
                for (int j = 0; j < 4; j++) acc[mt][nt][j] = 0.f;

#pragma unroll 1
        for (int kk = 0; kk < KW; kk++) {
            uint32_t wh[4][2];
            uint32_t rowa[4], mxor[4];
#pragma unroll
            for (int mt = 0; mt < 4; mt++) {
                wh[mt][0] = wsh2[kk * TILE + le0 + mt * 16 + g];
                wh[mt][1] = wsh2[kk * TILE + le0 + mt * 16 + g + 8];
                int jj = le0 + mt * 16 + kk + rr;
                rowa[mt] = sxt + (uint32_t)jj * 128;
                mxor[mt] = ((uint32_t)(jj & 7)) << 2;
            }
#pragma unroll
            for (int ks = 0; ks < 4; ks++) {
                const uint4* fbq = frag + (size_t)(((kk * 4 + ks) * 4 + ncolg * 2) * 32 + lane);
                uint4 q0 = fbq[0];  /* nt0, nt1 */
                uint4 q1 = fbq[32]; /* nt2, nt3 */
                const uint32_t koff = ((uint32_t)(8 * ks) + (uint32_t)ee);
                /* software-pipelined over mt: prefetch next A while computing cur */
                uint32_t acur[4], anext[4];
                ldsm_x4(acur, rowa[0] + ((koff ^ mxor[0]) << 2));
#pragma unroll
                for (int mt = 0; mt < 4; mt++) {
                    if (mt < 3) ldsm_x4(anext, rowa[mt + 1] + ((koff ^ mxor[mt + 1]) << 2));
                    uint32_t a0 = hmul2(acur[0], wh[mt][0]);
                    uint32_t a1 = hmul2(acur[1], wh[mt][1]);
                    uint32_t a2 = hmul2(acur[2], wh[mt][0]);
                    uint32_t a3 = hmul2(acur[3], wh[mt][1]);
                    mma_f16(acc[mt][0], a0, a1, a2, a3, q0.x, q0.y);
                    mma_f16(acc[mt][1], a0, a1, a2, a3, q0.z, q0.w);
                    mma_f16(acc[mt][2], a0, a1, a2, a3, q1.x, q1.y);
                    mma_f16(acc[mt][3], a0, a1, a2, a3, q1.z, q1.w);
                    if (mt < 3) {
                        acur[0] = anext[0];
                        acur[1] = anext[1];
                        acur[2] = anext[2];
                        acur[3] = anext[3];
                    }
                }
            }
        }

        /* epilogue: +bias, store raw conv (fp16 scratch), stats into smem */
        __half* scrb = g_scr + (size_t)b * COUT * LSEQ + l0;
#pragma unroll
        for (int mt = 0; mt < 4; mt++) {
            const int le = le0 + mt * 16 + g;
#pragma unroll
            for (int nt = 0; nt < 4; nt++) {
                int o = ncolg * 32 + nt * 8 + t * 2;
                float b0 = bsh[o];
                float b1 = bsh[o + 1];
                float v0 = acc[mt][nt][0] + b0;
                float v1 = acc[mt][nt][1] + b1;
                float v2 = acc[mt][nt][2] + b0;
                float v3 = acc[mt][nt][3] + b1;
                scrb[(size_t)o * LSEQ + le] = __float2half_rn(v0);
                scrb[(size_t)(o + 1) * LSEQ + le] = __float2half_rn(v1);
                scrb[(size_t)o * LSEQ + le + 8] = __float2half_rn(v2);
                scrb[(size_t)(o + 1) * LSEQ + le + 8] = __float2half_rn(v3);
                float* st = stsh + (nt * 4) * NTHREADS + tid;
                st[0] += v0 + v2;
                st[NTHREADS] += v1 + v3;
                st[2 * NTHREADS] += v0 * v0 + v2 * v2;
                st[3 * NTHREADS] += v1 * v1 + v3 * v3;
            }
        }
    }

    /* flush stats: read smem partials, reduce over lanes sharing t, atomics */
#pragma unroll
    for (int nt = 0; nt < 4; nt++)
#pragma unroll
        for (int j = 0; j < 2; j++) {
            float a = stsh[(nt * 4 + j) * NTHREADS + tid];
            float q = stsh[(nt * 4 + 2 + j) * NTHREADS + tid];
#pragma unroll
            for (int off = 16; off >= 4; off >>= 1) {
                a += __shfl_xor_sync(0xffffffffu, a, off);
                q += __shfl_xor_sync(0xffffffffu, q, off);
            }
            if (g == 0) {
                int o = ncolg * 32 + nt * 8 + t * 2 + j;
                atomicAdd(&g_sum[o], (double)a);
                atomicAdd(&g_sumsq[o], (double)q);
            }
        }
}

/* Computes per-channel scale/shift, then resets accumulators for the next
   (graph-replayed) run. Statics are zero-initialized at module load, so run 1
   also sees zeros. */
__global__ void stats_kernel(const float* __restrict__ gamma, const float* __restrict__ beta) {
    int o = threadIdx.x;
    if (o < COUT) {
        double N = (double)BATCH * (double)LSEQ;
        double mean = g_sum[o] / N;
        double var = g_sumsq[o] / N - mean * mean;
        double rstd = 1.0 / sqrt(var + 1e-5);
        float sc = gamma[o] * (float)rstd;
        g_scale[o] = sc;
        g_shift[o] = beta[o] - (float)mean * sc;
        g_sum[o] = 0.0;
        g_sumsq[o] = 0.0;
    }
}

__global__ void norm_kernel(float* __restrict__ out) {
    const size_t total4 = (size_t)BATCH * COUT * LSEQ / 4;
    size_t stride = (size_t)gridDim.x * blockDim.x;
    const uint2* scr4 = (const uint2*)g_scr;
    for (size_t i = (size_t)blockIdx.x * blockDim.x + threadIdx.x; i < total4; i += stride) {
        uint2 hv = scr4[i];
        float2 f01 = __half22float2(*(const __half2*)&hv.x);
        float2 f23 = __half22float2(*(const __half2*)&hv.y);
        int ch = (int)((i * 4 / LSEQ)) & (COUT - 1);
        float sc = g_scale[ch];
        float sh = g_shift[ch];
        float4 v;
        v.x = fmaxf(fmaf(f01.x, sc, sh), 0.0f);
        v.y = fmaxf(fmaf(f01.y, sc, sh), 0.0f);
        v.z = fmaxf(fmaf(f23.x, sc, sh), 0.0f);
        v.w = fmaxf(fmaf(f23.y, sc, sh), 0.0f);
        reinterpret_cast<float4*>(out)[i] = v;
    }
}

extern "C" void kernel_launch(void* const* d_in, const int* in_sizes, int n_in, void* d_out,
                              int out_size) {
    const float* x = (const float*)d_in[0];       // [4,64,131072]
    const float* coords = (const float*)d_in[1];  // [4,3,131072]
    const float* W = (const float*)d_in[2];       // [64,64,9]
    const float* bias = (const float*)d_in[3];    // [64]
    const float* gamma = (const float*)d_in[4];   // [64]
    const float* beta = (const float*)d_in[5];    // [64]
    float* out = (float*)d_out;

    cudaFuncSetAttribute(conv_mma_kernel, cudaFuncAttributeMaxDynamicSharedMemorySize, SM_TOTAL);
    int sms = 148;
    cudaDeviceGetAttribute(&sms, cudaDevAttrMultiProcessorCount, 0);

    conv_mma_kernel<<<sms, NTHREADS, SM_TOTAL>>>(x, coords, W, bias);
    stats_kernel<<<1, 64>>>(gamma, beta);
    norm_kernel<<<8192, 256>>>(out);
}

// round 13
// speedup vs baseline: 4.9422x; 1.0481x over previous
#include <cuda_runtime.h>
#include <cuda_fp16.h>
#include <math.h>
#include <stddef.h>
#include <stdint.h>

#define BATCH 4
#define CIN 64
#define COUT 64
#define LSEQ 131072
#define KW 9
#define PADW 4
#define TILE 128
#define JW 136 /* padded rows of xht */
#define NTHREADS 256
#define TPB_L (LSEQ / TILE)    /* 1024 */
#define NTILES (BATCH * TPB_L) /* 4096 */

/* SMEM (bytes), per CTA (2 CTAs/SM) */
#define SM_FRAG 0
#define SM_XT (SM_FRAG + KW * 4 * 4 * 32 * 16) /* 73728 */
#define SM_C (SM_XT + JW * 128)                /* +17408 */
#define SM_W (SM_C + 3 * JW * 4)               /* +1632 */
#define SM_BIAS (SM_W + KW * TILE * 4)         /* +4608 */
#define SM_TOTAL (SM_BIAS + 256)               /* = 97632 */

static __device__ double g_sum[COUT];
static __device__ double g_sumsq[COUT];
static __device__ float g_scale[COUT];
static __device__ float g_shift[COUT];
static __device__ __align__(16) __half g_scr[(size_t)BATCH * COUT * LSEQ]; /* 67 MB */

__device__ __forceinline__ uint32_t smem_u32(const void* p) {
    uint32_t a;
    asm("{ .reg .u64 t; cvta.to.shared.u64 t, %1; cvt.u32.u64 %0, t; }" : "=r"(a) : "l"(p));
    return a;
}
/* pack two f32 -> f16x2: lo half = 'even', hi half = 'odd' */
__device__ __forceinline__ uint32_t pack_f16x2(float even, float odd) {
    uint32_t r;
    asm("cvt.rn.f16x2.f32 %0, %1, %2;" : "=r"(r) : "f"(odd), "f"(even));
    return r;
}
__device__ __forceinline__ uint32_t hmul2(uint32_t a, uint32_t b) {
    uint32_t r;
    asm("mul.rn.f16x2 %0, %1, %2;" : "=r"(r) : "r"(a), "r"(b));
    return r;
}
__device__ __forceinline__ void ldsm_x4(uint32_t* r, uint32_t addr) {
    asm volatile("ldmatrix.sync.aligned.m8n8.x4.shared.b16 {%0,%1,%2,%3}, [%4];"
                 : "=r"(r[0]), "=r"(r[1]), "=r"(r[2]), "=r"(r[3])
                 : "r"(addr));
}
__device__ __forceinline__ void mma_f16(float* d, uint32_t a0, uint32_t a1, uint32_t a2,
                                        uint32_t a3, uint32_t b0, uint32_t b1) {
    asm volatile(
        "mma.sync.aligned.m16n8k16.row.col.f32.f16.f16.f32 "
        "{%0,%1,%2,%3}, {%4,%5,%6,%7}, {%8,%9}, {%0,%1,%2,%3};"
        : "+f"(d[0]), "+f"(d[1]), "+f"(d[2]), "+f"(d[3])
        : "r"(a0), "r"(a1), "r"(a2), "r"(a3), "r"(b0), "r"(b1));
}

__global__ __launch_bounds__(NTHREADS, 2) void conv_mma_kernel(
    const float* __restrict__ x, const float* __restrict__ coords, const float* __restrict__ W,
    const float* __restrict__ bias) {
    extern __shared__ char smem[];
    uint4* frag = (uint4*)(smem + SM_FRAG);
    float* csh = (float*)(smem + SM_C);
    uint32_t* wsh2 = (uint32_t*)(smem + SM_W);
    float* bsh = (float*)(smem + SM_BIAS);
    const uint32_t sxt = smem_u32(smem + SM_XT);

    const int tid = threadIdx.x;
    const int wid = tid >> 5;
    const int lane = tid & 31;
    const int t = lane & 3;
    const int g = lane >> 2;
    const int mrowg = wid & 3;  /* 32 L rows per warp */
    const int ncolg = wid >> 2; /* 32 Couts per warp */
    const int le0 = mrowg * 32;
    const int rr = lane & 15;        /* ldmatrix row offset */
    const int ee = (lane >> 4) << 2; /* +4 words when lane>=16 */

    /* One-time: bake W into fp16 B fragments, nt-paired (uint4/lane) */
    for (int i = tid; i < KW * 4 * 4 * 32; i += NTHREADS) {
        int kk = i >> 9;
        int r = i & 511;
        int ks = r >> 7;
        int r2 = r & 127;
        int np = r2 >> 5;
        int li = r2 & 31;
        int c = ks * 16 + 2 * (li & 3);
        int o0 = 2 * np * 8 + (li >> 2);
        const float* wp0 = W + (size_t)(o0 * CIN + c) * KW + kk;
        const float* wp1 = wp0 + (size_t)8 * CIN * KW;
        uint4 f;
        f.x = pack_f16x2(wp0[0], wp0[KW]);
        f.y = pack_f16x2(wp0[8 * KW], wp0[9 * KW]);
        f.z = pack_f16x2(wp1[0], wp1[KW]);
        f.w = pack_f16x2(wp1[8 * KW], wp1[9 * KW]);
        frag[i] = f;
    }
    for (int i = tid; i < COUT; i += NTHREADS) bsh[i] = bias[i];

    float s1[4][2], s2[4][2];
#pragma unroll
    for (int nt = 0; nt < 4; nt++)
#pragma unroll
        for (int j = 0; j < 2; j++) {
            s1[nt][j] = 0.f;
            s2[nt][j] = 0.f;
        }
    __syncthreads();

    for (int tt = blockIdx.x; tt < NTILES; tt += gridDim.x) {
        const int b = tt >> 10;
        const int l0 = (tt & (TPB_L - 1)) * TILE;
        __syncthreads(); /* previous tile fully consumed before restage */

        /* ---- early LDGs: coords (408 floats) + halo ---- */
        const float* cb = coords + (size_t)b * 3 * LSEQ;
        float cr0, cr1;
        {
            int i0 = tid, i1 = tid + 256;
            int d0 = i0 / JW, j0 = i0 - d0 * JW, l0c = l0 - PADW + j0;
            cr0 = (l0c >= 0 && l0c < LSEQ) ? cb[(size_t)d0 * LSEQ + l0c] : 0.0f;
            cr1 = 0.0f;
            if (i1 < 3 * JW) {
                int d1 = i1 / JW, j1 = i1 - d1 * JW, l1c = l0 - PADW + j1;
                cr1 = (l1c >= 0 && l1c < LSEQ) ? cb[(size_t)d1 * LSEQ + l1c] : 0.0f;
            }
        }
        float he = 0.0f, ho = 0.0f;
        int hj;
        {
            int c2 = tid & 31;
            int hs = tid >> 5;
            hj = (hs < 4) ? hs : 128 + hs; /* 0..3 or 132..135 */
            int l = l0 - PADW + hj;
            const float* xr = x + (size_t)b * CIN * LSEQ + (size_t)(2 * c2) * LSEQ;
            he = (l >= 0 && l < LSEQ) ? xr[l] : 0.0f;
            ho = (l >= 0 && l < LSEQ) ? xr[LSEQ + l] : 0.0f;
        }

        /* ---- stage xht: fp16 transposed [j][c=64], swizzled 128B rows.
           warp handles c = 8*wid..8*wid+7; iter it: cgrp=it&1 (4ch), jblk=it>>1 ---- */
        {
            const int i4 = lane >> 3; /* c sub-row 0..3 */
            const int q = lane & 7;   /* j quad selector */
            const float* xb = x + (size_t)b * CIN * LSEQ + l0 + 4 * q;
            float4 vb[4], vn[4];
#pragma unroll
            for (int i = 0; i < 4; i++)
                vb[i] = *(const float4*)(xb + (size_t)(8 * wid + (i & 1) * 4 + i4) * LSEQ +
                                         32 * (i >> 1));
#pragma unroll 1
            for (int itb = 0; itb < 2; itb++) {
                if (itb == 0) {
#pragma unroll
                    for (int i = 0; i < 4; i++) {
                        int it = 4 + i;
                        vn[i] = *(const float4*)(xb + (size_t)(8 * wid + (it & 1) * 4 + i4) * LSEQ +
                                                 32 * (it >> 1));
                    }
                }
#pragma unroll
                for (int i = 0; i < 4; i++) {
                    int it = 4 * itb + i;
                    float4 v = vb[i];
                    if (i4 & 1) { float tmp = v.x; v.x = v.y; v.y = tmp; tmp = v.z; v.z = v.w; v.w = tmp; }
                    v.y = __shfl_xor_sync(0xffffffffu, v.y, 8);
                    v.w = __shfl_xor_sync(0xffffffffu, v.w, 8);
                    if (i4 & 1) { float tmp = v.x; v.x = v.y; v.y = tmp; tmp = v.z; v.z = v.w; v.w = tmp; }
                    if (i4 & 2) { float tmp = v.x; v.x = v.z; v.z = tmp; tmp = v.y; v.y = v.w; v.w = tmp; }
                    v.z = __shfl_xor_sync(0xffffffffu, v.z, 16);
                    v.w = __shfl_xor_sync(0xffffffffu, v.w, 16);
                    if (i4 & 2) { float tmp = v.x; v.x = v.z; v.z = tmp; tmp = v.y; v.y = v.w; v.w = tmp; }
                    int j = PADW + 32 * (it >> 1) + 4 * q + i4;
                    int c2 = 4 * wid + 2 * (it & 1);
                    uint32_t h0 = pack_f16x2(v.x, v.y);
                    uint32_t h1 = pack_f16x2(v.z, v.w);
                    uint32_t word =
                        (uint32_t)j * 32 + (((uint32_t)c2) ^ (((uint32_t)(j & 7)) << 2));
                    asm volatile("st.shared.v2.b32 [%0], {%1, %2};" ::"r"(sxt + word * 4),
                                 "r"(h0), "r"(h1)
                                 : "memory");
                }
#pragma unroll
                for (int i = 0; i < 4; i++) vb[i] = vn[i];
            }
            /* halo store: all 256 threads */
            {
                int c2 = tid & 31;
                uint32_t h = pack_f16x2(he, ho);
                uint32_t word =
                    (uint32_t)hj * 32 + (((uint32_t)c2) ^ (((uint32_t)(hj & 7)) << 2));
                asm volatile("st.shared.b32 [%0], %1;" ::"r"(sxt + word * 4), "r"(h) : "memory");
            }
        }
        /* coords stores */
        csh[tid] = cr0;
        if (tid + 256 < 3 * JW) csh[tid + 256] = cr1;
        __syncthreads();

        /* gaussian weights, pre-packed f16x2(w, w) */
        for (int i = tid; i < KW * TILE; i += NTHREADS) {
            int k = i >> 7;
            int lc = i & (TILE - 1);
            float d0 = csh[lc + k] - csh[lc + PADW];
            float d1 = csh[JW + lc + k] - csh[JW + lc + PADW];
            float d2 = csh[2 * JW + lc + k] - csh[2 * JW + lc + PADW];
            float w = __expf(-0.5f * (d0 * d0 + d1 * d1 + d2 * d2));
            wsh2[i] = pack_f16x2(w, w);
        }
        __syncthreads();

        float acc[2][4][4];
#pragma unroll
        for (int mt = 0; mt < 2; mt++)
#pragma unroll
            for (int nt = 0; nt < 4; nt++)
#pragma unroll
                for (int j = 0; j < 4; j++) acc[mt][nt][j] = 0.f;

#pragma unroll 1
        for (int kk = 0; kk < KW; kk++) {
            uint32_t wh[2][2];
            uint32_t rowa[2], mxor[2];
#pragma unroll
            for (int mt = 0; mt < 2; mt++) {
                wh[mt][0] = wsh2[kk * TILE + le0 + mt * 16 + g];
                wh[mt][1] = wsh2[kk * TILE + le0 + mt * 16 + g + 8];
                int jj = le0 + mt * 16 + kk + rr;
                rowa[mt] = sxt + (uint32_t)jj * 128;
                mxor[mt] = ((uint32_t)(jj & 7)) << 2;
            }
#pragma unroll
            for (int ks = 0; ks < 4; ks++) {
                const uint4* fbq = frag + (size_t)(((kk * 4 + ks) * 4 + ncolg * 2) * 32 + lane);
                uint4 q0 = fbq[0];  /* nt0, nt1 */
                uint4 q1 = fbq[32]; /* nt2, nt3 */
                const uint32_t koff = ((uint32_t)(8 * ks) + (uint32_t)ee);
                uint32_t acur[4], anext[4];
                ldsm_x4(acur, rowa[0] + ((koff ^ mxor[0]) << 2));
#pragma unroll
                for (int mt = 0; mt < 2; mt++) {
                    if (mt < 1) ldsm_x4(anext, rowa[1] + ((koff ^ mxor[1]) << 2));
                    uint32_t a0 = hmul2(acur[0], wh[mt][0]);
                    uint32_t a1 = hmul2(acur[1], wh[mt][1]);
                    uint32_t a2 = hmul2(acur[2], wh[mt][0]);
                    uint32_t a3 = hmul2(acur[3], wh[mt][1]);
                    mma_f16(acc[mt][0], a0, a1, a2, a3, q0.x, q0.y);
                    mma_f16(acc[mt][1], a0, a1, a2, a3, q0.z, q0.w);
                    mma_f16(acc[mt][2], a0, a1, a2, a3, q1.x, q1.y);
                    mma_f16(acc[mt][3], a0, a1, a2, a3, q1.z, q1.w);
                    if (mt < 1) {
                        acur[0] = anext[0];
                        acur[1] = anext[1];
                        acur[2] = anext[2];
                        acur[3] = anext[3];
                    }
                }
            }
        }

        /* epilogue: +bias, store raw conv (fp16 scratch), stats in regs */
        __half* scrb = g_scr + (size_t)b * COUT * LSEQ + l0;
#pragma unroll
        for (int mt = 0; mt < 2; mt++) {
            const int le = le0 + mt * 16 + g;
#pragma unroll
            for (int nt = 0; nt < 4; nt++) {
                int o = ncolg * 32 + nt * 8 + t * 2;
                float b0 = bsh[o];
                float b1 = bsh[o + 1];
                float v0 = acc[mt][nt][0] + b0;
                float v1 = acc[mt][nt][1] + b1;
                float v2 = acc[mt][nt][2] + b0;
                float v3 = acc[mt][nt][3] + b1;
                scrb[(size_t)o * LSEQ + le] = __float2half_rn(v0);
                scrb[(size_t)(o + 1) * LSEQ + le] = __float2half_rn(v1);
                scrb[(size_t)o * LSEQ + le + 8] = __float2half_rn(v2);
                scrb[(size_t)(o + 1) * LSEQ + le + 8] = __float2half_rn(v3);
                s1[nt][0] += v0 + v2;
                s1[nt][1] += v1 + v3;
                s2[nt][0] += v0 * v0 + v2 * v2;
                s2[nt][1] += v1 * v1 + v3 * v3;
            }
        }
    }

    /* flush stats: reduce over lanes sharing t (xor 16,8,4 preserves t) */
#pragma unroll
    for (int nt = 0; nt < 4; nt++)
#pragma unroll
        for (int j = 0; j < 2; j++) {
            float a = s1[nt][j], q = s2[nt][j];
#pragma unroll
            for (int off = 16; off >= 4; off >>= 1) {
                a += __shfl_xor_sync(0xffffffffu, a, off);
                q += __shfl_xor_sync(0xffffffffu, q, off);
            }
            if (g == 0) {
                int o = ncolg * 32 + nt * 8 + t * 2 + j;
                atomicAdd(&g_sum[o], (double)a);
                atomicAdd(&g_sumsq[o], (double)q);
            }
        }
}

/* Computes per-channel scale/shift, then resets accumulators for the next
   (graph-replayed) run. Statics are zero-initialized at module load. */
__global__ void stats_kernel(const float* __restrict__ gamma, const float* __restrict__ beta) {
    int o = threadIdx.x;
    if (o < COUT) {
        double N = (double)BATCH * (double)LSEQ;
        double mean = g_sum[o] / N;
        double var = g_sumsq[o] / N - mean * mean;
        double rstd = 1.0 / sqrt(var + 1e-5);
        float sc = gamma[o] * (float)rstd;
        g_scale[o] = sc;
        g_shift[o] = beta[o] - (float)mean * sc;
        g_sum[o] = 0.0;
        g_sumsq[o] = 0.0;
    }
}

__global__ void norm_kernel(float* __restrict__ out) {
    const size_t total4 = (size_t)BATCH * COUT * LSEQ / 4;
    size_t stride = (size_t)gridDim.x * blockDim.x;
    const uint2* scr4 = (const uint2*)g_scr;
    for (size_t i = (size_t)blockIdx.x * blockDim.x + threadIdx.x; i < total4; i += stride) {
        uint2 hv = scr4[i];
        float2 f01 = __half22float2(*(const __half2*)&hv.x);
        float2 f23 = __half22float2(*(const __half2*)&hv.y);
        int ch = (int)((i * 4 / LSEQ)) & (COUT - 1);
        float sc = g_scale[ch];
        float sh = g_shift[ch];
        float4 v;
        v.x = fmaxf(fmaf(f01.x, sc, sh), 0.0f);
        v.y = fmaxf(fmaf(f01.y, sc, sh), 0.0f);
        v.z = fmaxf(fmaf(f23.x, sc, sh), 0.0f);
        v.w = fmaxf(fmaf(f23.y, sc, sh), 0.0f);
        reinterpret_cast<float4*>(out)[i] = v;
    }
}

extern "C" void kernel_launch(void* const* d_in, const int* in_sizes, int n_in, void* d_out,
                              int out_size) {
    const float* x = (const float*)d_in[0];       // [4,64,131072]
    const float* coords = (const float*)d_in[1];  // [4,3,131072]
    const float* W = (const float*)d_in[2];       // [64,64,9]
    const float* bias = (const float*)d_in[3];    // [64]
    const float* gamma = (const float*)d_in[4];   // [64]
    const float* beta = (const float*)d_in[5];    // [64]
    float* out = (float*)d_out;

    cudaFuncSetAttribute(conv_mma_kernel, cudaFuncAttributeMaxDynamicSharedMemorySize, SM_TOTAL);
    int sms = 148;
    cudaDeviceGetAttribute(&sms, cudaDevAttrMultiProcessorCount, 0);

    conv_mma_kernel<<<2 * sms, NTHREADS, SM_TOTAL>>>(x, coords, W, bias);
    stats_kernel<<<1, 64>>>(gamma, beta);
    norm_kernel<<<8192, 256>>>(out);
}

// round 14
// speedup vs baseline: 4.9430x; 1.0002x over previous
#include <cuda_runtime.h>
#include <cuda_fp16.h>
#include <math.h>
#include <stddef.h>
#include <stdint.h>

#define BATCH 4
#define CIN 64
#define COUT 64
#define LSEQ 131072
#define KW 9
#define PADW 4
#define TILE 128
#define JW 136 /* padded rows of xht */
#define NTHREADS 128
#define TPB_L (LSEQ / TILE)    /* 1024 */
#define NTILES (BATCH * TPB_L) /* 4096 */

/* SMEM (bytes), per CTA (2 CTAs/SM) */
#define SM_FRAG 0
#define SM_XT (SM_FRAG + KW * 4 * 4 * 32 * 16) /* 73728 */
#define SM_C (SM_XT + JW * 128)                /* +17408 */
#define SM_W (SM_C + 3 * JW * 4)               /* +1632 */
#define SM_BIAS (SM_W + KW * TILE * 4)         /* +4608 */
#define SM_TOTAL (SM_BIAS + 256)               /* = 97632 */

static __device__ double g_sum[COUT];
static __device__ double g_sumsq[COUT];
static __device__ float g_scale[COUT];
static __device__ float g_shift[COUT];
static __device__ __align__(16) __half g_scr[(size_t)BATCH * COUT * LSEQ]; /* 67 MB */

__device__ __forceinline__ uint32_t smem_u32(const void* p) {
    uint32_t a;
    asm("{ .reg .u64 t; cvta.to.shared.u64 t, %1; cvt.u32.u64 %0, t; }" : "=r"(a) : "l"(p));
    return a;
}
/* pack two f32 -> f16x2: lo half = 'even', hi half = 'odd' */
__device__ __forceinline__ uint32_t pack_f16x2(float even, float odd) {
    uint32_t r;
    asm("cvt.rn.f16x2.f32 %0, %1, %2;" : "=r"(r) : "f"(odd), "f"(even));
    return r;
}
__device__ __forceinline__ uint32_t hmul2(uint32_t a, uint32_t b) {
    uint32_t r;
    asm("mul.rn.f16x2 %0, %1, %2;" : "=r"(r) : "r"(a), "r"(b));
    return r;
}
__device__ __forceinline__ void ldsm_x4(uint32_t* r, uint32_t addr) {
    asm volatile("ldmatrix.sync.aligned.m8n8.x4.shared.b16 {%0,%1,%2,%3}, [%4];"
                 : "=r"(r[0]), "=r"(r[1]), "=r"(r[2]), "=r"(r[3])
                 : "r"(addr));
}
__device__ __forceinline__ void mma_f16(float* d, uint32_t a0, uint32_t a1, uint32_t a2,
                                        uint32_t a3, uint32_t b0, uint32_t b1) {
    asm volatile(
        "mma.sync.aligned.m16n8k16.row.col.f32.f16.f16.f32 "
        "{%0,%1,%2,%3}, {%4,%5,%6,%7}, {%8,%9}, {%0,%1,%2,%3};"
        : "+f"(d[0]), "+f"(d[1]), "+f"(d[2]), "+f"(d[3])
        : "r"(a0), "r"(a1), "r"(a2), "r"(a3), "r"(b0), "r"(b1));
}

__global__ __launch_bounds__(NTHREADS, 2) void conv_mma_kernel(
    const float* __restrict__ x, const float* __restrict__ coords, const float* __restrict__ W,
    const float* __restrict__ bias) {
    extern __shared__ char smem[];
    uint4* frag = (uint4*)(smem + SM_FRAG);
    float* csh = (float*)(smem + SM_C);
    uint32_t* wsh2 = (uint32_t*)(smem + SM_W);
    float* bsh = (float*)(smem + SM_BIAS);
    const uint32_t sxt = smem_u32(smem + SM_XT);

    const int tid = threadIdx.x;
    const int wid = tid >> 5; /* 0..3 */
    const int lane = tid & 31;
    const int t = lane & 3;
    const int g = lane >> 2;
    const int mrowg = wid & 1;  /* 64 L rows per warp */
    const int ncolg = wid >> 1; /* 32 Couts per warp */
    const int le0 = mrowg * 64;
    const int rr = lane & 15;        /* ldmatrix row offset */
    const int ee = (lane >> 4) << 2; /* +4 words when lane>=16 */

    /* One-time: bake W into fp16 B fragments, nt-paired (uint4/lane) */
    for (int i = tid; i < KW * 4 * 4 * 32; i += NTHREADS) {
        int kk = i >> 9;
        int r = i & 511;
        int ks = r >> 7;
        int r2 = r & 127;
        int np = r2 >> 5;
        int li = r2 & 31;
        int c = ks * 16 + 2 * (li & 3);
        int o0 = 2 * np * 8 + (li >> 2);
        const float* wp0 = W + (size_t)(o0 * CIN + c) * KW + kk;
        const float* wp1 = wp0 + (size_t)8 * CIN * KW;
        uint4 f;
        f.x = pack_f16x2(wp0[0], wp0[KW]);
        f.y = pack_f16x2(wp0[8 * KW], wp0[9 * KW]);
        f.z = pack_f16x2(wp1[0], wp1[KW]);
        f.w = pack_f16x2(wp1[8 * KW], wp1[9 * KW]);
        frag[i] = f;
    }
    for (int i = tid; i < COUT; i += NTHREADS) bsh[i] = bias[i];

    float s1[4][2], s2[4][2];
#pragma unroll
    for (int nt = 0; nt < 4; nt++)
#pragma unroll
        for (int j = 0; j < 2; j++) {
            s1[nt][j] = 0.f;
            s2[nt][j] = 0.f;
        }
    __syncthreads();

    for (int tt = blockIdx.x; tt < NTILES; tt += gridDim.x) {
        const int b = tt >> 10;
        const int l0 = (tt & (TPB_L - 1)) * TILE;
        __syncthreads(); /* previous tile fully consumed before restage */

        /* ---- early LDGs: coords (3*JW = 408 floats, 4 strided slots) + halo (2/thread) ---- */
        const float* cb = coords + (size_t)b * 3 * LSEQ;
        float cr0, cr1, cr2, cr3;
        {
            int i0 = tid, i1 = tid + 128, i2 = tid + 256, i3 = tid + 384;
            int d0 = i0 / JW, j0 = i0 - d0 * JW, l0c = l0 - PADW + j0;
            int d1 = i1 / JW, j1 = i1 - d1 * JW, l1c = l0 - PADW + j1;
            int d2 = i2 / JW, j2 = i2 - d2 * JW, l2c = l0 - PADW + j2;
            cr0 = (l0c >= 0 && l0c < LSEQ) ? cb[(size_t)d0 * LSEQ + l0c] : 0.0f;
            cr1 = (l1c >= 0 && l1c < LSEQ) ? cb[(size_t)d1 * LSEQ + l1c] : 0.0f;
            cr2 = (l2c >= 0 && l2c < LSEQ) ? cb[(size_t)d2 * LSEQ + l2c] : 0.0f;
            cr3 = 0.0f;
            if (i3 < 3 * JW) {
                int j3 = i3 - 2 * JW; /* tail is all d=2 */
                int l3c = l0 - PADW + j3;
                cr3 = (l3c >= 0 && l3c < LSEQ) ? cb[(size_t)2 * LSEQ + l3c] : 0.0f;
            }
        }
        float he[2], ho[2];
        int hjv[2];
        {
#pragma unroll
            for (int e = 0; e < 2; e++) {
                int ei = tid + e * 128;
                int c2 = ei & 31;
                int hs = ei >> 5;
                int hj = (hs < 4) ? hs : 128 + hs; /* 0..3 or 132..135 */
                hjv[e] = hj;
                int l = l0 - PADW + hj;
                const float* xr = x + (size_t)b * CIN * LSEQ + (size_t)(2 * c2) * LSEQ;
                he[e] = (l >= 0 && l < LSEQ) ? xr[l] : 0.0f;
                ho[e] = (l >= 0 && l < LSEQ) ? xr[LSEQ + l] : 0.0f;
            }
        }

        /* ---- stage xht: fp16 transposed [j][c=64], swizzled 128B rows.
           warp w owns c = 16w..16w+15; it = 0..15: cgrp = it&3, jblk = it>>2 ---- */
        {
            const int i4 = lane >> 3; /* c sub-row 0..3 */
            const int q = lane & 7;   /* j quad selector */
            const float* xb = x + (size_t)b * CIN * LSEQ + l0 + 4 * q;
            float4 vb[4], vn[4];
#pragma unroll
            for (int i = 0; i < 4; i++)
                vb[i] = *(const float4*)(xb + (size_t)(16 * wid + 4 * (i & 3) + i4) * LSEQ +
                                         32 * (i >> 2));
#pragma unroll 1
            for (int itb = 0; itb < 4; itb++) {
                if (itb < 3) {
#pragma unroll
                    for (int i = 0; i < 4; i++) {
                        int it = 4 * (itb + 1) + i;
                        vn[i] = *(const float4*)(xb +
                                                 (size_t)(16 * wid + 4 * (it & 3) + i4) * LSEQ +
                                                 32 * (it >> 2));
                    }
                }
#pragma unroll
                for (int i = 0; i < 4; i++) {
                    int it = 4 * itb + i;
                    float4 v = vb[i];
                    if (i4 & 1) { float tmp = v.x; v.x = v.y; v.y = tmp; tmp = v.z; v.z = v.w; v.w = tmp; }
                    v.y = __shfl_xor_sync(0xffffffffu, v.y, 8);
                    v.w = __shfl_xor_sync(0xffffffffu, v.w, 8);
                    if (i4 & 1) { float tmp = v.x; v.x = v.y; v.y = tmp; tmp = v.z; v.z = v.w; v.w = tmp; }
                    if (i4 & 2) { float tmp = v.x; v.x = v.z; v.z = tmp; tmp = v.y; v.y = v.w; v.w = tmp; }
                    v.z = __shfl_xor_sync(0xffffffffu, v.z, 16);
                    v.w = __shfl_xor_sync(0xffffffffu, v.w, 16);
                    if (i4 & 2) { float tmp = v.x; v.x = v.z; v.z = tmp; tmp = v.y; v.y = v.w; v.w = tmp; }
                    int j = PADW + 32 * (it >> 2) + 4 * q + i4;
                    int c2 = 8 * wid + 2 * (it & 3); /* f16x2-word column */
                    uint32_t h0 = pack_f16x2(v.x, v.y);
                    uint32_t h1 = pack_f16x2(v.z, v.w);
                    uint32_t word =
                        (uint32_t)j * 32 + (((uint32_t)c2) ^ (((uint32_t)(j & 7)) << 2));
                    asm volatile("st.shared.v2.b32 [%0], {%1, %2};" ::"r"(sxt + word * 4),
                                 "r"(h0), "r"(h1)
                                 : "memory");
                }
#pragma unroll
                for (int i = 0; i < 4; i++) vb[i] = vn[i];
            }
            /* halo stores */
#pragma unroll
            for (int e = 0; e < 2; e++) {
                int ei = tid + e * 128;
                int c2 = ei & 31;
                int hj = hjv[e];
                uint32_t h = pack_f16x2(he[e], ho[e]);
                uint32_t word =
                    (uint32_t)hj * 32 + (((uint32_t)c2) ^ (((uint32_t)(hj & 7)) << 2));
                asm volatile("st.shared.b32 [%0], %1;" ::"r"(sxt + word * 4), "r"(h) : "memory");
            }
        }
        /* coords stores */
        csh[tid] = cr0;
        csh[tid + 128] = cr1;
        csh[tid + 256] = cr2;
        if (tid + 384 < 3 * JW) csh[tid + 384] = cr3;
        __syncthreads();

        /* gaussian weights, pre-packed f16x2(w, w) */
        for (int i = tid; i < KW * TILE; i += NTHREADS) {
            int k = i >> 7;
            int lc = i & (TILE - 1);
            float d0 = csh[lc + k] - csh[lc + PADW];
            float d1 = csh[JW + lc + k] - csh[JW + lc + PADW];
            float d2 = csh[2 * JW + lc + k] - csh[2 * JW + lc + PADW];
            float w = __expf(-0.5f * (d0 * d0 + d1 * d1 + d2 * d2));
            wsh2[i] = pack_f16x2(w, w);
        }
        __syncthreads();

        float acc[4][4][4];
#pragma unroll
        for (int mt = 0; mt < 4; mt++)
#pragma unroll
            for (int nt = 0; nt < 4; nt++)
#pragma unroll
                for (int j = 0; j < 4; j++) acc[mt][nt][j] = 0.f;

#pragma unroll 1
        for (int kk = 0; kk < KW; kk++) {
            uint32_t wh[4][2];
            uint32_t rowa[4], mxor[4];
#pragma unroll
            for (int mt = 0; mt < 4; mt++) {
                wh[mt][0] = wsh2[kk * TILE + le0 + mt * 16 + g];
                wh[mt][1] = wsh2[kk * TILE + le0 + mt * 16 + g + 8];
                int jj = le0 + mt * 16 + kk + rr;
                rowa[mt] = sxt + (uint32_t)jj * 128;
                mxor[mt] = ((uint32_t)(jj & 7)) << 2;
            }
#pragma unroll
            for (int ks = 0; ks < 4; ks++) {
                const uint4* fbq = frag + (size_t)(((kk * 4 + ks) * 4 + ncolg * 2) * 32 + lane);
                uint4 q0 = fbq[0];  /* nt0, nt1 */
                uint4 q1 = fbq[32]; /* nt2, nt3 */
                const uint32_t koff = ((uint32_t)(8 * ks) + (uint32_t)ee);
                uint32_t acur[4], anext[4];
                ldsm_x4(acur, rowa[0] + ((koff ^ mxor[0]) << 2));
#pragma unroll
                for (int mt = 0; mt < 4; mt++) {
                    if (mt < 3) ldsm_x4(anext, rowa[mt + 1] + ((koff ^ mxor[mt + 1]) << 2));
                    uint32_t a0 = hmul2(acur[0], wh[mt][0]);
                    uint32_t a1 = hmul2(acur[1], wh[mt][1]);
                    uint32_t a2 = hmul2(acur[2], wh[mt][0]);
                    uint32_t a3 = hmul2(acur[3], wh[mt][1]);
                    mma_f16(acc[mt][0], a0, a1, a2, a3, q0.x, q0.y);
                    mma_f16(acc[mt][1], a0, a1, a2, a3, q0.z, q0.w);
                    mma_f16(acc[mt][2], a0, a1, a2, a3, q1.x, q1.y);
                    mma_f16(acc[mt][3], a0, a1, a2, a3, q1.z, q1.w);
                    if (mt < 3) {
                        acur[0] = anext[0];
                        acur[1] = anext[1];
                        acur[2] = anext[2];
                        acur[3] = anext[3];
                    }
                }
            }
        }

        /* epilogue: +bias, store raw conv (fp16 scratch), stats in regs */
        __half* scrb = g_scr + (size_t)b * COUT * LSEQ + l0;
#pragma unroll
        for (int mt = 0; mt < 4; mt++) {
            const int le = le0 + mt * 16 + g;
#pragma unroll
            for (int nt = 0; nt < 4; nt++) {
                int o = ncolg * 32 + nt * 8 + t * 2;
                float b0 = bsh[o];
                float b1 = bsh[o + 1];
                float v0 = acc[mt][nt][0] + b0;
                float v1 = acc[mt][nt][1] + b1;
                float v2 = acc[mt][nt][2] + b0;
                float v3 = acc[mt][nt][3] + b1;
                scrb[(size_t)o * LSEQ + le] = __float2half_rn(v0);
                scrb[(size_t)(o + 1) * LSEQ + le] = __float2half_rn(v1);
                scrb[(size_t)o * LSEQ + le + 8] = __float2half_rn(v2);
                scrb[(size_t)(o + 1) * LSEQ + le + 8] = __float2half_rn(v3);
                s1[nt][0] += v0 + v2;
                s1[nt][1] += v1 + v3;
                s2[nt][0] += v0 * v0 + v2 * v2;
                s2[nt][1] += v1 * v1 + v3 * v3;
            }
        }
    }

    /* flush stats: reduce over lanes sharing t (xor 16,8,4 preserves t) */
#pragma unroll
    for (int nt = 0; nt < 4; nt++)
#pragma unroll
        for (int j = 0; j < 2; j++) {
            float a = s1[nt][j], q = s2[nt][j];
#pragma unroll
            for (int off = 16; off >= 4; off >>= 1) {
                a += __shfl_xor_sync(0xffffffffu, a, off);
                q += __shfl_xor_sync(0xffffffffu, q, off);
            }
            if (g == 0) {
                int o = ncolg * 32 + nt * 8 + t * 2 + j;
                atomicAdd(&g_sum[o], (double)a);
                atomicAdd(&g_sumsq[o], (double)q);
            }
        }
}

/* Computes per-channel scale/shift, then resets accumulators for the next
   (graph-replayed) run. Statics are zero-initialized at module load. */
__global__ void stats_kernel(const float* __restrict__ gamma, const float* __restrict__ beta) {
    int o = threadIdx.x;
    if (o < COUT) {
        double N = (double)BATCH * (double)LSEQ;
        double mean = g_sum[o] / N;
        double var = g_sumsq[o] / N - mean * mean;
        double rstd = 1.0 / sqrt(var + 1e-5);
        float sc = gamma[o] * (float)rstd;
        g_scale[o] = sc;
        g_shift[o] = beta[o] - (float)mean * sc;
        g_sum[o] = 0.0;
        g_sumsq[o] = 0.0;
    }
}

__global__ void norm_kernel(float* __restrict__ out) {
    const size_t total4 = (size_t)BATCH * COUT * LSEQ / 4;
    size_t stride = (size_t)gridDim.x * blockDim.x;
    const uint2* scr4 = (const uint2*)g_scr;
    for (size_t i = (size_t)blockIdx.x * blockDim.x + threadIdx.x; i < total4; i += stride) {
        uint2 hv = scr4[i];
        float2 f01 = __half22float2(*(const __half2*)&hv.x);
        float2 f23 = __half22float2(*(const __half2*)&hv.y);
        int ch = (int)((i * 4 / LSEQ)) & (COUT - 1);
        float sc = g_scale[ch];
        float sh = g_shift[ch];
        float4 v;
        v.x = fmaxf(fmaf(f01.x, sc, sh), 0.0f);
        v.y = fmaxf(fmaf(f01.y, sc, sh), 0.0f);
        v.z = fmaxf(fmaf(f23.x, sc, sh), 0.0f);
        v.w = fmaxf(fmaf(f23.y, sc, sh), 0.0f);
        reinterpret_cast<float4*>(out)[i] = v;
    }
}

extern "C" void kernel_launch(void* const* d_in, const int* in_sizes, int n_in, void* d_out,
                              int out_size) {
    const float* x = (const float*)d_in[0];       // [4,64,131072]
    const float* coords = (const float*)d_in[1];  // [4,3,131072]
    const float* W = (const float*)d_in[2];       // [64,64,9]
    const float* bias = (const float*)d_in[3];    // [64]
    const float* gamma = (const float*)d_in[4];   // [64]
    const float* beta = (const float*)d_in[5];    // [64]
    float* out = (float*)d_out;

    cudaFuncSetAttribute(conv_mma_kernel, cudaFuncAttributeMaxDynamicSharedMemorySize, SM_TOTAL);
    int sms = 148;
    cudaDeviceGetAttribute(&sms, cudaDevAttrMultiProcessorCount, 0);

    conv_mma_kernel<<<2 * sms, NTHREADS, SM_TOTAL>>>(x, coords, W, bias);
    stats_kernel<<<1, 64>>>(gamma, beta);
    norm_kernel<<<8192, 256>>>(out);
}

// round 15
// speedup vs baseline: 5.1618x; 1.0443x over previous
#include <cuda_runtime.h>
#include <cuda_fp16.h>
#include <math.h>
#include <stddef.h>
#include <stdint.h>

#define BATCH 4
#define CIN 64
#define COUT 64
#define LSEQ 131072
#define KW 9
#define PADW 4
#define TILE 128
#define JW 136 /* padded rows of xht */
#define NTHREADS 128
#define TPB_L (LSEQ / TILE)    /* 1024 */
#define NTILES (BATCH * TPB_L) /* 4096 */

/* SMEM (bytes), per CTA (2 CTAs/SM) */
#define SM_FRAG 0
#define SM_XT (SM_FRAG + KW * 4 * 4 * 32 * 16) /* 73728 */
#define SM_C (SM_XT + JW * 128)                /* +17408 */
#define SM_W (SM_C + 3 * JW * 4)               /* +1632 */
#define SM_BIAS (SM_W + KW * TILE * 4)         /* +4608 */
#define SM_TOTAL (SM_BIAS + 256)               /* = 97632 */

static __device__ double g_sum[COUT];
static __device__ double g_sumsq[COUT];
static __device__ float g_scale[COUT];
static __device__ float g_shift[COUT];
static __device__ __align__(16) __half g_scr[(size_t)BATCH * COUT * LSEQ]; /* 67 MB */

__device__ __forceinline__ uint32_t smem_u32(const void* p) {
    uint32_t a;
    asm("{ .reg .u64 t; cvta.to.shared.u64 t, %1; cvt.u32.u64 %0, t; }" : "=r"(a) : "l"(p));
    return a;
}
/* pack two f32 -> f16x2: lo half = 'even', hi half = 'odd' */
__device__ __forceinline__ uint32_t pack_f16x2(float even, float odd) {
    uint32_t r;
    asm("cvt.rn.f16x2.f32 %0, %1, %2;" : "=r"(r) : "f"(odd), "f"(even));
    return r;
}
__device__ __forceinline__ uint32_t hmul2(uint32_t a, uint32_t b) {
    uint32_t r;
    asm("mul.rn.f16x2 %0, %1, %2;" : "=r"(r) : "r"(a), "r"(b));
    return r;
}
__device__ __forceinline__ void ldsm_x4(uint32_t* r, uint32_t addr) {
    asm volatile("ldmatrix.sync.aligned.m8n8.x4.shared.b16 {%0,%1,%2,%3}, [%4];"
                 : "=r"(r[0]), "=r"(r[1]), "=r"(r[2]), "=r"(r[3])
                 : "r"(addr));
}
__device__ __forceinline__ void mma_f16(float* d, uint32_t a0, uint32_t a1, uint32_t a2,
                                        uint32_t a3, uint32_t b0, uint32_t b1) {
    asm volatile(
        "mma.sync.aligned.m16n8k16.row.col.f32.f16.f16.f32 "
        "{%0,%1,%2,%3}, {%4,%5,%6,%7}, {%8,%9}, {%0,%1,%2,%3};"
        : "+f"(d[0]), "+f"(d[1]), "+f"(d[2]), "+f"(d[3])
        : "r"(a0), "r"(a1), "r"(a2), "r"(a3), "r"(b0), "r"(b1));
}

__global__ __launch_bounds__(NTHREADS, 2) void conv_mma_kernel(
    const float* __restrict__ x, const float* __restrict__ coords, const float* __restrict__ W,
    const float* __restrict__ bias) {
    extern __shared__ char smem[];
    uint4* frag = (uint4*)(smem + SM_FRAG);
    float* csh = (float*)(smem + SM_C);
    uint32_t* wsh2 = (uint32_t*)(smem + SM_W);
    float* bsh = (float*)(smem + SM_BIAS);
    const uint32_t sxt = smem_u32(smem + SM_XT);

    const int tid = threadIdx.x;
    const int wid = tid >> 5; /* 0..3 */
    const int lane = tid & 31;
    const int t = lane & 3;
    const int g = lane >> 2;
    const int mrowg = wid & 1;  /* 64 L rows per warp */
    const int ncolg = wid >> 1; /* 32 Couts per warp */
    const int le0 = mrowg * 64;
    const int rr = lane & 15;        /* ldmatrix row offset */
    const int ee = (lane >> 4) << 2; /* +4 words when lane>=16 */
    const int i4 = lane >> 3;        /* staging: c sub-row 0..3 */
    const int q = lane & 7;          /* staging: j quad selector */
    const int gridn = gridDim.x;

    /* One-time: bake W into fp16 B fragments, nt-paired (uint4/lane) */
    for (int i = tid; i < KW * 4 * 4 * 32; i += NTHREADS) {
        int kk = i >> 9;
        int r = i & 511;
        int ks = r >> 7;
        int r2 = r & 127;
        int np = r2 >> 5;
        int li = r2 & 31;
        int c = ks * 16 + 2 * (li & 3);
        int o0 = 2 * np * 8 + (li >> 2);
        const float* wp0 = W + (size_t)(o0 * CIN + c) * KW + kk;
        const float* wp1 = wp0 + (size_t)8 * CIN * KW;
        uint4 f;
        f.x = pack_f16x2(wp0[0], wp0[KW]);
        f.y = pack_f16x2(wp0[8 * KW], wp0[9 * KW]);
        f.z = pack_f16x2(wp1[0], wp1[KW]);
        f.w = pack_f16x2(wp1[8 * KW], wp1[9 * KW]);
        frag[i] = f;
    }
    for (int i = tid; i < COUT; i += NTHREADS) bsh[i] = bias[i];

    float s1[4][2], s2[4][2];
#pragma unroll
    for (int nt = 0; nt < 4; nt++)
#pragma unroll
        for (int j = 0; j < 2; j++) {
            s1[nt][j] = 0.f;
            s2[nt][j] = 0.f;
        }

    /* prefetch register state (tile "next") */
    float4 pa[8], pb[8];
    float cr0, cr1, cr2, cr3;
    float he[2], ho[2];

/* ---- LDG a batch of 4 x-float4s for tile (bn, l0n) into dst[] at it-range base ---- */
#define LDG_X4(dst, itbase, xbn)                                                             \
    {                                                                                        \
        _Pragma("unroll") for (int i = 0; i < 4; i++) {                                      \
            int it = (itbase) + i;                                                           \
            (dst)[((itbase) & 4) + i] = *(const float4*)((xbn) +                             \
                (size_t)(16 * wid + 4 * (it & 3) + i4) * LSEQ + 32 * (it >> 2));             \
        }                                                                                    \
    }

/* ---- LDG coords + halo for tile (bn, l0n) ---- */
#define LDG_CH(bn, l0n)                                                                      \
    {                                                                                        \
        const float* cb = coords + (size_t)(bn)*3 * LSEQ;                                    \
        int i0 = tid, i1 = tid + 128, i2 = tid + 256, i3 = tid + 384;                        \
        int d0 = i0 / JW, j0 = i0 - d0 * JW, l0c = (l0n)-PADW + j0;                          \
        int d1 = i1 / JW, j1 = i1 - d1 * JW, l1c = (l0n)-PADW + j1;                          \
        int d2 = i2 / JW, j2 = i2 - d2 * JW, l2c = (l0n)-PADW + j2;                          \
        cr0 = (l0c >= 0 && l0c < LSEQ) ? cb[(size_t)d0 * LSEQ + l0c] : 0.0f;                 \
        cr1 = (l1c >= 0 && l1c < LSEQ) ? cb[(size_t)d1 * LSEQ + l1c] : 0.0f;                 \
        cr2 = (l2c >= 0 && l2c < LSEQ) ? cb[(size_t)d2 * LSEQ + l2c] : 0.0f;                 \
        cr3 = 0.0f;                                                                         \
        if (i3 < 3 * JW) {                                                                  \
            int j3 = i3 - 2 * JW;                                                           \
            int l3c = (l0n)-PADW + j3;                                                      \
            cr3 = (l3c >= 0 && l3c < LSEQ) ? cb[(size_t)2 * LSEQ + l3c] : 0.0f;             \
        }                                                                                   \
        _Pragma("unroll") for (int e = 0; e < 2; e++) {                                     \
            int ei = tid + e * 128;                                                         \
            int c2 = ei & 31;                                                               \
            int hs = ei >> 5;                                                               \
            int hj = (hs < 4) ? hs : 128 + hs;                                              \
            int l = (l0n)-PADW + hj;                                                        \
            const float* xr = x + (size_t)(bn)*CIN * LSEQ + (size_t)(2 * c2) * LSEQ;        \
            he[e] = (l >= 0 && l < LSEQ) ? xr[l] : 0.0f;                                    \
            ho[e] = (l >= 0 && l < LSEQ) ? xr[LSEQ + l] : 0.0f;                             \
        }                                                                                   \
    }

/* ---- transpose + STS the prefetched tile (pa/pb + coords + halo) ---- */
#define STS_TILE()                                                                           \
    {                                                                                        \
        _Pragma("unroll") for (int it = 0; it < 16; it++) {                                  \
            float4 v = (it < 8) ? pa[it] : pb[it - 8];                                       \
            if (i4 & 1) { float tmp = v.x; v.x = v.y; v.y = tmp; tmp = v.z; v.z = v.w; v.w = tmp; } \
            v.y = __shfl_xor_sync(0xffffffffu, v.y, 8);                                      \
            v.w = __shfl_xor_sync(0xffffffffu, v.w, 8);                                      \
            if (i4 & 1) { float tmp = v.x; v.x = v.y; v.y = tmp; tmp = v.z; v.z = v.w; v.w = tmp; } \
            if (i4 & 2) { float tmp = v.x; v.x = v.z; v.z = tmp; tmp = v.y; v.y = v.w; v.w = tmp; } \
            v.z = __shfl_xor_sync(0xffffffffu, v.z, 16);                                     \
            v.w = __shfl_xor_sync(0xffffffffu, v.w, 16);                                     \
            if (i4 & 2) { float tmp = v.x; v.x = v.z; v.z = tmp; tmp = v.y; v.y = v.w; v.w = tmp; } \
            int j = PADW + 32 * (it >> 2) + 4 * q + i4;                                      \
            int c2 = 8 * wid + 2 * (it & 3);                                                 \
            uint32_t h0 = pack_f16x2(v.x, v.y);                                              \
            uint32_t h1 = pack_f16x2(v.z, v.w);                                              \
            uint32_t word = (uint32_t)j * 32 + (((uint32_t)c2) ^ (((uint32_t)(j & 7)) << 2)); \
            asm volatile("st.shared.v2.b32 [%0], {%1, %2};" ::"r"(sxt + word * 4), "r"(h0),  \
                         "r"(h1)                                                             \
                         : "memory");                                                        \
        }                                                                                    \
        _Pragma("unroll") for (int e = 0; e < 2; e++) {                                      \
            int ei = tid + e * 128;                                                          \
            int c2 = ei & 31;                                                                \
            int hs = ei >> 5;                                                                \
            int hj = (hs < 4) ? hs : 128 + hs;                                               \
            uint32_t h = pack_f16x2(he[e], ho[e]);                                           \
            uint32_t word = (uint32_t)hj * 32 + (((uint32_t)c2) ^ (((uint32_t)(hj & 7)) << 2)); \
            asm volatile("st.shared.b32 [%0], %1;" ::"r"(sxt + word * 4), "r"(h) : "memory"); \
        }                                                                                    \
        csh[tid] = cr0;                                                                      \
        csh[tid + 128] = cr1;                                                                \
        csh[tid + 256] = cr2;                                                                \
        if (tid + 384 < 3 * JW) csh[tid + 384] = cr3;                                        \
    }

/* ---- gaussian weights from staged coords ---- */
#define WEIGHTS()                                                                            \
    for (int i = tid; i < KW * TILE; i += NTHREADS) {                                        \
        int k = i >> 7;                                                                      \
        int lc = i & (TILE - 1);                                                             \
        float d0 = csh[lc + k] - csh[lc + PADW];                                             \
        float d1 = csh[JW + lc + k] - csh[JW + lc + PADW];                                   \
        float d2 = csh[2 * JW + lc + k] - csh[2 * JW + lc + PADW];                           \
        float w = __expf(-0.5f * (d0 * d0 + d1 * d1 + d2 * d2));                             \
        wsh2[i] = pack_f16x2(w, w);                                                          \
    }

/* ---- mainloop over kk range ---- */
#define MAINLOOP(KK0, KK1)                                                                   \
    _Pragma("unroll 1") for (int kk = (KK0); kk < (KK1); kk++) {                             \
        uint32_t wh[4][2];                                                                   \
        uint32_t rowa[4], mxor[4];                                                           \
        _Pragma("unroll") for (int mt = 0; mt < 4; mt++) {                                   \
            wh[mt][0] = wsh2[kk * TILE + le0 + mt * 16 + g];                                 \
            wh[mt][1] = wsh2[kk * TILE + le0 + mt * 16 + g + 8];                             \
            int jj = le0 + mt * 16 + kk + rr;                                                \
            rowa[mt] = sxt + (uint32_t)jj * 128;                                             \
            mxor[mt] = ((uint32_t)(jj & 7)) << 2;                                            \
        }                                                                                    \
        _Pragma("unroll") for (int ks = 0; ks < 4; ks++) {                                   \
            const uint4* fbq = frag + (size_t)(((kk * 4 + ks) * 4 + ncolg * 2) * 32 + lane); \
            uint4 q0 = fbq[0];                                                               \
            uint4 q1 = fbq[32];                                                              \
            const uint32_t koff = ((uint32_t)(8 * ks) + (uint32_t)ee);                       \
            uint32_t acur[4], anext[4];                                                      \
            ldsm_x4(acur, rowa[0] + ((koff ^ mxor[0]) << 2));                                \
            _Pragma("unroll") for (int mt = 0; mt < 4; mt++) {                               \
                if (mt < 3) ldsm_x4(anext, rowa[mt + 1] + ((koff ^ mxor[mt + 1]) << 2));     \
                uint32_t a0 = hmul2(acur[0], wh[mt][0]);                                     \
                uint32_t a1 = hmul2(acur[1], wh[mt][1]);                                     \
                uint32_t a2 = hmul2(acur[2], wh[mt][0]);                                     \
                uint32_t a3 = hmul2(acur[3], wh[mt][1]);                                     \
                mma_f16(acc[mt][0], a0, a1, a2, a3, q0.x, q0.y);                             \
                mma_f16(acc[mt][1], a0, a1, a2, a3, q0.z, q0.w);                             \
                mma_f16(acc[mt][2], a0, a1, a2, a3, q1.x, q1.y);                             \
                mma_f16(acc[mt][3], a0, a1, a2, a3, q1.z, q1.w);                             \
                if (mt < 3) {                                                                \
                    acur[0] = anext[0];                                                      \
                    acur[1] = anext[1];                                                      \
                    acur[2] = anext[2];                                                      \
                    acur[3] = anext[3];                                                      \
                }                                                                            \
            }                                                                                \
        }                                                                                    \
    }

    /* ---- prologue: stage the first tile (latency exposed once) ---- */
    const int tt0 = blockIdx.x;
    {
        const int b = tt0 >> 10;
        const int l0 = (tt0 & (TPB_L - 1)) * TILE;
        const float* xb = x + (size_t)b * CIN * LSEQ + l0 + 4 * q;
        LDG_X4(pa, 0, xb);
        LDG_X4(pa, 4, xb);
        LDG_X4(pb, 8, xb);
        LDG_X4(pb, 12, xb);
        LDG_CH(b, l0);
        STS_TILE();
        __syncthreads();
        WEIGHTS();
        __syncthreads();
    }

    for (int tt = tt0; tt < NTILES; tt += gridn) {
        const int b = tt >> 10;
        const int l0 = (tt & (TPB_L - 1)) * TILE;
        const int tn = tt + gridn;
        const bool have = tn < NTILES;
        const int bn = tn >> 10;
        const int l0n = (tn & (TPB_L - 1)) * TILE;
        const float* xbn = x + (size_t)bn * CIN * LSEQ + l0n + 4 * q;

        /* issue next tile's loads; they complete under the mainloop */
        if (have) {
            LDG_X4(pa, 0, xbn);
            LDG_X4(pa, 4, xbn);
            LDG_CH(bn, l0n);
        }

        float acc[4][4][4];
#pragma unroll
        for (int mt = 0; mt < 4; mt++)
#pragma unroll
            for (int nt = 0; nt < 4; nt++)
#pragma unroll
                for (int j = 0; j < 4; j++) acc[mt][nt][j] = 0.f;

        MAINLOOP(0, 4);
        if (have) {
            LDG_X4(pb, 8, xbn);
            LDG_X4(pb, 12, xbn);
        }
        MAINLOOP(4, KW);

        /* epilogue: +bias, store raw conv (fp16 scratch), stats in regs */
        __half* scrb = g_scr + (size_t)b * COUT * LSEQ + l0;
#pragma unroll
        for (int mt = 0; mt < 4; mt++) {
            const int le = le0 + mt * 16 + g;
#pragma unroll
            for (int nt = 0; nt < 4; nt++) {
                int o = ncolg * 32 + nt * 8 + t * 2;
                float b0 = bsh[o];
                float b1 = bsh[o + 1];
                float v0 = acc[mt][nt][0] + b0;
                float v1 = acc[mt][nt][1] + b1;
                float v2 = acc[mt][nt][2] + b0;
                float v3 = acc[mt][nt][3] + b1;
                scrb[(size_t)o * LSEQ + le] = __float2half_rn(v0);
                scrb[(size_t)(o + 1) * LSEQ + le] = __float2half_rn(v1);
                scrb[(size_t)o * LSEQ + le + 8] = __float2half_rn(v2);
                scrb[(size_t)(o + 1) * LSEQ + le + 8] = __float2half_rn(v3);
                s1[nt][0] += v0 + v2;
                s1[nt][1] += v1 + v3;
                s2[nt][0] += v0 * v0 + v2 * v2;
                s2[nt][1] += v1 * v1 + v3 * v3;
            }
        }

        __syncthreads(); /* all reads of xht/wsh2 for tile tt done */
        if (have) {
            STS_TILE();
            __syncthreads();
            WEIGHTS();
            __syncthreads();
        }
    }

    /* flush stats: reduce over lanes sharing t (xor 16,8,4 preserves t) */
#pragma unroll
    for (int nt = 0; nt < 4; nt++)
#pragma unroll
        for (int j = 0; j < 2; j++) {
            float a = s1[nt][j], q2 = s2[nt][j];
#pragma unroll
            for (int off = 16; off >= 4; off >>= 1) {
                a += __shfl_xor_sync(0xffffffffu, a, off);
                q2 += __shfl_xor_sync(0xffffffffu, q2, off);
            }
            if (g == 0) {
                int o = ncolg * 32 + nt * 8 + t * 2 + j;
                atomicAdd(&g_sum[o], (double)a);
                atomicAdd(&g_sumsq[o], (double)q2);
            }
        }
}

/* Computes per-channel scale/shift, then resets accumulators for the next
   (graph-replayed) run. Statics are zero-initialized at module load. */
__global__ void stats_kernel(const float* __restrict__ gamma, const float* __restrict__ beta) {
    int o = threadIdx.x;
    if (o < COUT) {
        double N = (double)BATCH * (double)LSEQ;
        double mean = g_sum[o] / N;
        double var = g_sumsq[o] / N - mean * mean;
        double rstd = 1.0 / sqrt(var + 1e-5);
        float sc = gamma[o] * (float)rstd;
        g_scale[o] = sc;
        g_shift[o] = beta[o] - (float)mean * sc;
        g_sum[o] = 0.0;
        g_sumsq[o] = 0.0;
    }
}

__global__ void norm_kernel(float* __restrict__ out) {
    const size_t total4 = (size_t)BATCH * COUT * LSEQ / 4;
    size_t stride = (size_t)gridDim.x * blockDim.x;
    const uint2* scr4 = (const uint2*)g_scr;
    for (size_t i = (size_t)blockIdx.x * blockDim.x + threadIdx.x; i < total4; i += stride) {
        uint2 hv = scr4[i];
        float2 f01 = __half22float2(*(const __half2*)&hv.x);
        float2 f23 = __half22float2(*(const __half2*)&hv.y);
        int ch = (int)((i * 4 / LSEQ)) & (COUT - 1);
        float sc = g_scale[ch];
        float sh = g_shift[ch];
        float4 v;
        v.x = fmaxf(fmaf(f01.x, sc, sh), 0.0f);
        v.y = fmaxf(fmaf(f01.y, sc, sh), 0.0f);
        v.z = fmaxf(fmaf(f23.x, sc, sh), 0.0f);
        v.w = fmaxf(fmaf(f23.y, sc, sh), 0.0f);
        reinterpret_cast<float4*>(out)[i] = v;
    }
}

extern "C" void kernel_launch(void* const* d_in, const int* in_sizes, int n_in, void* d_out,
                              int out_size) {
    const float* x = (const float*)d_in[0];       // [4,64,131072]
    const float* coords = (const float*)d_in[1];  // [4,3,131072]
    const float* W = (const float*)d_in[2];       // [64,64,9]
    const float* bias = (const float*)d_in[3];    // [64]
    const float* gamma = (const float*)d_in[4];   // [64]
    const float* beta = (const float*)d_in[5];    // [64]
    float* out = (float*)d_out;

    cudaFuncSetAttribute(conv_mma_kernel, cudaFuncAttributeMaxDynamicSharedMemorySize, SM_TOTAL);
    int sms = 148;
    cudaDeviceGetAttribute(&sms, cudaDevAttrMultiProcessorCount, 0);

    conv_mma_kernel<<<2 * sms, NTHREADS, SM_TOTAL>>>(x, coords, W, bias);
    stats_kernel<<<1, 64>>>(gamma, beta);
    norm_kernel<<<8192, 256>>>(out);
}

// round 16
// speedup vs baseline: 5.4403x; 1.0540x over previous
#include <cuda_runtime.h>
#include <cuda_fp16.h>
#include <math.h>
#include <stddef.h>
#include <stdint.h>

#define BATCH 4
#define CIN 64
#define COUT 64
#define LSEQ 131072
#define KW 9
#define PADW 4
#define TILE 128
#define JW 136 /* padded rows of xht */
#define NTHREADS 128
#define TPB_L (LSEQ / TILE)    /* 1024 */
#define NTILES (BATCH * TPB_L) /* 4096 */

/* SMEM (bytes), per CTA (2 CTAs/SM) */
#define SM_FRAG 0
#define SM_XT (SM_FRAG + KW * 4 * 4 * 32 * 16) /* 73728 */
#define SM_C (SM_XT + JW * 128)                /* +17408 */
#define SM_W (SM_C + 3 * JW * 4)               /* +1632 */
#define SM_BIAS (SM_W + KW * TILE * 4)         /* +4608 */
#define SM_TOTAL (SM_BIAS + 256)               /* = 97632 */

static __device__ double g_sum[COUT];
static __device__ double g_sumsq[COUT];
static __device__ float g_scale[COUT];
static __device__ float g_shift[COUT];
/* conv scratch in fragment-native order:
   uint2 index = tile*2048 + wid*512 + (mt*4+nt)*32 + lane
   holding halfs (v0,v1,v2,v3) = (o,le),(o+1,le),(o,le+8),(o+1,le+8) */
static __device__ __align__(16) __half g_scr[(size_t)BATCH * COUT * LSEQ]; /* 67 MB */

__device__ __forceinline__ uint32_t smem_u32(const void* p) {
    uint32_t a;
    asm("{ .reg .u64 t; cvta.to.shared.u64 t, %1; cvt.u32.u64 %0, t; }" : "=r"(a) : "l"(p));
    return a;
}
/* pack two f32 -> f16x2: lo half = 'even', hi half = 'odd' */
__device__ __forceinline__ uint32_t pack_f16x2(float even, float odd) {
    uint32_t r;
    asm("cvt.rn.f16x2.f32 %0, %1, %2;" : "=r"(r) : "f"(odd), "f"(even));
    return r;
}
__device__ __forceinline__ uint32_t hmul2(uint32_t a, uint32_t b) {
    uint32_t r;
    asm("mul.rn.f16x2 %0, %1, %2;" : "=r"(r) : "r"(a), "r"(b));
    return r;
}
__device__ __forceinline__ void ldsm_x4(uint32_t* r, uint32_t addr) {
    asm volatile("ldmatrix.sync.aligned.m8n8.x4.shared.b16 {%0,%1,%2,%3}, [%4];"
                 : "=r"(r[0]), "=r"(r[1]), "=r"(r[2]), "=r"(r[3])
                 : "r"(addr));
}
__device__ __forceinline__ void mma_f16(float* d, uint32_t a0, uint32_t a1, uint32_t a2,
                                        uint32_t a3, uint32_t b0, uint32_t b1) {
    asm volatile(
        "mma.sync.aligned.m16n8k16.row.col.f32.f16.f16.f32 "
        "{%0,%1,%2,%3}, {%4,%5,%6,%7}, {%8,%9}, {%0,%1,%2,%3};"
        : "+f"(d[0]), "+f"(d[1]), "+f"(d[2]), "+f"(d[3])
        : "r"(a0), "r"(a1), "r"(a2), "r"(a3), "r"(b0), "r"(b1));
}

__global__ __launch_bounds__(NTHREADS, 2) void conv_mma_kernel(
    const float* __restrict__ x, const float* __restrict__ coords, const float* __restrict__ W,
    const float* __restrict__ bias) {
    extern __shared__ char smem[];
    uint4* frag = (uint4*)(smem + SM_FRAG);
    float* csh = (float*)(smem + SM_C);
    uint32_t* wsh2 = (uint32_t*)(smem + SM_W);
    float* bsh = (float*)(smem + SM_BIAS);
    const uint32_t sxt = smem_u32(smem + SM_XT);

    const int tid = threadIdx.x;
    const int wid = tid >> 5; /* 0..3 */
    const int lane = tid & 31;
    const int t = lane & 3;
    const int g = lane >> 2;
    const int mrowg = wid & 1;  /* 64 L rows per warp */
    const int ncolg = wid >> 1; /* 32 Couts per warp */
    const int le0 = mrowg * 64;
    const int rr = lane & 15;        /* ldmatrix row offset */
    const int ee = (lane >> 4) << 2; /* +4 words when lane>=16 */
    const int i4 = lane >> 3;        /* staging: c sub-row 0..3 */
    const int q = lane & 7;          /* staging: j quad selector */
    const int gridn = gridDim.x;

    /* One-time: bake W into fp16 B fragments, nt-paired (uint4/lane) */
    for (int i = tid; i < KW * 4 * 4 * 32; i += NTHREADS) {
        int kk = i >> 9;
        int r = i & 511;
        int ks = r >> 7;
        int r2 = r & 127;
        int np = r2 >> 5;
        int li = r2 & 31;
        int c = ks * 16 + 2 * (li & 3);
        int o0 = 2 * np * 8 + (li >> 2);
        const float* wp0 = W + (size_t)(o0 * CIN + c) * KW + kk;
        const float* wp1 = wp0 + (size_t)8 * CIN * KW;
        uint4 f;
        f.x = pack_f16x2(wp0[0], wp0[KW]);
        f.y = pack_f16x2(wp0[8 * KW], wp0[9 * KW]);
        f.z = pack_f16x2(wp1[0], wp1[KW]);
        f.w = pack_f16x2(wp1[8 * KW], wp1[9 * KW]);
        frag[i] = f;
    }
    for (int i = tid; i < COUT; i += NTHREADS) bsh[i] = bias[i];

    float s1[4][2], s2[4][2];
#pragma unroll
    for (int nt = 0; nt < 4; nt++)
#pragma unroll
        for (int j = 0; j < 2; j++) {
            s1[nt][j] = 0.f;
            s2[nt][j] = 0.f;
        }

    /* prefetch register state (tile "next") */
    float4 pa[8], pb[8];
    float cr0, cr1, cr2, cr3;
    float he[2], ho[2];

/* ---- LDG a batch of 4 x-float4s for tile (bn, l0n) into dst[] at it-range base ---- */
#define LDG_X4(dst, itbase, xbn)                                                             \
    {                                                                                        \
        _Pragma("unroll") for (int i = 0; i < 4; i++) {                                      \
            int it = (itbase) + i;                                                           \
            (dst)[((itbase) & 4) + i] = *(const float4*)((xbn) +                             \
                (size_t)(16 * wid + 4 * (it & 3) + i4) * LSEQ + 32 * (it >> 2));             \
        }                                                                                    \
    }

/* ---- LDG coords + halo for tile (bn, l0n) ---- */
#define LDG_CH(bn, l0n)                                                                      \
    {                                                                                        \
        const float* cb = coords + (size_t)(bn)*3 * LSEQ;                                    \
        int i0 = tid, i1 = tid + 128, i2 = tid + 256, i3 = tid + 384;                        \
        int d0 = i0 / JW, j0 = i0 - d0 * JW, l0c = (l0n)-PADW + j0;                          \
        int d1 = i1 / JW, j1 = i1 - d1 * JW, l1c = (l0n)-PADW + j1;                          \
        int d2 = i2 / JW, j2 = i2 - d2 * JW, l2c = (l0n)-PADW + j2;                          \
        cr0 = (l0c >= 0 && l0c < LSEQ) ? cb[(size_t)d0 * LSEQ + l0c] : 0.0f;                 \
        cr1 = (l1c >= 0 && l1c < LSEQ) ? cb[(size_t)d1 * LSEQ + l1c] : 0.0f;                 \
        cr2 = (l2c >= 0 && l2c < LSEQ) ? cb[(size_t)d2 * LSEQ + l2c] : 0.0f;                 \
        cr3 = 0.0f;                                                                         \
        if (i3 < 3 * JW) {                                                                  \
            int j3 = i3 - 2 * JW;                                                           \
            int l3c = (l0n)-PADW + j3;                                                      \
            cr3 = (l3c >= 0 && l3c < LSEQ) ? cb[(size_t)2 * LSEQ + l3c] : 0.0f;             \
        }                                                                                   \
        _Pragma("unroll") for (int e = 0; e < 2; e++) {                                     \
            int ei = tid + e * 128;                                                         \
            int c2 = ei & 31;                                                               \
            int hs = ei >> 5;                                                               \
            int hj = (hs < 4) ? hs : 128 + hs;                                              \
            int l = (l0n)-PADW + hj;                                                        \
            const float* xr = x + (size_t)(bn)*CIN * LSEQ + (size_t)(2 * c2) * LSEQ;        \
            he[e] = (l >= 0 && l < LSEQ) ? xr[l] : 0.0f;                                    \
            ho[e] = (l >= 0 && l < LSEQ) ? xr[LSEQ + l] : 0.0f;                             \
        }                                                                                   \
    }

/* ---- transpose + STS the prefetched tile (pa/pb + coords + halo) ---- */
#define STS_TILE()                                                                           \
    {                                                                                        \
        _Pragma("unroll") for (int it = 0; it < 16; it++) {                                  \
            float4 v = (it < 8) ? pa[it] : pb[it - 8];                                       \
            if (i4 & 1) { float tmp = v.x; v.x = v.y; v.y = tmp; tmp = v.z; v.z = v.w; v.w = tmp; } \
            v.y = __shfl_xor_sync(0xffffffffu, v.y, 8);                                      \
            v.w = __shfl_xor_sync(0xffffffffu, v.w, 8);                                      \
            if (i4 & 1) { float tmp = v.x; v.x = v.y; v.y = tmp; tmp = v.z; v.z = v.w; v.w = tmp; } \
            if (i4 & 2) { float tmp = v.x; v.x = v.z; v.z = tmp; tmp = v.y; v.y = v.w; v.w = tmp; } \
            v.z = __shfl_xor_sync(0xffffffffu, v.z, 16);                                     \
            v.w = __shfl_xor_sync(0xffffffffu, v.w, 16);                                     \
            if (i4 & 2) { float tmp = v.x; v.x = v.z; v.z = tmp; tmp = v.y; v.y = v.w; v.w = tmp; } \
            int j = PADW + 32 * (it >> 2) + 4 * q + i4;                                      \
            int c2 = 8 * wid + 2 * (it & 3);                                                 \
            uint32_t h0 = pack_f16x2(v.x, v.y);                                              \
            uint32_t h1 = pack_f16x2(v.z, v.w);                                              \
            uint32_t word = (uint32_t)j * 32 + (((uint32_t)c2) ^ (((uint32_t)(j & 7)) << 2)); \
            asm volatile("st.shared.v2.b32 [%0], {%1, %2};" ::"r"(sxt + word * 4), "r"(h0),  \
                         "r"(h1)                                                             \
                         : "memory");                                                        \
        }                                                                                    \
        _Pragma("unroll") for (int e = 0; e < 2; e++) {                                      \
            int ei = tid + e * 128;                                                          \
            int c2 = ei & 31;                                                                \
            int hs = ei >> 5;                                                                \
            int hj = (hs < 4) ? hs : 128 + hs;                                               \
            uint32_t h = pack_f16x2(he[e], ho[e]);                                           \
            uint32_t word = (uint32_t)hj * 32 + (((uint32_t)c2) ^ (((uint32_t)(hj & 7)) << 2)); \
            asm volatile("st.shared.b32 [%0], %1;" ::"r"(sxt + word * 4), "r"(h) : "memory"); \
        }                                                                                    \
        csh[tid] = cr0;                                                                      \
        csh[tid + 128] = cr1;                                                                \
        csh[tid + 256] = cr2;                                                                \
        if (tid + 384 < 3 * JW) csh[tid + 384] = cr3;                                        \
    }

/* ---- gaussian weights from staged coords ---- */
#define WEIGHTS()                                                                            \
    for (int i = tid; i < KW * TILE; i += NTHREADS) {                                        \
        int k = i >> 7;                                                                      \
        int lc = i & (TILE - 1);                                                             \
        float d0 = csh[lc + k] - csh[lc + PADW];                                             \
        float d1 = csh[JW + lc + k] - csh[JW + lc + PADW];                                   \
        float d2 = csh[2 * JW + lc + k] - csh[2 * JW + lc + PADW];                           \
        float w = __expf(-0.5f * (d0 * d0 + d1 * d1 + d2 * d2));                             \
        wsh2[i] = pack_f16x2(w, w);                                                          \
    }

/* ---- mainloop over kk range ---- */
#define MAINLOOP(KK0, KK1)                                                                   \
    _Pragma("unroll 1") for (int kk = (KK0); kk < (KK1); kk++) {                             \
        uint32_t wh[4][2];                                                                   \
        uint32_t rowa[4], mxor[4];                                                           \
        _Pragma("unroll") for (int mt = 0; mt < 4; mt++) {                                   \
            wh[mt][0] = wsh2[kk * TILE + le0 + mt * 16 + g];                                 \
            wh[mt][1] = wsh2[kk * TILE + le0 + mt * 16 + g + 8];                             \
            int jj = le0 + mt * 16 + kk + rr;                                                \
            rowa[mt] = sxt + (uint32_t)jj * 128;                                             \
            mxor[mt] = ((uint32_t)(jj & 7)) << 2;                                            \
        }                                                                                    \
        _Pragma("unroll") for (int ks = 0; ks < 4; ks++) {                                   \
            const uint4* fbq = frag + (size_t)(((kk * 4 + ks) * 4 + ncolg * 2) * 32 + lane); \
            uint4 q0 = fbq[0];                                                               \
            uint4 q1 = fbq[32];                                                              \
            const uint32_t koff = ((uint32_t)(8 * ks) + (uint32_t)ee);                       \
            uint32_t acur[4], anext[4];                                                      \
            ldsm_x4(acur, rowa[0] + ((koff ^ mxor[0]) << 2));                                \
            _Pragma("unroll") for (int mt = 0; mt < 4; mt++) {                               \
                if (mt < 3) ldsm_x4(anext, rowa[mt + 1] + ((koff ^ mxor[mt + 1]) << 2));     \
                uint32_t a0 = hmul2(acur[0], wh[mt][0]);                                     \
                uint32_t a1 = hmul2(acur[1], wh[mt][1]);                                     \
                uint32_t a2 = hmul2(acur[2], wh[mt][0]);                                     \
                uint32_t a3 = hmul2(acur[3], wh[mt][1]);                                     \
                mma_f16(acc[mt][0], a0, a1, a2, a3, q0.x, q0.y);                             \
                mma_f16(acc[mt][1], a0, a1, a2, a3, q0.z, q0.w);                             \
                mma_f16(acc[mt][2], a0, a1, a2, a3, q1.x, q1.y);                             \
                mma_f16(acc[mt][3], a0, a1, a2, a3, q1.z, q1.w);                             \
                if (mt < 3) {                                                                \
                    acur[0] = anext[0];                                                      \
                    acur[1] = anext[1];                                                      \
                    acur[2] = anext[2];                                                      \
                    acur[3] = anext[3];                                                      \
                }                                                                            \
            }                                                                                \
        }                                                                                    \
    }

    /* ---- prologue: stage the first tile (latency exposed once) ---- */
    const int tt0 = blockIdx.x;
    {
        const int b = tt0 >> 10;
        const int l0 = (tt0 & (TPB_L - 1)) * TILE;
        const float* xb = x + (size_t)b * CIN * LSEQ + l0 + 4 * q;
        LDG_X4(pa, 0, xb);
        LDG_X4(pa, 4, xb);
        LDG_X4(pb, 8, xb);
        LDG_X4(pb, 12, xb);
        LDG_CH(b, l0);
        STS_TILE();
        __syncthreads();
        WEIGHTS();
        __syncthreads();
    }

    for (int tt = tt0; tt < NTILES; tt += gridn) {
        const int tn = tt + gridn;
        const bool have = tn < NTILES;
        const int bn = tn >> 10;
        const int l0n = (tn & (TPB_L - 1)) * TILE;
        const float* xbn = x + (size_t)bn * CIN * LSEQ + l0n + 4 * q;

        /* issue next tile's loads; they complete under the mainloop */
        if (have) {
            LDG_X4(pa, 0, xbn);
            LDG_X4(pa, 4, xbn);
            LDG_CH(bn, l0n);
        }

        float acc[4][4][4];
#pragma unroll
        for (int mt = 0; mt < 4; mt++)
#pragma unroll
            for (int nt = 0; nt < 4; nt++)
#pragma unroll
                for (int j = 0; j < 4; j++) acc[mt][nt][j] = 0.f;

        MAINLOOP(0, 4);
        if (have) {
            LDG_X4(pb, 8, xbn);
            LDG_X4(pb, 12, xbn);
        }
        MAINLOOP(4, KW);

        /* epilogue: +bias, stats, fragment-native coalesced scratch store */
        uint2* scrt = (uint2*)g_scr + ((size_t)tt * 2048 + (size_t)wid * 512 + lane);
#pragma unroll
        for (int mt = 0; mt < 4; mt++) {
#pragma unroll
            for (int nt = 0; nt < 4; nt++) {
                int o = ncolg * 32 + nt * 8 + t * 2;
                float b0 = bsh[o];
                float b1 = bsh[o + 1];
                float v0 = acc[mt][nt][0] + b0;
                float v1 = acc[mt][nt][1] + b1;
                float v2 = acc[mt][nt][2] + b0;
                float v3 = acc[mt][nt][3] + b1;
                uint2 hv;
                hv.x = pack_f16x2(v0, v1);
                hv.y = pack_f16x2(v2, v3);
                scrt[(mt * 4 + nt) * 32] = hv;
                s1[nt][0] += v0 + v2;
                s1[nt][1] += v1 + v3;
                s2[nt][0] += v0 * v0 + v2 * v2;
                s2[nt][1] += v1 * v1 + v3 * v3;
            }
        }

        __syncthreads(); /* all reads of xht/wsh2 for tile tt done */
        if (have) {
            STS_TILE();
            __syncthreads();
            WEIGHTS();
            __syncthreads();
        }
    }

    /* flush stats: reduce over lanes sharing t (xor 16,8,4 preserves t) */
#pragma unroll
    for (int nt = 0; nt < 4; nt++)
#pragma unroll
        for (int j = 0; j < 2; j++) {
            float a = s1[nt][j], q2 = s2[nt][j];
#pragma unroll
            for (int off = 16; off >= 4; off >>= 1) {
                a += __shfl_xor_sync(0xffffffffu, a, off);
                q2 += __shfl_xor_sync(0xffffffffu, q2, off);
            }
            if (g == 0) {
                int o = ncolg * 32 + nt * 8 + t * 2 + j;
                atomicAdd(&g_sum[o], (double)a);
                atomicAdd(&g_sumsq[o], (double)q2);
            }
        }
}

/* Computes per-channel scale/shift, then resets accumulators for the next
   (graph-replayed) run. Statics are zero-initialized at module load. */
__global__ void stats_kernel(const float* __restrict__ gamma, const float* __restrict__ beta) {
    int o = threadIdx.x;
    if (o < COUT) {
        double N = (double)BATCH * (double)LSEQ;
        double mean = g_sum[o] / N;
        double var = g_sumsq[o] / N - mean * mean;
        double rstd = 1.0 / sqrt(var + 1e-5);
        float sc = gamma[o] * (float)rstd;
        g_scale[o] = sc;
        g_shift[o] = beta[o] - (float)mean * sc;
        g_sum[o] = 0.0;
        g_sumsq[o] = 0.0;
    }
}

/* Reads fragment-native scratch, decodes (tile, wid, mt, nt, lane) -> (b, o, le),
   applies BN+ReLU, writes out[b][o][l]. Writes are 32B-sector aligned. */
__global__ void norm_kernel(float* __restrict__ out) {
    const size_t total = (size_t)NTILES * 2048; /* uint2 elements */
    size_t stride = (size_t)gridDim.x * blockDim.x;
    const uint2* scr2 = (const uint2*)g_scr;
    for (size_t i = (size_t)blockIdx.x * blockDim.x + threadIdx.x; i < total; i += stride) {
        uint2 hv = scr2[i];
        int tile = (int)(i >> 11);
        int r = (int)i & 2047;
        int lane = r & 31;
        int nt = (r >> 5) & 3;
        int mt = (r >> 7) & 3;
        int wd = r >> 9;
        int b = tile >> 10;
        int l0 = (tile & 1023) << 7;
        int le = (wd & 1) * 64 + mt * 16 + (lane >> 2);
        int o = (wd >> 1) * 32 + nt * 8 + (lane & 3) * 2;
        float2 f01 = __half22float2(*(const __half2*)&hv.x); /* (o,le), (o+1,le)   */
        float2 f23 = __half22float2(*(const __half2*)&hv.y); /* (o,le+8),(o+1,le+8)*/
        float sc0 = g_scale[o], sh0 = g_shift[o];
        float sc1 = g_scale[o + 1], sh1 = g_shift[o + 1];
        float* ob = out + ((size_t)b * COUT + o) * LSEQ + l0 + le;
        ob[0] = fmaxf(fmaf(f01.x, sc0, sh0), 0.0f);
        ob[LSEQ] = fmaxf(fmaf(f01.y, sc1, sh1), 0.0f);
        ob[8] = fmaxf(fmaf(f23.x, sc0, sh0), 0.0f);
        ob[LSEQ + 8] = fmaxf(fmaf(f23.y, sc1, sh1), 0.0f);
    }
}

extern "C" void kernel_launch(void* const* d_in, const int* in_sizes, int n_in, void* d_out,
                              int out_size) {
    const float* x = (const float*)d_in[0];       // [4,64,131072]
    const float* coords = (const float*)d_in[1];  // [4,3,131072]
    const float* W = (const float*)d_in[2];       // [64,64,9]
    const float* bias = (const float*)d_in[3];    // [64]
    const float* gamma = (const float*)d_in[4];   // [64]
    const float* beta = (const float*)d_in[5];    // [64]
    float* out = (float*)d_out;

    cudaFuncSetAttribute(conv_mma_kernel, cudaFuncAttributeMaxDynamicSharedMemorySize, SM_TOTAL);
    int sms = 148;
    cudaDeviceGetAttribute(&sms, cudaDevAttrMultiProcessorCount, 0);

    conv_mma_kernel<<<2 * sms, NTHREADS, SM_TOTAL>>>(x, coords, W, bias);
    stats_kernel<<<1, 64>>>(gamma, beta);
    norm_kernel<<<8192, 256>>>(out);
}